// round 2
// baseline (speedup 1.0000x reference)
#include <cuda_runtime.h>
#include <cuda_bf16.h>
#include <mma.h>

using namespace nvcuda;

#define NN 50000
#define EE 800000
#define LL 128
#define NSTEPS 10

// ---- scratch (device globals; no allocations allowed) ----
__device__ float g_nl[(size_t)NN * LL];    // node latents
__device__ float g_el[(size_t)EE * LL];    // edge latents (410 MB)
__device__ float g_agg[(size_t)NN * LL];   // scatter-add target (zeroed as consumed)
__device__ float g_deg[NN];
__device__ float g_center[3];

typedef wmma::fragment<wmma::matrix_a, 16, 16, 16, __nv_bfloat16, wmma::row_major> AF;
typedef wmma::fragment<wmma::matrix_b, 16, 16, 16, __nv_bfloat16, wmma::row_major> BF;
typedef wmma::fragment<wmma::accumulator, 16, 16, 16, float> CF;

// split a float4 into bf16 hi/lo planes (two-term twofloat split)
__device__ __forceinline__ void split_store4(float4 v, __nv_bfloat16* hip, __nv_bfloat16* lop) {
    __nv_bfloat162 h0 = __floats2bfloat162_rn(v.x, v.y);
    __nv_bfloat162 h1 = __floats2bfloat162_rn(v.z, v.w);
    float2 f0 = __bfloat1622float2(h0);
    float2 f1 = __bfloat1622float2(h1);
    __nv_bfloat162 l0 = __floats2bfloat162_rn(v.x - f0.x, v.y - f0.y);
    __nv_bfloat162 l1 = __floats2bfloat162_rn(v.z - f1.x, v.w - f1.y);
    *(__nv_bfloat162*)(hip)     = h0;
    *(__nv_bfloat162*)(hip + 2) = h1;
    *(__nv_bfloat162*)(lop)     = l0;
    *(__nv_bfloat162*)(lop + 2) = l1;
}

__device__ __forceinline__ void red_add_v4(float* dst, float4 v) {
    asm volatile("red.global.add.v4.f32 [%0], {%1,%2,%3,%4};"
                 :: "l"(dst), "f"(v.x), "f"(v.y), "f"(v.z), "f"(v.w) : "memory");
}

// ---------------------------------------------------------------- init / deg / center
__global__ void k_init() {
    int i = blockIdx.x * blockDim.x + threadIdx.x;
    if (i < NN) g_deg[i] = 0.f;
    if (i < 3) g_center[i] = 0.f;
}

__global__ void k_deg(const int* __restrict__ rcv) {
    int i = blockIdx.x * blockDim.x + threadIdx.x;
    if (i < EE) atomicAdd(&g_deg[rcv[i]], 1.f);
}

__global__ void k_center(const float* __restrict__ pos) {
    float sx = 0.f, sy = 0.f, sz = 0.f;
    for (int i = blockIdx.x * blockDim.x + threadIdx.x; i < NN; i += gridDim.x * blockDim.x) {
        sx += pos[i * 3 + 0];
        sy += pos[i * 3 + 1];
        sz += pos[i * 3 + 2];
    }
#pragma unroll
    for (int o = 16; o > 0; o >>= 1) {
        sx += __shfl_down_sync(0xffffffffu, sx, o);
        sy += __shfl_down_sync(0xffffffffu, sy, o);
        sz += __shfl_down_sync(0xffffffffu, sz, o);
    }
    if ((threadIdx.x & 31) == 0) {
        atomicAdd(&g_center[0], sx);
        atomicAdd(&g_center[1], sy);
        atomicAdd(&g_center[2], sz);
    }
}

// ---------------------------------------------------------------- node encoder (SIMT fp32; exact)
__global__ void __launch_bounds__(128) k_node_enc(
    const float* __restrict__ pos, const float* __restrict__ vel,
    const int* __restrict__ rid, const float* __restrict__ remb,
    const float* __restrict__ W1, const float* __restrict__ B1,
    const float* __restrict__ W2, const float* __restrict__ B2)
{
    __shared__ float F[32][24];
    __shared__ float H[32][128];
    const int tid = threadIdx.x;
    const int nbase = blockIdx.x * 32;
    const float inv = 1.f / (float)NN;
    const float cx = g_center[0] * inv, cy = g_center[1] * inv, cz = g_center[2] * inv;

    for (int i = tid; i < 32 * 23; i += 128) {
        int n = i / 23, k = i % 23;
        int gn = nbase + n;
        float v = 0.f;
        if (gn < NN) {
            if (k < 3) v = vel[gn * 3 + k];
            else if (k < 6) v = pos[gn * 3 + (k - 3)] - ((k == 3) ? cx : (k == 4) ? cy : cz);
            else if (k == 6) v = g_deg[gn];
            else v = remb[rid[gn] * 16 + (k - 7)];
        }
        F[n][k] = v;
    }
    __syncthreads();

    const int j = tid;
#pragma unroll 1
    for (int n = 0; n < 32; n++) {
        float acc = B1[j];
#pragma unroll
        for (int k = 0; k < 23; k++) acc += F[n][k] * W1[k * 128 + j];
        H[n][j] = fmaxf(acc, 0.f);
    }
    __syncthreads();
#pragma unroll 1
    for (int n = 0; n < 32; n++) {
        int gn = nbase + n;
        float acc = B2[j];
#pragma unroll 8
        for (int k = 0; k < 128; k++) acc += H[n][k] * W2[k * 128 + j];
        if (gn < NN) g_nl[(size_t)gn * LL + j] = acc;
    }
}

// ---------------------------------------------------------------- edge encoder
// feat + L1 SIMT fp32 (exact), L2 via bf16-split wmma.
__global__ void __launch_bounds__(256, 1) k_edge_enc(
    const float* __restrict__ pos, const float* __restrict__ vel,
    const int* __restrict__ rid,
    const int* __restrict__ snd, const int* __restrict__ rcv,
    const float* __restrict__ W1, const float* __restrict__ B1,
    const float* __restrict__ W2, const float* __restrict__ B2)
{
    extern __shared__ char smc[];
    const int LDF = 12, LDH = 132, LDHB = 136, LDWB = 136;
    float*         F   = (float*)(smc + 0);          // 64 x 12
    float*         Hf  = (float*)(smc + 3072);       // 64 x 132
    __nv_bfloat16* Hhi = (__nv_bfloat16*)(smc + 36864);
    __nv_bfloat16* Hlo = (__nv_bfloat16*)(smc + 54272);
    __nv_bfloat16* Whi = (__nv_bfloat16*)(smc + 71680);   // 128 x 136
    __nv_bfloat16* Wlo = (__nv_bfloat16*)(smc + 106496);
    const int tid = threadIdx.x;
    const int w = tid >> 5, rt = w >> 1, cg = w & 1;
    const int ebase = blockIdx.x * 64;

    if (tid < 64) {
        int e = ebase + tid;
        int s = snd[e], r = rcv[e];
        float rp0 = pos[s * 3 + 0] - pos[r * 3 + 0];
        float rp1 = pos[s * 3 + 1] - pos[r * 3 + 1];
        float rp2 = pos[s * 3 + 2] - pos[r * 3 + 2];
        float rv0 = vel[s * 3 + 0] - vel[r * 3 + 0];
        float rv1 = vel[s * 3 + 1] - vel[r * 3 + 1];
        float rv2 = vel[s * 3 + 2] - vel[r * 3 + 2];
        float sq = rp0 * rp0 + rp1 * rp1 + rp2 * rp2;
        float dist = sqrtf(sq);
        float same = (rid[s] == rid[r]) ? 1.f : 0.f;
        float* f = F + tid * LDF;
        f[0] = rp0; f[1] = rp1; f[2] = rp2;
        f[3] = rv0; f[4] = rv1; f[5] = rv2;
        f[6] = dist; f[7] = sq; f[8] = same;
    }
    // stage full W2 (128x128) into bf16 planes
    for (int i = tid; i < 128 * 32; i += 256) {
        int rr = i >> 5, c4 = i & 31;
        float4 v = ((const float4*)(W2 + rr * 128))[c4];
        split_store4(v, Whi + rr * LDWB + c4 * 4, Wlo + rr * LDWB + c4 * 4);
    }
    __syncthreads();

    // L1 SIMT: H = relu(F @ W1 + B1)
    for (int i = tid; i < 64 * 128; i += 256) {
        int e = i >> 7, j = i & 127;
        const float* f = F + e * LDF;
        float acc = B1[j];
#pragma unroll
        for (int k = 0; k < 9; k++) acc += f[k] * W1[k * 128 + j];
        Hf[e * LDH + j] = fmaxf(acc, 0.f);
    }
    __syncthreads();
    // convert H to bf16 planes
    for (int i = tid; i < 64 * 32; i += 256) {
        int row = i >> 5, c4 = i & 31;
        float4 v = ((const float4*)(Hf + row * LDH))[c4];
        split_store4(v, Hhi + row * LDHB + c4 * 4, Hlo + row * LDHB + c4 * 4);
    }
    __syncthreads();

    CF acc[4];
#pragma unroll
    for (int f = 0; f < 4; f++) wmma::fill_fragment(acc[f], 0.f);

    for (int kk = 0; kk < 128; kk += 16) {
        AF ah, al;
        wmma::load_matrix_sync(ah, Hhi + rt * 16 * LDHB + kk, LDHB);
        wmma::load_matrix_sync(al, Hlo + rt * 16 * LDHB + kk, LDHB);
#pragma unroll
        for (int f = 0; f < 4; f++) {
            BF bh, bl;
            wmma::load_matrix_sync(bh, Whi + kk * LDWB + cg * 64 + f * 16, LDWB);
            wmma::load_matrix_sync(bl, Wlo + kk * LDWB + cg * 64 + f * 16, LDWB);
            wmma::mma_sync(acc[f], ah, bh, acc[f]);
            wmma::mma_sync(acc[f], ah, bl, acc[f]);
            wmma::mma_sync(acc[f], al, bh, acc[f]);
        }
    }
    __syncthreads();
#pragma unroll
    for (int f = 0; f < 4; f++)
        wmma::store_matrix_sync(Hf + rt * 16 * LDH + cg * 64 + f * 16, acc[f], LDH, wmma::mem_row_major);
    __syncthreads();

    for (int i = tid; i < 64 * 32; i += 256) {
        int e = i >> 5, c4 = i & 31;
        float4 c2 = ((const float4*)(Hf + e * LDH))[c4];
        float4 bb = ((const float4*)B2)[c4];
        float4 nv = make_float4(c2.x + bb.x, c2.y + bb.y, c2.z + bb.z, c2.w + bb.w);
        ((float4*)(g_el + (size_t)(ebase + e) * LL))[c4] = nv;
    }
}

// ---------------------------------------------------------------- edge processor step (dominant kernel)
// 128 edges/block, 8 warps, each warp 16 rows x 128 cols (8 accum frags). bf16-split MMAs.
__global__ void __launch_bounds__(256, 1) k_edge_step(
    const int* __restrict__ snd, const int* __restrict__ rcv,
    const float* __restrict__ W1, const float* __restrict__ B1,
    const float* __restrict__ W2, const float* __restrict__ B2)
{
    extern __shared__ char smc[];
    const int LDXB = 80, LDWB = 136, LDH = 132, LDHB = 136;
    __nv_bfloat16* Xhi = (__nv_bfloat16*)(smc + 0);        // 128 x 80
    __nv_bfloat16* Xlo = (__nv_bfloat16*)(smc + 20480);
    __nv_bfloat16* Whi = (__nv_bfloat16*)(smc + 40960);    // 64 x 136
    __nv_bfloat16* Wlo = (__nv_bfloat16*)(smc + 58368);
    float*         Hf  = (float*)(smc + 75776);            // 128 x 132
    __nv_bfloat16* Hhi = (__nv_bfloat16*)(smc + 143360);   // 128 x 136
    __nv_bfloat16* Hlo = (__nv_bfloat16*)(smc + 178176);
    int* ssh = (int*)(smc + 212992);                        // 128
    int* rsh = ssh + 128;                                   // 128
    const int tid = threadIdx.x;
    const int w = tid >> 5;
    const int ebase = blockIdx.x * 128;

    if (tid < 128) {
        ssh[tid] = snd[ebase + tid];
        rsh[tid] = rcv[ebase + tid];
    }

    CF acc[8];
#pragma unroll
    for (int f = 0; f < 8; f++) wmma::fill_fragment(acc[f], 0.f);

    // ---- GEMM1: [128 x 384] @ W1[384 x 128], K chunked by 64
    for (int kc = 0; kc < 384; kc += 64) {
        __syncthreads();
        const int sel = kc >> 7;        // 0: el, 1: nl[s], 2: nl[r]
        const int coff = kc & 127;
        for (int i = tid; i < 128 * 16; i += 256) {
            int e = i >> 4, c4 = i & 15;
            const float* src;
            if (sel == 0)      src = g_el + (size_t)(ebase + e) * LL;
            else if (sel == 1) src = g_nl + (size_t)ssh[e] * LL;
            else               src = g_nl + (size_t)rsh[e] * LL;
            float4 v = ((const float4*)(src + coff))[c4];
            split_store4(v, Xhi + e * LDXB + c4 * 4, Xlo + e * LDXB + c4 * 4);
        }
        const float* wsrc = W1 + (size_t)kc * 128;
        for (int i = tid; i < 64 * 32; i += 256) {
            int rr = i >> 5, c4 = i & 31;
            float4 v = ((const float4*)(wsrc + rr * 128))[c4];
            split_store4(v, Whi + rr * LDWB + c4 * 4, Wlo + rr * LDWB + c4 * 4);
        }
        __syncthreads();
        for (int kk = 0; kk < 64; kk += 16) {
            AF ah, al;
            wmma::load_matrix_sync(ah, Xhi + w * 16 * LDXB + kk, LDXB);
            wmma::load_matrix_sync(al, Xlo + w * 16 * LDXB + kk, LDXB);
#pragma unroll
            for (int f = 0; f < 8; f++) {
                BF bh, bl;
                wmma::load_matrix_sync(bh, Whi + kk * LDWB + f * 16, LDWB);
                wmma::load_matrix_sync(bl, Wlo + kk * LDWB + f * 16, LDWB);
                wmma::mma_sync(acc[f], ah, bh, acc[f]);
                wmma::mma_sync(acc[f], ah, bl, acc[f]);
                wmma::mma_sync(acc[f], al, bh, acc[f]);
            }
        }
    }
    // C1 -> Hf, bias+relu, convert to bf16 planes
#pragma unroll
    for (int f = 0; f < 8; f++)
        wmma::store_matrix_sync(Hf + w * 16 * LDH + f * 16, acc[f], LDH, wmma::mem_row_major);
    __syncthreads();
    for (int i = tid; i < 128 * 32; i += 256) {
        int row = i >> 5, c4 = i & 31;
        float4 v = ((const float4*)(Hf + row * LDH))[c4];
        float4 bb = ((const float4*)B1)[c4];
        v.x = fmaxf(v.x + bb.x, 0.f);
        v.y = fmaxf(v.y + bb.y, 0.f);
        v.z = fmaxf(v.z + bb.z, 0.f);
        v.w = fmaxf(v.w + bb.w, 0.f);
        split_store4(v, Hhi + row * LDHB + c4 * 4, Hlo + row * LDHB + c4 * 4);
    }
    __syncthreads();

    // ---- GEMM2: [128 x 128] @ W2[128 x 128]
#pragma unroll
    for (int f = 0; f < 8; f++) wmma::fill_fragment(acc[f], 0.f);
    for (int kc = 0; kc < 128; kc += 64) {
        const float* wsrc = W2 + (size_t)kc * 128;
        for (int i = tid; i < 64 * 32; i += 256) {
            int rr = i >> 5, c4 = i & 31;
            float4 v = ((const float4*)(wsrc + rr * 128))[c4];
            split_store4(v, Whi + rr * LDWB + c4 * 4, Wlo + rr * LDWB + c4 * 4);
        }
        __syncthreads();
        for (int kk = 0; kk < 64; kk += 16) {
            AF ah, al;
            wmma::load_matrix_sync(ah, Hhi + w * 16 * LDHB + kc + kk, LDHB);
            wmma::load_matrix_sync(al, Hlo + w * 16 * LDHB + kc + kk, LDHB);
#pragma unroll
            for (int f = 0; f < 8; f++) {
                BF bh, bl;
                wmma::load_matrix_sync(bh, Whi + kk * LDWB + f * 16, LDWB);
                wmma::load_matrix_sync(bl, Wlo + kk * LDWB + f * 16, LDWB);
                wmma::mma_sync(acc[f], ah, bh, acc[f]);
                wmma::mma_sync(acc[f], ah, bl, acc[f]);
                wmma::mma_sync(acc[f], al, bh, acc[f]);
            }
        }
        __syncthreads();
    }
    // C2 -> Hf (Hf free: last read was the convert pass)
#pragma unroll
    for (int f = 0; f < 8; f++)
        wmma::store_matrix_sync(Hf + w * 16 * LDH + f * 16, acc[f], LDH, wmma::mem_row_major);
    __syncthreads();

    // epilogue: el += C2 + b2 ; scatter-add into agg
    for (int i = tid; i < 128 * 32; i += 256) {
        int e = i >> 5, c4 = i & 31;
        size_t go = (size_t)(ebase + e) * LL;
        float4 oldv = ((const float4*)(g_el + go))[c4];
        float4 c2 = ((const float4*)(Hf + e * LDH))[c4];
        float4 bb = ((const float4*)B2)[c4];
        float4 nv = make_float4(oldv.x + c2.x + bb.x, oldv.y + c2.y + bb.y,
                                oldv.z + c2.z + bb.z, oldv.w + c2.w + bb.w);
        ((float4*)(g_el + go))[c4] = nv;
        red_add_v4(g_agg + (size_t)rsh[e] * LL + c4 * 4, nv);
    }
}

// ---------------------------------------------------------------- node processor step
// 64 nodes/block, 8 warps as 4x2. Consumes+zeroes agg. bf16-split MMAs.
__global__ void __launch_bounds__(256, 1) k_node_step(
    const float* __restrict__ W1, const float* __restrict__ B1,
    const float* __restrict__ W2, const float* __restrict__ B2)
{
    extern __shared__ char smc[];
    const int LDXB = 264, LDWB = 136, LDH = 132, LDHB = 136;
    __nv_bfloat16* Xhi = (__nv_bfloat16*)(smc + 0);        // 64 x 264
    __nv_bfloat16* Xlo = (__nv_bfloat16*)(smc + 33792);
    __nv_bfloat16* Whi = (__nv_bfloat16*)(smc + 67584);    // 64 x 136
    __nv_bfloat16* Wlo = (__nv_bfloat16*)(smc + 84992);
    float*         Hf  = (float*)(smc + 102400);           // 64 x 132
    __nv_bfloat16* Hhi = (__nv_bfloat16*)(smc + 136192);   // 64 x 136
    __nv_bfloat16* Hlo = (__nv_bfloat16*)(smc + 153600);
    const int tid = threadIdx.x;
    const int w = tid >> 5, rt = w >> 1, cg = w & 1;
    const int nbase = blockIdx.x * 64;

    // X = [nl | agg]; zero agg as we read it
    for (int i = tid; i < 64 * 64; i += 256) {
        int row = i >> 6, c4 = i & 63;
        int n = nbase + row;
        float4 v = make_float4(0.f, 0.f, 0.f, 0.f);
        if (n < NN) {
            if (c4 < 32) {
                v = ((const float4*)(g_nl + (size_t)n * LL))[c4];
            } else {
                float4* ap = (float4*)(g_agg + (size_t)n * LL) + (c4 - 32);
                v = *ap;
                *ap = make_float4(0.f, 0.f, 0.f, 0.f);
            }
        }
        split_store4(v, Xhi + row * LDXB + c4 * 4, Xlo + row * LDXB + c4 * 4);
    }

    CF acc[4];
#pragma unroll
    for (int f = 0; f < 4; f++) wmma::fill_fragment(acc[f], 0.f);

    // GEMM1: [64 x 256] @ W1[256 x 128]
    for (int kc = 0; kc < 256; kc += 64) {
        __syncthreads();
        const float* wsrc = W1 + (size_t)kc * 128;
        for (int i = tid; i < 64 * 32; i += 256) {
            int rr = i >> 5, c4 = i & 31;
            float4 v = ((const float4*)(wsrc + rr * 128))[c4];
            split_store4(v, Whi + rr * LDWB + c4 * 4, Wlo + rr * LDWB + c4 * 4);
        }
        __syncthreads();
        for (int kk = 0; kk < 64; kk += 16) {
            AF ah, al;
            wmma::load_matrix_sync(ah, Xhi + rt * 16 * LDXB + kc + kk, LDXB);
            wmma::load_matrix_sync(al, Xlo + rt * 16 * LDXB + kc + kk, LDXB);
#pragma unroll
            for (int f = 0; f < 4; f++) {
                BF bh, bl;
                wmma::load_matrix_sync(bh, Whi + kk * LDWB + cg * 64 + f * 16, LDWB);
                wmma::load_matrix_sync(bl, Wlo + kk * LDWB + cg * 64 + f * 16, LDWB);
                wmma::mma_sync(acc[f], ah, bh, acc[f]);
                wmma::mma_sync(acc[f], ah, bl, acc[f]);
                wmma::mma_sync(acc[f], al, bh, acc[f]);
            }
        }
    }
    __syncthreads();
#pragma unroll
    for (int f = 0; f < 4; f++)
        wmma::store_matrix_sync(Hf + rt * 16 * LDH + cg * 64 + f * 16, acc[f], LDH, wmma::mem_row_major);
    __syncthreads();
    for (int i = tid; i < 64 * 32; i += 256) {
        int row = i >> 5, c4 = i & 31;
        float4 v = ((const float4*)(Hf + row * LDH))[c4];
        float4 bb = ((const float4*)B1)[c4];
        v.x = fmaxf(v.x + bb.x, 0.f);
        v.y = fmaxf(v.y + bb.y, 0.f);
        v.z = fmaxf(v.z + bb.z, 0.f);
        v.w = fmaxf(v.w + bb.w, 0.f);
        split_store4(v, Hhi + row * LDHB + c4 * 4, Hlo + row * LDHB + c4 * 4);
    }
    __syncthreads();

    // GEMM2: [64 x 128] @ W2[128 x 128]
#pragma unroll
    for (int f = 0; f < 4; f++) wmma::fill_fragment(acc[f], 0.f);
    for (int kc = 0; kc < 128; kc += 64) {
        const float* wsrc = W2 + (size_t)kc * 128;
        for (int i = tid; i < 64 * 32; i += 256) {
            int rr = i >> 5, c4 = i & 31;
            float4 v = ((const float4*)(wsrc + rr * 128))[c4];
            split_store4(v, Whi + rr * LDWB + c4 * 4, Wlo + rr * LDWB + c4 * 4);
        }
        __syncthreads();
        for (int kk = 0; kk < 64; kk += 16) {
            AF ah, al;
            wmma::load_matrix_sync(ah, Hhi + rt * 16 * LDHB + kc + kk, LDHB);
            wmma::load_matrix_sync(al, Hlo + rt * 16 * LDHB + kc + kk, LDHB);
#pragma unroll
            for (int f = 0; f < 4; f++) {
                BF bh, bl;
                wmma::load_matrix_sync(bh, Whi + kk * LDWB + cg * 64 + f * 16, LDWB);
                wmma::load_matrix_sync(bl, Wlo + kk * LDWB + cg * 64 + f * 16, LDWB);
                wmma::mma_sync(acc[f], ah, bh, acc[f]);
                wmma::mma_sync(acc[f], ah, bl, acc[f]);
                wmma::mma_sync(acc[f], al, bh, acc[f]);
            }
        }
        __syncthreads();
    }
#pragma unroll
    for (int f = 0; f < 4; f++)
        wmma::store_matrix_sync(Hf + rt * 16 * LDH + cg * 64 + f * 16, acc[f], LDH, wmma::mem_row_major);
    __syncthreads();

    for (int i = tid; i < 64 * 32; i += 256) {
        int row = i >> 5, c4 = i & 31;
        int n = nbase + row;
        if (n < NN) {
            float4 oldv = ((const float4*)(g_nl + (size_t)n * LL))[c4];
            float4 c2 = ((const float4*)(Hf + row * LDH))[c4];
            float4 bb = ((const float4*)B2)[c4];
            float4 nv = make_float4(oldv.x + c2.x + bb.x, oldv.y + c2.y + bb.y,
                                    oldv.z + c2.z + bb.z, oldv.w + c2.w + bb.w);
            ((float4*)(g_nl + (size_t)n * LL))[c4] = nv;
        }
    }
}

// ---------------------------------------------------------------- decoder (SIMT fp32; exact)
__global__ void __launch_bounds__(128) k_decoder(
    const float* __restrict__ W1, const float* __restrict__ B1,
    const float* __restrict__ W2, const float* __restrict__ B2,
    float* __restrict__ out)
{
    __shared__ float Xs[32][128];
    __shared__ float H[32][128];
    const int tid = threadIdx.x;
    const int nbase = blockIdx.x * 32;

    for (int i = tid; i < 32 * 32; i += 128) {
        int n = i >> 5, c4 = i & 31;
        int gn = nbase + n;
        float4 v = make_float4(0.f, 0.f, 0.f, 0.f);
        if (gn < NN) v = ((const float4*)(g_nl + (size_t)gn * LL))[c4];
        ((float4*)Xs[n])[c4] = v;
    }
    __syncthreads();

    const int j = tid;
#pragma unroll 1
    for (int n = 0; n < 32; n++) {
        float acc = B1[j];
#pragma unroll 8
        for (int k = 0; k < 128; k++) acc += Xs[n][k] * W1[k * 128 + j];
        H[n][j] = fmaxf(acc, 0.f);
    }
    __syncthreads();

    if (tid < 96) {
        int n = tid / 3, d = tid % 3;
        int gn = nbase + n;
        float acc = B2[d];
#pragma unroll 8
        for (int k = 0; k < 128; k++) acc += H[n][k] * W2[k * 3 + d];
        if (gn < NN) out[gn * 3 + d] = acc;
    }
}

// ---------------------------------------------------------------- launch
extern "C" void kernel_launch(void* const* d_in, const int* in_sizes, int n_in,
                              void* d_out, int out_size)
{
    const float* pos   = (const float*)d_in[0];
    const float* vel   = (const float*)d_in[1];
    const int*   rid   = (const int*)d_in[2];
    const int*   snd   = (const int*)d_in[3];
    const int*   rcv   = (const int*)d_in[4];
    const float* remb  = (const float*)d_in[5];
    const float* ne_w1 = (const float*)d_in[6];
    const float* ne_b1 = (const float*)d_in[7];
    const float* ne_w2 = (const float*)d_in[8];
    const float* ne_b2 = (const float*)d_in[9];
    const float* ee_w1 = (const float*)d_in[10];
    const float* ee_b1 = (const float*)d_in[11];
    const float* ee_w2 = (const float*)d_in[12];
    const float* ee_b2 = (const float*)d_in[13];
    const float* pe_w1 = (const float*)d_in[14];
    const float* pe_b1 = (const float*)d_in[15];
    const float* pe_w2 = (const float*)d_in[16];
    const float* pe_b2 = (const float*)d_in[17];
    const float* pn_w1 = (const float*)d_in[18];
    const float* pn_b1 = (const float*)d_in[19];
    const float* pn_w2 = (const float*)d_in[20];
    const float* pn_b2 = (const float*)d_in[21];
    const float* de_w1 = (const float*)d_in[22];
    const float* de_b1 = (const float*)d_in[23];
    const float* de_w2 = (const float*)d_in[24];
    const float* de_b2 = (const float*)d_in[25];

    const int SMEM_ES = 214016;
    const int SMEM_NS = 171008;
    const int SMEM_EE = 141312;

    cudaFuncSetAttribute(k_edge_step, cudaFuncAttributeMaxDynamicSharedMemorySize, SMEM_ES);
    cudaFuncSetAttribute(k_node_step, cudaFuncAttributeMaxDynamicSharedMemorySize, SMEM_NS);
    cudaFuncSetAttribute(k_edge_enc, cudaFuncAttributeMaxDynamicSharedMemorySize, SMEM_EE);

    k_init<<<(NN + 255) / 256, 256>>>();
    k_deg<<<(EE + 255) / 256, 256>>>(rcv);
    k_center<<<104, 256>>>(pos);
    k_node_enc<<<(NN + 31) / 32, 128>>>(pos, vel, rid, remb, ne_w1, ne_b1, ne_w2, ne_b2);
    k_edge_enc<<<EE / 64, 256, SMEM_EE>>>(pos, vel, rid, snd, rcv, ee_w1, ee_b1, ee_w2, ee_b2);

    for (int st = 0; st < NSTEPS; st++) {
        k_edge_step<<<EE / 128, 256, SMEM_ES>>>(
            snd, rcv,
            pe_w1 + (size_t)st * 384 * 128, pe_b1 + (size_t)st * 128,
            pe_w2 + (size_t)st * 128 * 128, pe_b2 + (size_t)st * 128);
        k_node_step<<<(NN + 63) / 64, 256, SMEM_NS>>>(
            pn_w1 + (size_t)st * 256 * 128, pn_b1 + (size_t)st * 128,
            pn_w2 + (size_t)st * 128 * 128, pn_b2 + (size_t)st * 128);
    }

    k_decoder<<<(NN + 31) / 32, 128>>>(de_w1, de_b1, de_w2, de_b2, (float*)d_out);
}

// round 4
// speedup vs baseline: 1.5834x; 1.5834x over previous
#include <cuda_runtime.h>
#include <cuda_bf16.h>
#include <mma.h>
#include <cstdint>

using namespace nvcuda;

#define NN 50000
#define EE 800000
#define LL 128
#define NSTEPS 10

// ---- scratch (device globals; no allocations allowed) ----
__device__ float g_nl[(size_t)NN * LL];     // node latents
__device__ float g_el[(size_t)EE * LL];     // edge latents
__device__ float g_agg[(size_t)NN * LL];    // scatter-add target (zeroed as consumed)
__device__ float g_z[(size_t)NN * 256];     // per-node projections: [0:128)=nl@W1b, [128:256)=nl@W1c
__device__ float g_deg[NN];
__device__ float g_center[3];

// pre-split weight planes (bf16 hi/lo), per step:
//  EW1A (el part of pe_w1, [128K][128N]) hi/lo, EW2 [128][128] hi/lo,
//  PRJ (pe_w1 rows 128..383 as [128K][256N]) hi/lo, NW1 [256][128] hi/lo, NW2 [128][128] hi/lo
#define EW1A_HI 0
#define EW1A_LO 16384
#define EW2_HI  32768
#define EW2_LO  49152
#define PRJ_HI  65536
#define PRJ_LO  98304
#define NW1_HI  131072
#define NW1_LO  163840
#define NW2_HI  196608
#define NW2_LO  212992
#define STEP_W  229376
__device__ __nv_bfloat16 g_ws[(size_t)NSTEPS * STEP_W];

typedef wmma::fragment<wmma::matrix_a, 16, 16, 16, __nv_bfloat16, wmma::row_major> AF;
typedef wmma::fragment<wmma::matrix_b, 16, 16, 16, __nv_bfloat16, wmma::row_major> BF;
typedef wmma::fragment<wmma::accumulator, 16, 16, 16, float> CF;

__device__ __forceinline__ void split_store4(float4 v, __nv_bfloat16* hip, __nv_bfloat16* lop) {
    __nv_bfloat162 h0 = __floats2bfloat162_rn(v.x, v.y);
    __nv_bfloat162 h1 = __floats2bfloat162_rn(v.z, v.w);
    float2 f0 = __bfloat1622float2(h0);
    float2 f1 = __bfloat1622float2(h1);
    __nv_bfloat162 l0 = __floats2bfloat162_rn(v.x - f0.x, v.y - f0.y);
    __nv_bfloat162 l1 = __floats2bfloat162_rn(v.z - f1.x, v.w - f1.y);
    *(__nv_bfloat162*)(hip)     = h0;
    *(__nv_bfloat162*)(hip + 2) = h1;
    *(__nv_bfloat162*)(lop)     = l0;
    *(__nv_bfloat162*)(lop + 2) = l1;
}

__device__ __forceinline__ void red_add_v4(float* dst, float4 v) {
    asm volatile("red.global.add.v4.f32 [%0], {%1,%2,%3,%4};"
                 :: "l"(dst), "f"(v.x), "f"(v.y), "f"(v.z), "f"(v.w) : "memory");
}

// ---------------------------------------------------------------- weight prep (once)
__global__ void __launch_bounds__(256) k_prep_w(
    const float* __restrict__ pe_w1, const float* __restrict__ pe_w2,
    const float* __restrict__ pn_w1, const float* __restrict__ pn_w2)
{
    int idx = blockIdx.x * blockDim.x + threadIdx.x;
    if (idx >= NSTEPS * 114688) return;
    int s = idx / 114688;
    int e = idx % 114688;
    float v;
    size_t dhi, dlo;
    if (e < 16384) {                       // EW1A: pe_w1 rows 0..127
        v = pe_w1[(size_t)s * 384 * 128 + e];
        dhi = EW1A_HI + e; dlo = EW1A_LO + e;
    } else if (e < 32768) {                // EW2
        int e2 = e - 16384;
        v = pe_w2[(size_t)s * 128 * 128 + e2];
        dhi = EW2_HI + e2; dlo = EW2_LO + e2;
    } else if (e < 65536) {                // PRJ: [k][n256], n<128 -> W1b row 128+k, else W1c row 256+k
        int e2 = e - 32768;
        int k = e2 >> 8, n = e2 & 255;
        int srcrow = 128 + (n >> 7) * 128 + k;
        v = pe_w1[(size_t)s * 384 * 128 + (size_t)srcrow * 128 + (n & 127)];
        dhi = PRJ_HI + e2; dlo = PRJ_LO + e2;
    } else if (e < 98304) {                // NW1
        int e2 = e - 65536;
        v = pn_w1[(size_t)s * 256 * 128 + e2];
        dhi = NW1_HI + e2; dlo = NW1_LO + e2;
    } else {                               // NW2
        int e2 = e - 98304;
        v = pn_w2[(size_t)s * 128 * 128 + e2];
        dhi = NW2_HI + e2; dlo = NW2_LO + e2;
    }
    __nv_bfloat16 h = __float2bfloat16(v);
    g_ws[(size_t)s * STEP_W + dhi] = h;
    g_ws[(size_t)s * STEP_W + dlo] = __float2bfloat16(v - __bfloat162float(h));
}

// ---------------------------------------------------------------- init / deg / center
__global__ void k_init() {
    int i = blockIdx.x * blockDim.x + threadIdx.x;
    if (i < NN) g_deg[i] = 0.f;
    if (i < 3) g_center[i] = 0.f;
}

__global__ void k_deg(const int* __restrict__ rcv) {
    int i = blockIdx.x * blockDim.x + threadIdx.x;
    if (i < EE) atomicAdd(&g_deg[rcv[i]], 1.f);
}

__global__ void k_center(const float* __restrict__ pos) {
    float sx = 0.f, sy = 0.f, sz = 0.f;
    for (int i = blockIdx.x * blockDim.x + threadIdx.x; i < NN; i += gridDim.x * blockDim.x) {
        sx += pos[i * 3 + 0];
        sy += pos[i * 3 + 1];
        sz += pos[i * 3 + 2];
    }
#pragma unroll
    for (int o = 16; o > 0; o >>= 1) {
        sx += __shfl_down_sync(0xffffffffu, sx, o);
        sy += __shfl_down_sync(0xffffffffu, sy, o);
        sz += __shfl_down_sync(0xffffffffu, sz, o);
    }
    if ((threadIdx.x & 31) == 0) {
        atomicAdd(&g_center[0], sx);
        atomicAdd(&g_center[1], sy);
        atomicAdd(&g_center[2], sz);
    }
}

// ---------------------------------------------------------------- node encoder (SIMT fp32; exact)
__global__ void __launch_bounds__(128) k_node_enc(
    const float* __restrict__ pos, const float* __restrict__ vel,
    const int* __restrict__ rid, const float* __restrict__ remb,
    const float* __restrict__ W1, const float* __restrict__ B1,
    const float* __restrict__ W2, const float* __restrict__ B2)
{
    __shared__ float F[32][24];
    __shared__ float H[32][128];
    const int tid = threadIdx.x;
    const int nbase = blockIdx.x * 32;
    const float inv = 1.f / (float)NN;
    const float cx = g_center[0] * inv, cy = g_center[1] * inv, cz = g_center[2] * inv;

    for (int i = tid; i < 32 * 23; i += 128) {
        int n = i / 23, k = i % 23;
        int gn = nbase + n;
        float v = 0.f;
        if (gn < NN) {
            if (k < 3) v = vel[gn * 3 + k];
            else if (k < 6) v = pos[gn * 3 + (k - 3)] - ((k == 3) ? cx : (k == 4) ? cy : cz);
            else if (k == 6) v = g_deg[gn];
            else v = remb[rid[gn] * 16 + (k - 7)];
        }
        F[n][k] = v;
    }
    __syncthreads();

    const int j = tid;
#pragma unroll 1
    for (int n = 0; n < 32; n++) {
        float acc = B1[j];
#pragma unroll
        for (int k = 0; k < 23; k++) acc += F[n][k] * W1[k * 128 + j];
        H[n][j] = fmaxf(acc, 0.f);
    }
    __syncthreads();
#pragma unroll 1
    for (int n = 0; n < 32; n++) {
        int gn = nbase + n;
        float acc = B2[j];
#pragma unroll 8
        for (int k = 0; k < 128; k++) acc += H[n][k] * W2[k * 128 + j];
        if (gn < NN) g_nl[(size_t)gn * LL + j] = acc;
    }
}

// ---------------------------------------------------------------- edge encoder (wmma bf16-split)
__global__ void __launch_bounds__(256, 1) k_edge_enc(
    const float* __restrict__ pos, const float* __restrict__ vel,
    const int* __restrict__ rid,
    const int* __restrict__ snd, const int* __restrict__ rcv,
    const float* __restrict__ W1, const float* __restrict__ B1,
    const float* __restrict__ W2, const float* __restrict__ B2)
{
    extern __shared__ char smc[];
    const int LDF = 12, LDH = 132, LDHB = 136, LDWB = 136;
    float*         F   = (float*)(smc + 0);
    float*         Hf  = (float*)(smc + 3072);
    __nv_bfloat16* Hhi = (__nv_bfloat16*)(smc + 36864);
    __nv_bfloat16* Hlo = (__nv_bfloat16*)(smc + 54272);
    __nv_bfloat16* Whi = (__nv_bfloat16*)(smc + 71680);
    __nv_bfloat16* Wlo = (__nv_bfloat16*)(smc + 106496);
    const int tid = threadIdx.x;
    const int w = tid >> 5, rt = w >> 1, cg = w & 1;
    const int ebase = blockIdx.x * 64;

    if (tid < 64) {
        int e = ebase + tid;
        int s = snd[e], r = rcv[e];
        float rp0 = pos[s * 3 + 0] - pos[r * 3 + 0];
        float rp1 = pos[s * 3 + 1] - pos[r * 3 + 1];
        float rp2 = pos[s * 3 + 2] - pos[r * 3 + 2];
        float rv0 = vel[s * 3 + 0] - vel[r * 3 + 0];
        float rv1 = vel[s * 3 + 1] - vel[r * 3 + 1];
        float rv2 = vel[s * 3 + 2] - vel[r * 3 + 2];
        float sq = rp0 * rp0 + rp1 * rp1 + rp2 * rp2;
        float dist = sqrtf(sq);
        float same = (rid[s] == rid[r]) ? 1.f : 0.f;
        float* f = F + tid * LDF;
        f[0] = rp0; f[1] = rp1; f[2] = rp2;
        f[3] = rv0; f[4] = rv1; f[5] = rv2;
        f[6] = dist; f[7] = sq; f[8] = same;
    }
    for (int i = tid; i < 128 * 32; i += 256) {
        int rr = i >> 5, c4 = i & 31;
        float4 v = ((const float4*)(W2 + rr * 128))[c4];
        split_store4(v, Whi + rr * LDWB + c4 * 4, Wlo + rr * LDWB + c4 * 4);
    }
    __syncthreads();

    for (int i = tid; i < 64 * 128; i += 256) {
        int e = i >> 7, j = i & 127;
        const float* f = F + e * LDF;
        float acc = B1[j];
#pragma unroll
        for (int k = 0; k < 9; k++) acc += f[k] * W1[k * 128 + j];
        Hf[e * LDH + j] = fmaxf(acc, 0.f);
    }
    __syncthreads();
    for (int i = tid; i < 64 * 32; i += 256) {
        int row = i >> 5, c4 = i & 31;
        float4 v = ((const float4*)(Hf + row * LDH))[c4];
        split_store4(v, Hhi + row * LDHB + c4 * 4, Hlo + row * LDHB + c4 * 4);
    }
    __syncthreads();

    CF acc[4];
#pragma unroll
    for (int f = 0; f < 4; f++) wmma::fill_fragment(acc[f], 0.f);

    for (int kk = 0; kk < 128; kk += 16) {
        AF ah, al;
        wmma::load_matrix_sync(ah, Hhi + rt * 16 * LDHB + kk, LDHB);
        wmma::load_matrix_sync(al, Hlo + rt * 16 * LDHB + kk, LDHB);
#pragma unroll
        for (int f = 0; f < 4; f++) {
            BF bh, bl;
            wmma::load_matrix_sync(bh, Whi + kk * LDWB + cg * 64 + f * 16, LDWB);
            wmma::load_matrix_sync(bl, Wlo + kk * LDWB + cg * 64 + f * 16, LDWB);
            wmma::mma_sync(acc[f], ah, bh, acc[f]);
            wmma::mma_sync(acc[f], ah, bl, acc[f]);
            wmma::mma_sync(acc[f], al, bh, acc[f]);
        }
    }
    __syncthreads();
#pragma unroll
    for (int f = 0; f < 4; f++)
        wmma::store_matrix_sync(Hf + rt * 16 * LDH + cg * 64 + f * 16, acc[f], LDH, wmma::mem_row_major);
    __syncthreads();

    for (int i = tid; i < 64 * 32; i += 256) {
        int e = i >> 5, c4 = i & 31;
        float4 c2 = ((const float4*)(Hf + e * LDH))[c4];
        float4 bb = ((const float4*)B2)[c4];
        float4 nv = make_float4(c2.x + bb.x, c2.y + bb.y, c2.z + bb.z, c2.w + bb.w);
        ((float4*)(g_el + (size_t)(ebase + e) * LL))[c4] = nv;
    }
}

// ---------------------------------------------------------------- node projector: Z = nl @ [W1b | W1c]
// 64 nodes/block, 256 threads, 8 warps (4 row x 2 col, each 16 rows x 128 cols).
#define PJ_AHI 0
#define PJ_ALO 17408
#define PJ_WHI 34816
#define PJ_WLO 102400
#define PJ_SMEM 169984

__global__ void __launch_bounds__(256, 1) k_node_project(int step)
{
    extern __shared__ char smc[];
    __nv_bfloat16* Ahi = (__nv_bfloat16*)(smc + PJ_AHI);   // 64 x 136
    __nv_bfloat16* Alo = (__nv_bfloat16*)(smc + PJ_ALO);
    __nv_bfloat16* Whi = (__nv_bfloat16*)(smc + PJ_WHI);   // 128 x 264
    __nv_bfloat16* Wlo = (__nv_bfloat16*)(smc + PJ_WLO);
    const int tid = threadIdx.x;
    const int w = tid >> 5, rt = w >> 1, cg = w & 1;
    const int nbase = blockIdx.x * 64;
    const bool full = (nbase + 64 <= NN);
    const __nv_bfloat16* wh = g_ws + (size_t)step * STEP_W + PRJ_HI;
    const __nv_bfloat16* wl = g_ws + (size_t)step * STEP_W + PRJ_LO;

    // load nl rows, split
    for (int i = tid; i < 64 * 32; i += 256) {
        int row = i >> 5, c4 = i & 31;
        int n = nbase + row;
        float4 v = make_float4(0.f, 0.f, 0.f, 0.f);
        if (n < NN) v = ((const float4*)(g_nl + (size_t)n * LL))[c4];
        split_store4(v, Ahi + row * 136 + c4 * 4, Alo + row * 136 + c4 * 4);
    }
    // stage W' planes [128][256] -> stride 264
    for (int i = tid; i < 128 * 32; i += 256) {
        int rr = i >> 5, g = i & 31;
        *(float4*)(Whi + rr * 264 + g * 8) = ((const float4*)(wh + rr * 256))[g];
        *(float4*)(Wlo + rr * 264 + g * 8) = ((const float4*)(wl + rr * 256))[g];
    }
    __syncthreads();

    CF acc[8];
#pragma unroll
    for (int f = 0; f < 8; f++) wmma::fill_fragment(acc[f], 0.f);
    for (int kk = 0; kk < 128; kk += 16) {
        AF ah, al;
        wmma::load_matrix_sync(ah, Ahi + rt * 16 * 136 + kk, 136);
        wmma::load_matrix_sync(al, Alo + rt * 16 * 136 + kk, 136);
#pragma unroll
        for (int f = 0; f < 8; f++) {
            BF bh, bl;
            wmma::load_matrix_sync(bh, Whi + kk * 264 + cg * 128 + f * 16, 264);
            wmma::load_matrix_sync(bl, Wlo + kk * 264 + cg * 128 + f * 16, 264);
            wmma::mma_sync(acc[f], ah, bh, acc[f]);
            wmma::mma_sync(acc[f], ah, bl, acc[f]);
            wmma::mma_sync(acc[f], al, bh, acc[f]);
        }
    }

    if (full) {
#pragma unroll
        for (int f = 0; f < 8; f++)
            wmma::store_matrix_sync(g_z + (size_t)(nbase + rt * 16) * 256 + cg * 128 + f * 16,
                                    acc[f], 256, wmma::mem_row_major);
    } else {
        float* Csm = (float*)(smc + PJ_WHI);   // 64 x 260 (W region dead)
        __syncthreads();
#pragma unroll
        for (int f = 0; f < 8; f++)
            wmma::store_matrix_sync(Csm + rt * 16 * 260 + cg * 128 + f * 16, acc[f], 260, wmma::mem_row_major);
        __syncthreads();
        for (int i = tid; i < 64 * 64; i += 256) {
            int row = i >> 6, g = i & 63;
            int n = nbase + row;
            if (n < NN)
                ((float4*)(g_z + (size_t)n * 256))[g] = *(float4*)(Csm + row * 260 + g * 4);
        }
    }
}

// ---------------------------------------------------------------- edge processor step
// 128 edges/block, 512 threads, 16 warps (8 row x 2 col, each 16 rows x 64 cols).
// GEMM1: el @ W1a (K=128); epilogue adds Z[s], Z[r], B1, relu; GEMM2: H @ W2; residual + scatter.
#define ES_SSH 0
#define ES_RSH 512
#define ES_B1  1024
#define ES_B2  1536
#define ES_AHI 2048
#define ES_ALO 36864
#define ES_WHI 71680
#define ES_WLO 106496
#define ES_CF  141312
#define ES_SMEM 208896

__global__ void __launch_bounds__(512, 1) k_edge_step(
    const int* __restrict__ snd, const int* __restrict__ rcv, int step,
    const float* __restrict__ B1, const float* __restrict__ B2)
{
    extern __shared__ char smc[];
    int*   ssh = (int*)(smc + ES_SSH);
    int*   rsh = (int*)(smc + ES_RSH);
    float* B1s = (float*)(smc + ES_B1);
    float* B2s = (float*)(smc + ES_B2);
    __nv_bfloat16* Ahi = (__nv_bfloat16*)(smc + ES_AHI);   // 128 x 136
    __nv_bfloat16* Alo = (__nv_bfloat16*)(smc + ES_ALO);
    __nv_bfloat16* Whi = (__nv_bfloat16*)(smc + ES_WHI);   // 128 x 136
    __nv_bfloat16* Wlo = (__nv_bfloat16*)(smc + ES_WLO);
    float*         Cf  = (float*)(smc + ES_CF);            // 128 x 132
    const int tid = threadIdx.x;
    const int w = tid >> 5, rt = w >> 1, cg = w & 1;
    const int ebase = blockIdx.x * 128;
    const __nv_bfloat16* wbase = g_ws + (size_t)step * STEP_W;

    if (tid < 128) {
        ssh[tid] = snd[ebase + tid];
        rsh[tid] = rcv[ebase + tid];
        B1s[tid] = B1[tid];
        B2s[tid] = B2[tid];
    }
    // gather el rows, split
    for (int i = tid; i < 128 * 32; i += 512) {
        int row = i >> 5, c4 = i & 31;
        float4 v = ((const float4*)(g_el + (size_t)(ebase + row) * LL))[c4];
        split_store4(v, Ahi + row * 136 + c4 * 4, Alo + row * 136 + c4 * 4);
    }
    // stage W1a planes
    for (int i = tid; i < 128 * 16; i += 512) {
        int rr = i >> 4, g = i & 15;
        *(float4*)(Whi + rr * 136 + g * 8) = ((const float4*)(wbase + EW1A_HI + rr * 128))[g];
        *(float4*)(Wlo + rr * 136 + g * 8) = ((const float4*)(wbase + EW1A_LO + rr * 128))[g];
    }
    __syncthreads();

    // ---- GEMM1: el @ W1a
    CF acc[4];
#pragma unroll
    for (int f = 0; f < 4; f++) wmma::fill_fragment(acc[f], 0.f);
    for (int kk = 0; kk < 128; kk += 16) {
        AF ah, al;
        wmma::load_matrix_sync(ah, Ahi + rt * 16 * 136 + kk, 136);
        wmma::load_matrix_sync(al, Alo + rt * 16 * 136 + kk, 136);
#pragma unroll
        for (int f = 0; f < 4; f++) {
            BF bh, bl;
            wmma::load_matrix_sync(bh, Whi + kk * 136 + cg * 64 + f * 16, 136);
            wmma::load_matrix_sync(bl, Wlo + kk * 136 + cg * 64 + f * 16, 136);
            wmma::mma_sync(acc[f], ah, bh, acc[f]);
            wmma::mma_sync(acc[f], ah, bl, acc[f]);
            wmma::mma_sync(acc[f], al, bh, acc[f]);
        }
    }
#pragma unroll
    for (int f = 0; f < 4; f++)
        wmma::store_matrix_sync(Cf + rt * 16 * 132 + cg * 64 + f * 16, acc[f], 132, wmma::mem_row_major);
    __syncthreads();

    // ---- epilogue 1: C1 + Z[s] + Z[r] + B1, relu -> H planes (overwrite A); stage W2
    for (int i = tid; i < 128 * 32; i += 512) {
        int row = i >> 5, c4 = i & 31;
        int s = ssh[row], r = rsh[row];
        float4 c = *(float4*)(Cf + row * 132 + c4 * 4);
        float4 zb = ((const float4*)(g_z + (size_t)s * 256))[c4];
        float4 zc = ((const float4*)(g_z + (size_t)r * 256 + 128))[c4];
        float4 b = ((const float4*)B1s)[c4];
        float4 v = make_float4(
            fmaxf(c.x + zb.x + zc.x + b.x, 0.f),
            fmaxf(c.y + zb.y + zc.y + b.y, 0.f),
            fmaxf(c.z + zb.z + zc.z + b.z, 0.f),
            fmaxf(c.w + zb.w + zc.w + b.w, 0.f));
        split_store4(v, Ahi + row * 136 + c4 * 4, Alo + row * 136 + c4 * 4);
    }
    for (int i = tid; i < 128 * 16; i += 512) {
        int rr = i >> 4, g = i & 15;
        *(float4*)(Whi + rr * 136 + g * 8) = ((const float4*)(wbase + EW2_HI + rr * 128))[g];
        *(float4*)(Wlo + rr * 136 + g * 8) = ((const float4*)(wbase + EW2_LO + rr * 128))[g];
    }
    __syncthreads();

    // ---- GEMM2: H @ W2
#pragma unroll
    for (int f = 0; f < 4; f++) wmma::fill_fragment(acc[f], 0.f);
    for (int kk = 0; kk < 128; kk += 16) {
        AF ah, al;
        wmma::load_matrix_sync(ah, Ahi + rt * 16 * 136 + kk, 136);
        wmma::load_matrix_sync(al, Alo + rt * 16 * 136 + kk, 136);
#pragma unroll
        for (int f = 0; f < 4; f++) {
            BF bh, bl;
            wmma::load_matrix_sync(bh, Whi + kk * 136 + cg * 64 + f * 16, 136);
            wmma::load_matrix_sync(bl, Wlo + kk * 136 + cg * 64 + f * 16, 136);
            wmma::mma_sync(acc[f], ah, bh, acc[f]);
            wmma::mma_sync(acc[f], ah, bl, acc[f]);
            wmma::mma_sync(acc[f], al, bh, acc[f]);
        }
    }
#pragma unroll
    for (int f = 0; f < 4; f++)
        wmma::store_matrix_sync(Cf + rt * 16 * 132 + cg * 64 + f * 16, acc[f], 132, wmma::mem_row_major);
    __syncthreads();

    // ---- epilogue 2: el += C2 + b2; scatter-add into agg
    for (int i = tid; i < 128 * 32; i += 512) {
        int row = i >> 5, c4 = i & 31;
        size_t go = (size_t)(ebase + row) * LL;
        float4 oldv = ((const float4*)(g_el + go))[c4];
        float4 c = *(float4*)(Cf + row * 132 + c4 * 4);
        float4 b = ((const float4*)B2s)[c4];
        float4 nv = make_float4(oldv.x + c.x + b.x, oldv.y + c.y + b.y,
                                oldv.z + c.z + b.z, oldv.w + c.w + b.w);
        ((float4*)(g_el + go))[c4] = nv;
        red_add_v4(g_agg + (size_t)rsh[row] * LL + c4 * 4, nv);
    }
}

// ---------------------------------------------------------------- node processor step (pre-split weights)
__global__ void __launch_bounds__(256, 1) k_node_step(
    int step, const float* __restrict__ B1, const float* __restrict__ B2)
{
    extern __shared__ char smc[];
    const int LDXB = 264, LDWB = 136, LDH = 132, LDHB = 136;
    __nv_bfloat16* Xhi = (__nv_bfloat16*)(smc + 0);        // 64 x 264
    __nv_bfloat16* Xlo = (__nv_bfloat16*)(smc + 33792);
    __nv_bfloat16* Whi = (__nv_bfloat16*)(smc + 67584);    // 64 x 136
    __nv_bfloat16* Wlo = (__nv_bfloat16*)(smc + 84992);
    float*         Hf  = (float*)(smc + 102400);           // 64 x 132
    __nv_bfloat16* Hhi = (__nv_bfloat16*)(smc + 136192);
    __nv_bfloat16* Hlo = (__nv_bfloat16*)(smc + 153600);
    const int tid = threadIdx.x;
    const int w = tid >> 5, rt = w >> 1, cg = w & 1;
    const int nbase = blockIdx.x * 64;
    const __nv_bfloat16* wbase = g_ws + (size_t)step * STEP_W;

    for (int i = tid; i < 64 * 64; i += 256) {
        int row = i >> 6, c4 = i & 63;
        int n = nbase + row;
        float4 v = make_float4(0.f, 0.f, 0.f, 0.f);
        if (n < NN) {
            if (c4 < 32) {
                v = ((const float4*)(g_nl + (size_t)n * LL))[c4];
            } else {
                float4* ap = (float4*)(g_agg + (size_t)n * LL) + (c4 - 32);
                v = *ap;
                *ap = make_float4(0.f, 0.f, 0.f, 0.f);
            }
        }
        split_store4(v, Xhi + row * LDXB + c4 * 4, Xlo + row * LDXB + c4 * 4);
    }

    CF acc[4];
#pragma unroll
    for (int f = 0; f < 4; f++) wmma::fill_fragment(acc[f], 0.f);

    for (int kc = 0; kc < 256; kc += 64) {
        __syncthreads();
        for (int i = tid; i < 64 * 16; i += 256) {
            int rr = i >> 4, g = i & 15;
            *(float4*)(Whi + rr * LDWB + g * 8) = ((const float4*)(wbase + NW1_HI + (kc + rr) * 128))[g];
            *(float4*)(Wlo + rr * LDWB + g * 8) = ((const float4*)(wbase + NW1_LO + (kc + rr) * 128))[g];
        }
        __syncthreads();
        for (int kk = 0; kk < 64; kk += 16) {
            AF ah, al;
            wmma::load_matrix_sync(ah, Xhi + rt * 16 * LDXB + kc + kk, LDXB);
            wmma::load_matrix_sync(al, Xlo + rt * 16 * LDXB + kc + kk, LDXB);
#pragma unroll
            for (int f = 0; f < 4; f++) {
                BF bh, bl;
                wmma::load_matrix_sync(bh, Whi + kk * LDWB + cg * 64 + f * 16, LDWB);
                wmma::load_matrix_sync(bl, Wlo + kk * LDWB + cg * 64 + f * 16, LDWB);
                wmma::mma_sync(acc[f], ah, bh, acc[f]);
                wmma::mma_sync(acc[f], ah, bl, acc[f]);
                wmma::mma_sync(acc[f], al, bh, acc[f]);
            }
        }
    }
    __syncthreads();
#pragma unroll
    for (int f = 0; f < 4; f++)
        wmma::store_matrix_sync(Hf + rt * 16 * LDH + cg * 64 + f * 16, acc[f], LDH, wmma::mem_row_major);
    __syncthreads();
    for (int i = tid; i < 64 * 32; i += 256) {
        int row = i >> 5, c4 = i & 31;
        float4 v = ((const float4*)(Hf + row * LDH))[c4];
        float4 bb = ((const float4*)B1)[c4];
        v.x = fmaxf(v.x + bb.x, 0.f);
        v.y = fmaxf(v.y + bb.y, 0.f);
        v.z = fmaxf(v.z + bb.z, 0.f);
        v.w = fmaxf(v.w + bb.w, 0.f);
        split_store4(v, Hhi + row * LDHB + c4 * 4, Hlo + row * LDHB + c4 * 4);
    }
    __syncthreads();

#pragma unroll
    for (int f = 0; f < 4; f++) wmma::fill_fragment(acc[f], 0.f);
    for (int kc = 0; kc < 128; kc += 64) {
        for (int i = tid; i < 64 * 16; i += 256) {
            int rr = i >> 4, g = i & 15;
            *(float4*)(Whi + rr * LDWB + g * 8) = ((const float4*)(wbase + NW2_HI + (kc + rr) * 128))[g];
            *(float4*)(Wlo + rr * LDWB + g * 8) = ((const float4*)(wbase + NW2_LO + (kc + rr) * 128))[g];
        }
        __syncthreads();
        for (int kk = 0; kk < 64; kk += 16) {
            AF ah, al;
            wmma::load_matrix_sync(ah, Hhi + rt * 16 * LDHB + kc + kk, LDHB);
            wmma::load_matrix_sync(al, Hlo + rt * 16 * LDHB + kc + kk, LDHB);
#pragma unroll
            for (int f = 0; f < 4; f++) {
                BF bh, bl;
                wmma::load_matrix_sync(bh, Whi + kk * LDWB + cg * 64 + f * 16, LDWB);
                wmma::load_matrix_sync(bl, Wlo + kk * LDWB + cg * 64 + f * 16, LDWB);
                wmma::mma_sync(acc[f], ah, bh, acc[f]);
                wmma::mma_sync(acc[f], ah, bl, acc[f]);
                wmma::mma_sync(acc[f], al, bh, acc[f]);
            }
        }
        __syncthreads();
    }
#pragma unroll
    for (int f = 0; f < 4; f++)
        wmma::store_matrix_sync(Hf + rt * 16 * LDH + cg * 64 + f * 16, acc[f], LDH, wmma::mem_row_major);
    __syncthreads();

    for (int i = tid; i < 64 * 32; i += 256) {
        int row = i >> 5, c4 = i & 31;
        int n = nbase + row;
        if (n < NN) {
            float4 oldv = ((const float4*)(g_nl + (size_t)n * LL))[c4];
            float4 c2 = ((const float4*)(Hf + row * LDH))[c4];
            float4 bb = ((const float4*)B2)[c4];
            float4 nv = make_float4(oldv.x + c2.x + bb.x, oldv.y + c2.y + bb.y,
                                    oldv.z + c2.z + bb.z, oldv.w + c2.w + bb.w);
            ((float4*)(g_nl + (size_t)n * LL))[c4] = nv;
        }
    }
}

// ---------------------------------------------------------------- decoder (SIMT fp32; exact)
__global__ void __launch_bounds__(128) k_decoder(
    const float* __restrict__ W1, const float* __restrict__ B1,
    const float* __restrict__ W2, const float* __restrict__ B2,
    float* __restrict__ out)
{
    __shared__ float Xs[32][128];
    __shared__ float H[32][128];
    const int tid = threadIdx.x;
    const int nbase = blockIdx.x * 32;

    for (int i = tid; i < 32 * 32; i += 128) {
        int n = i >> 5, c4 = i & 31;
        int gn = nbase + n;
        float4 v = make_float4(0.f, 0.f, 0.f, 0.f);
        if (gn < NN) v = ((const float4*)(g_nl + (size_t)gn * LL))[c4];
        ((float4*)Xs[n])[c4] = v;
    }
    __syncthreads();

    const int j = tid;
#pragma unroll 1
    for (int n = 0; n < 32; n++) {
        float acc = B1[j];
#pragma unroll 8
        for (int k = 0; k < 128; k++) acc += Xs[n][k] * W1[k * 128 + j];
        H[n][j] = fmaxf(acc, 0.f);
    }
    __syncthreads();

    if (tid < 96) {
        int n = tid / 3, d = tid % 3;
        int gn = nbase + n;
        float acc = B2[d];
#pragma unroll 8
        for (int k = 0; k < 128; k++) acc += H[n][k] * W2[k * 3 + d];
        if (gn < NN) out[gn * 3 + d] = acc;
    }
}

// ---------------------------------------------------------------- launch
extern "C" void kernel_launch(void* const* d_in, const int* in_sizes, int n_in,
                              void* d_out, int out_size)
{
    const float* pos   = (const float*)d_in[0];
    const float* vel   = (const float*)d_in[1];
    const int*   rid   = (const int*)d_in[2];
    const int*   snd   = (const int*)d_in[3];
    const int*   rcv   = (const int*)d_in[4];
    const float* remb  = (const float*)d_in[5];
    const float* ne_w1 = (const float*)d_in[6];
    const float* ne_b1 = (const float*)d_in[7];
    const float* ne_w2 = (const float*)d_in[8];
    const float* ne_b2 = (const float*)d_in[9];
    const float* ee_w1 = (const float*)d_in[10];
    const float* ee_b1 = (const float*)d_in[11];
    const float* ee_w2 = (const float*)d_in[12];
    const float* ee_b2 = (const float*)d_in[13];
    const float* pe_w1 = (const float*)d_in[14];
    const float* pe_b1 = (const float*)d_in[15];
    const float* pe_w2 = (const float*)d_in[16];
    const float* pe_b2 = (const float*)d_in[17];
    const float* pn_w1 = (const float*)d_in[18];
    const float* pn_b1 = (const float*)d_in[19];
    const float* pn_w2 = (const float*)d_in[20];
    const float* pn_b2 = (const float*)d_in[21];
    const float* de_w1 = (const float*)d_in[22];
    const float* de_b1 = (const float*)d_in[23];
    const float* de_w2 = (const float*)d_in[24];
    const float* de_b2 = (const float*)d_in[25];

    const int SMEM_NS = 171008;
    const int SMEM_EE = 141312;

    cudaFuncSetAttribute(k_edge_step, cudaFuncAttributeMaxDynamicSharedMemorySize, ES_SMEM);
    cudaFuncSetAttribute(k_node_step, cudaFuncAttributeMaxDynamicSharedMemorySize, SMEM_NS);
    cudaFuncSetAttribute(k_edge_enc, cudaFuncAttributeMaxDynamicSharedMemorySize, SMEM_EE);
    cudaFuncSetAttribute(k_node_project, cudaFuncAttributeMaxDynamicSharedMemorySize, PJ_SMEM);

    k_prep_w<<<(NSTEPS * 114688 + 255) / 256, 256>>>(pe_w1, pe_w2, pn_w1, pn_w2);
    k_init<<<(NN + 255) / 256, 256>>>();
    k_deg<<<(EE + 255) / 256, 256>>>(rcv);
    k_center<<<104, 256>>>(pos);
    k_node_enc<<<(NN + 31) / 32, 128>>>(pos, vel, rid, remb, ne_w1, ne_b1, ne_w2, ne_b2);
    k_edge_enc<<<EE / 64, 256, SMEM_EE>>>(pos, vel, rid, snd, rcv, ee_w1, ee_b1, ee_w2, ee_b2);

    for (int st = 0; st < NSTEPS; st++) {
        k_node_project<<<(NN + 63) / 64, 256, PJ_SMEM>>>(st);
        k_edge_step<<<EE / 128, 512, ES_SMEM>>>(
            snd, rcv, st, pe_b1 + (size_t)st * 128, pe_b2 + (size_t)st * 128);
        k_node_step<<<(NN + 63) / 64, 256, SMEM_NS>>>(
            st, pn_b1 + (size_t)st * 128, pn_b2 + (size_t)st * 128);
    }

    k_decoder<<<(NN + 31) / 32, 128>>>(de_w1, de_b1, de_w2, de_b2, (float*)d_out);
}

// round 5
// speedup vs baseline: 1.7083x; 1.0789x over previous
#include <cuda_runtime.h>
#include <cuda_bf16.h>
#include <mma.h>
#include <cstdint>

using namespace nvcuda;

#define NN 50000
#define EE 800000
#define LL 128
#define NSTEPS 10

// ---- scratch (device globals; no allocations allowed) ----
__device__ float g_nl[(size_t)NN * LL];     // node latents
__device__ float g_el[(size_t)EE * LL];     // edge latents
__device__ float g_agg[(size_t)NN * LL];    // scatter-add target (zeroed as consumed)
__device__ float g_z[(size_t)NN * 256];     // per-node projections: [0:128)=nl@W1b, [128:256)=nl@W1c
__device__ float g_deg[NN];
__device__ float g_center[3];

// pre-split weight planes (bf16 hi/lo), per step
#define EW1A_HI 0
#define EW1A_LO 16384
#define EW2_HI  32768
#define EW2_LO  49152
#define PRJ_HI  65536
#define PRJ_LO  98304
#define NW1_HI  131072
#define NW1_LO  163840
#define NW2_HI  196608
#define NW2_LO  212992
#define STEP_W  229376
__device__ __nv_bfloat16 g_ws[(size_t)NSTEPS * STEP_W];

typedef wmma::fragment<wmma::matrix_a, 16, 16, 16, __nv_bfloat16, wmma::row_major> AF;
typedef wmma::fragment<wmma::matrix_b, 16, 16, 16, __nv_bfloat16, wmma::row_major> BF;
typedef wmma::fragment<wmma::accumulator, 16, 16, 16, float> CF;

__device__ __forceinline__ void split_store4(float4 v, __nv_bfloat16* hip, __nv_bfloat16* lop) {
    __nv_bfloat162 h0 = __floats2bfloat162_rn(v.x, v.y);
    __nv_bfloat162 h1 = __floats2bfloat162_rn(v.z, v.w);
    float2 f0 = __bfloat1622float2(h0);
    float2 f1 = __bfloat1622float2(h1);
    __nv_bfloat162 l0 = __floats2bfloat162_rn(v.x - f0.x, v.y - f0.y);
    __nv_bfloat162 l1 = __floats2bfloat162_rn(v.z - f1.x, v.w - f1.y);
    *(__nv_bfloat162*)(hip)     = h0;
    *(__nv_bfloat162*)(hip + 2) = h1;
    *(__nv_bfloat162*)(lop)     = l0;
    *(__nv_bfloat162*)(lop + 2) = l1;
}

__device__ __forceinline__ void red_add_v4(float* dst, float4 v) {
    asm volatile("red.global.add.v4.f32 [%0], {%1,%2,%3,%4};"
                 :: "l"(dst), "f"(v.x), "f"(v.y), "f"(v.z), "f"(v.w) : "memory");
}

// ---------------------------------------------------------------- weight prep (once)
__global__ void __launch_bounds__(256) k_prep_w(
    const float* __restrict__ pe_w1, const float* __restrict__ pe_w2,
    const float* __restrict__ pn_w1, const float* __restrict__ pn_w2)
{
    int idx = blockIdx.x * blockDim.x + threadIdx.x;
    if (idx >= NSTEPS * 114688) return;
    int s = idx / 114688;
    int e = idx % 114688;
    float v;
    size_t dhi, dlo;
    if (e < 16384) {
        v = pe_w1[(size_t)s * 384 * 128 + e];
        dhi = EW1A_HI + e; dlo = EW1A_LO + e;
    } else if (e < 32768) {
        int e2 = e - 16384;
        v = pe_w2[(size_t)s * 128 * 128 + e2];
        dhi = EW2_HI + e2; dlo = EW2_LO + e2;
    } else if (e < 65536) {
        int e2 = e - 32768;
        int k = e2 >> 8, n = e2 & 255;
        int srcrow = 128 + (n >> 7) * 128 + k;
        v = pe_w1[(size_t)s * 384 * 128 + (size_t)srcrow * 128 + (n & 127)];
        dhi = PRJ_HI + e2; dlo = PRJ_LO + e2;
    } else if (e < 98304) {
        int e2 = e - 65536;
        v = pn_w1[(size_t)s * 256 * 128 + e2];
        dhi = NW1_HI + e2; dlo = NW1_LO + e2;
    } else {
        int e2 = e - 98304;
        v = pn_w2[(size_t)s * 128 * 128 + e2];
        dhi = NW2_HI + e2; dlo = NW2_LO + e2;
    }
    __nv_bfloat16 h = __float2bfloat16(v);
    g_ws[(size_t)s * STEP_W + dhi] = h;
    g_ws[(size_t)s * STEP_W + dlo] = __float2bfloat16(v - __bfloat162float(h));
}

// ---------------------------------------------------------------- init / deg / center
__global__ void k_init() {
    int i = blockIdx.x * blockDim.x + threadIdx.x;
    if (i < NN) g_deg[i] = 0.f;
    if (i < 3) g_center[i] = 0.f;
}

__global__ void k_deg(const int* __restrict__ rcv) {
    int i = blockIdx.x * blockDim.x + threadIdx.x;
    if (i < EE) atomicAdd(&g_deg[rcv[i]], 1.f);
}

__global__ void k_center(const float* __restrict__ pos) {
    float sx = 0.f, sy = 0.f, sz = 0.f;
    for (int i = blockIdx.x * blockDim.x + threadIdx.x; i < NN; i += gridDim.x * blockDim.x) {
        sx += pos[i * 3 + 0];
        sy += pos[i * 3 + 1];
        sz += pos[i * 3 + 2];
    }
#pragma unroll
    for (int o = 16; o > 0; o >>= 1) {
        sx += __shfl_down_sync(0xffffffffu, sx, o);
        sy += __shfl_down_sync(0xffffffffu, sy, o);
        sz += __shfl_down_sync(0xffffffffu, sz, o);
    }
    if ((threadIdx.x & 31) == 0) {
        atomicAdd(&g_center[0], sx);
        atomicAdd(&g_center[1], sy);
        atomicAdd(&g_center[2], sz);
    }
}

// ---------------------------------------------------------------- node encoder (SIMT fp32; exact)
__global__ void __launch_bounds__(128) k_node_enc(
    const float* __restrict__ pos, const float* __restrict__ vel,
    const int* __restrict__ rid, const float* __restrict__ remb,
    const float* __restrict__ W1, const float* __restrict__ B1,
    const float* __restrict__ W2, const float* __restrict__ B2)
{
    __shared__ float F[32][24];
    __shared__ float H[32][128];
    const int tid = threadIdx.x;
    const int nbase = blockIdx.x * 32;
    const float inv = 1.f / (float)NN;
    const float cx = g_center[0] * inv, cy = g_center[1] * inv, cz = g_center[2] * inv;

    for (int i = tid; i < 32 * 23; i += 128) {
        int n = i / 23, k = i % 23;
        int gn = nbase + n;
        float v = 0.f;
        if (gn < NN) {
            if (k < 3) v = vel[gn * 3 + k];
            else if (k < 6) v = pos[gn * 3 + (k - 3)] - ((k == 3) ? cx : (k == 4) ? cy : cz);
            else if (k == 6) v = g_deg[gn];
            else v = remb[rid[gn] * 16 + (k - 7)];
        }
        F[n][k] = v;
    }
    __syncthreads();

    const int j = tid;
#pragma unroll 1
    for (int n = 0; n < 32; n++) {
        float acc = B1[j];
#pragma unroll
        for (int k = 0; k < 23; k++) acc += F[n][k] * W1[k * 128 + j];
        H[n][j] = fmaxf(acc, 0.f);
    }
    __syncthreads();
#pragma unroll 1
    for (int n = 0; n < 32; n++) {
        int gn = nbase + n;
        float acc = B2[j];
#pragma unroll 8
        for (int k = 0; k < 128; k++) acc += H[n][k] * W2[k * 128 + j];
        if (gn < NN) g_nl[(size_t)gn * LL + j] = acc;
    }
}

// ---------------------------------------------------------------- edge encoder (wmma bf16-split)
__global__ void __launch_bounds__(256, 1) k_edge_enc(
    const float* __restrict__ pos, const float* __restrict__ vel,
    const int* __restrict__ rid,
    const int* __restrict__ snd, const int* __restrict__ rcv,
    const float* __restrict__ W1, const float* __restrict__ B1,
    const float* __restrict__ W2, const float* __restrict__ B2)
{
    extern __shared__ char smc[];
    const int LDF = 12, LDH = 132, LDHB = 136, LDWB = 136;
    float*         F   = (float*)(smc + 0);
    float*         Hf  = (float*)(smc + 3072);
    __nv_bfloat16* Hhi = (__nv_bfloat16*)(smc + 36864);
    __nv_bfloat16* Hlo = (__nv_bfloat16*)(smc + 54272);
    __nv_bfloat16* Whi = (__nv_bfloat16*)(smc + 71680);
    __nv_bfloat16* Wlo = (__nv_bfloat16*)(smc + 106496);
    const int tid = threadIdx.x;
    const int w = tid >> 5, rt = w >> 1, cg = w & 1;
    const int ebase = blockIdx.x * 64;

    if (tid < 64) {
        int e = ebase + tid;
        int s = snd[e], r = rcv[e];
        float rp0 = pos[s * 3 + 0] - pos[r * 3 + 0];
        float rp1 = pos[s * 3 + 1] - pos[r * 3 + 1];
        float rp2 = pos[s * 3 + 2] - pos[r * 3 + 2];
        float rv0 = vel[s * 3 + 0] - vel[r * 3 + 0];
        float rv1 = vel[s * 3 + 1] - vel[r * 3 + 1];
        float rv2 = vel[s * 3 + 2] - vel[r * 3 + 2];
        float sq = rp0 * rp0 + rp1 * rp1 + rp2 * rp2;
        float dist = sqrtf(sq);
        float same = (rid[s] == rid[r]) ? 1.f : 0.f;
        float* f = F + tid * LDF;
        f[0] = rp0; f[1] = rp1; f[2] = rp2;
        f[3] = rv0; f[4] = rv1; f[5] = rv2;
        f[6] = dist; f[7] = sq; f[8] = same;
    }
    for (int i = tid; i < 128 * 32; i += 256) {
        int rr = i >> 5, c4 = i & 31;
        float4 v = ((const float4*)(W2 + rr * 128))[c4];
        split_store4(v, Whi + rr * LDWB + c4 * 4, Wlo + rr * LDWB + c4 * 4);
    }
    __syncthreads();

    for (int i = tid; i < 64 * 128; i += 256) {
        int e = i >> 7, j = i & 127;
        const float* f = F + e * LDF;
        float acc = B1[j];
#pragma unroll
        for (int k = 0; k < 9; k++) acc += f[k] * W1[k * 128 + j];
        Hf[e * LDH + j] = fmaxf(acc, 0.f);
    }
    __syncthreads();
    for (int i = tid; i < 64 * 32; i += 256) {
        int row = i >> 5, c4 = i & 31;
        float4 v = ((const float4*)(Hf + row * LDH))[c4];
        split_store4(v, Hhi + row * LDHB + c4 * 4, Hlo + row * LDHB + c4 * 4);
    }
    __syncthreads();

    CF acc[4];
#pragma unroll
    for (int f = 0; f < 4; f++) wmma::fill_fragment(acc[f], 0.f);

    for (int kk = 0; kk < 128; kk += 16) {
        AF ah, al;
        wmma::load_matrix_sync(ah, Hhi + rt * 16 * LDHB + kk, LDHB);
        wmma::load_matrix_sync(al, Hlo + rt * 16 * LDHB + kk, LDHB);
#pragma unroll
        for (int f = 0; f < 4; f++) {
            BF bh, bl;
            wmma::load_matrix_sync(bh, Whi + kk * LDWB + cg * 64 + f * 16, LDWB);
            wmma::load_matrix_sync(bl, Wlo + kk * LDWB + cg * 64 + f * 16, LDWB);
            wmma::mma_sync(acc[f], ah, bh, acc[f]);
            wmma::mma_sync(acc[f], ah, bl, acc[f]);
            wmma::mma_sync(acc[f], al, bh, acc[f]);
        }
    }
    __syncthreads();
#pragma unroll
    for (int f = 0; f < 4; f++)
        wmma::store_matrix_sync(Hf + rt * 16 * LDH + cg * 64 + f * 16, acc[f], LDH, wmma::mem_row_major);
    __syncthreads();

    for (int i = tid; i < 64 * 32; i += 256) {
        int e = i >> 5, c4 = i & 31;
        float4 c2 = ((const float4*)(Hf + e * LDH))[c4];
        float4 bb = ((const float4*)B2)[c4];
        float4 nv = make_float4(c2.x + bb.x, c2.y + bb.y, c2.z + bb.z, c2.w + bb.w);
        ((float4*)(g_el + (size_t)(ebase + e) * LL))[c4] = nv;
    }
}

// ---------------------------------------------------------------- node projector (used once, step 0)
#define PJ_AHI 0
#define PJ_ALO 17408
#define PJ_WHI 34816
#define PJ_WLO 102400
#define PJ_SMEM 169984

__global__ void __launch_bounds__(256, 1) k_node_project(int step)
{
    extern __shared__ char smc[];
    __nv_bfloat16* Ahi = (__nv_bfloat16*)(smc + PJ_AHI);
    __nv_bfloat16* Alo = (__nv_bfloat16*)(smc + PJ_ALO);
    __nv_bfloat16* Whi = (__nv_bfloat16*)(smc + PJ_WHI);
    __nv_bfloat16* Wlo = (__nv_bfloat16*)(smc + PJ_WLO);
    const int tid = threadIdx.x;
    const int w = tid >> 5, rt = w >> 1, cg = w & 1;
    const int nbase = blockIdx.x * 64;
    const bool full = (nbase + 64 <= NN);
    const __nv_bfloat16* wh = g_ws + (size_t)step * STEP_W + PRJ_HI;
    const __nv_bfloat16* wl = g_ws + (size_t)step * STEP_W + PRJ_LO;

    for (int i = tid; i < 64 * 32; i += 256) {
        int row = i >> 5, c4 = i & 31;
        int n = nbase + row;
        float4 v = make_float4(0.f, 0.f, 0.f, 0.f);
        if (n < NN) v = ((const float4*)(g_nl + (size_t)n * LL))[c4];
        split_store4(v, Ahi + row * 136 + c4 * 4, Alo + row * 136 + c4 * 4);
    }
    for (int i = tid; i < 128 * 32; i += 256) {
        int rr = i >> 5, g = i & 31;
        *(float4*)(Whi + rr * 264 + g * 8) = ((const float4*)(wh + rr * 256))[g];
        *(float4*)(Wlo + rr * 264 + g * 8) = ((const float4*)(wl + rr * 256))[g];
    }
    __syncthreads();

    CF acc[8];
#pragma unroll
    for (int f = 0; f < 8; f++) wmma::fill_fragment(acc[f], 0.f);
    for (int kk = 0; kk < 128; kk += 16) {
        AF ah, al;
        wmma::load_matrix_sync(ah, Ahi + rt * 16 * 136 + kk, 136);
        wmma::load_matrix_sync(al, Alo + rt * 16 * 136 + kk, 136);
#pragma unroll
        for (int f = 0; f < 8; f++) {
            BF bh, bl;
            wmma::load_matrix_sync(bh, Whi + kk * 264 + cg * 128 + f * 16, 264);
            wmma::load_matrix_sync(bl, Wlo + kk * 264 + cg * 128 + f * 16, 264);
            wmma::mma_sync(acc[f], ah, bh, acc[f]);
            wmma::mma_sync(acc[f], ah, bl, acc[f]);
            wmma::mma_sync(acc[f], al, bh, acc[f]);
        }
    }

    if (full) {
#pragma unroll
        for (int f = 0; f < 8; f++)
            wmma::store_matrix_sync(g_z + (size_t)(nbase + rt * 16) * 256 + cg * 128 + f * 16,
                                    acc[f], 256, wmma::mem_row_major);
    } else {
        float* Csm = (float*)(smc + PJ_WHI);
        __syncthreads();
#pragma unroll
        for (int f = 0; f < 8; f++)
            wmma::store_matrix_sync(Csm + rt * 16 * 260 + cg * 128 + f * 16, acc[f], 260, wmma::mem_row_major);
        __syncthreads();
        for (int i = tid; i < 64 * 64; i += 256) {
            int row = i >> 6, g = i & 63;
            int n = nbase + row;
            if (n < NN)
                ((float4*)(g_z + (size_t)n * 256))[g] = *(float4*)(Csm + row * 260 + g * 4);
        }
    }
}

// ---------------------------------------------------------------- edge processor step
// 64 edges/block, 256 threads, 8 warps (4 row x 2 col), 2 blocks/SM.
// Cf (fp32 GEMM output) aliases the W region.
#define ES_SSH 0
#define ES_RSH 256
#define ES_B1  512
#define ES_B2  1024
#define ES_AHI 1536
#define ES_ALO 18944
#define ES_W   36352
#define ES_WLO 71168
#define ES_SMEM 105984

__global__ void __launch_bounds__(256, 2) k_edge_step(
    const int* __restrict__ snd, const int* __restrict__ rcv, int step,
    const float* __restrict__ B1, const float* __restrict__ B2)
{
    extern __shared__ char smc[];
    int*   ssh = (int*)(smc + ES_SSH);
    int*   rsh = (int*)(smc + ES_RSH);
    float* B1s = (float*)(smc + ES_B1);
    float* B2s = (float*)(smc + ES_B2);
    __nv_bfloat16* Ahi = (__nv_bfloat16*)(smc + ES_AHI);   // 64 x 136
    __nv_bfloat16* Alo = (__nv_bfloat16*)(smc + ES_ALO);
    __nv_bfloat16* Whi = (__nv_bfloat16*)(smc + ES_W);     // 128 x 136
    __nv_bfloat16* Wlo = (__nv_bfloat16*)(smc + ES_WLO);
    float*         Cf  = (float*)(smc + ES_W);             // 64 x 132 (aliases W)
    const int tid = threadIdx.x;
    const int w = tid >> 5, rt = w >> 1, cg = w & 1;
    const int ebase = blockIdx.x * 64;
    const __nv_bfloat16* wbase = g_ws + (size_t)step * STEP_W;

    if (tid < 64) {
        ssh[tid] = snd[ebase + tid];
        rsh[tid] = rcv[ebase + tid];
    }
    if (tid < 128) {
        B1s[tid] = B1[tid];
        B2s[tid] = B2[tid];
    }
    // gather el rows + split
    for (int i = tid; i < 2048; i += 256) {
        int row = i >> 5, c4 = i & 31;
        float4 v = ((const float4*)(g_el + (size_t)(ebase + row) * LL))[c4];
        split_store4(v, Ahi + row * 136 + c4 * 4, Alo + row * 136 + c4 * 4);
    }
    // stage W1a
    for (int i = tid; i < 2048; i += 256) {
        int rr = i >> 4, g = i & 15;
        *(float4*)(Whi + rr * 136 + g * 8) = ((const float4*)(wbase + EW1A_HI + rr * 128))[g];
        *(float4*)(Wlo + rr * 136 + g * 8) = ((const float4*)(wbase + EW1A_LO + rr * 128))[g];
    }
    __syncthreads();

    CF acc[4];
#pragma unroll
    for (int f = 0; f < 4; f++) wmma::fill_fragment(acc[f], 0.f);
    for (int kk = 0; kk < 128; kk += 16) {
        AF ah, al;
        wmma::load_matrix_sync(ah, Ahi + rt * 16 * 136 + kk, 136);
        wmma::load_matrix_sync(al, Alo + rt * 16 * 136 + kk, 136);
#pragma unroll
        for (int f = 0; f < 4; f++) {
            BF bh, bl;
            wmma::load_matrix_sync(bh, Whi + kk * 136 + cg * 64 + f * 16, 136);
            wmma::load_matrix_sync(bl, Wlo + kk * 136 + cg * 64 + f * 16, 136);
            wmma::mma_sync(acc[f], ah, bh, acc[f]);
            wmma::mma_sync(acc[f], ah, bl, acc[f]);
            wmma::mma_sync(acc[f], al, bh, acc[f]);
        }
    }
    __syncthreads();
#pragma unroll
    for (int f = 0; f < 4; f++)
        wmma::store_matrix_sync(Cf + rt * 16 * 132 + cg * 64 + f * 16, acc[f], 132, wmma::mem_row_major);
    __syncthreads();

    // epilogue 1: C1 + Z[s] + Z[r] + B1, relu -> A planes
    for (int i = tid; i < 2048; i += 256) {
        int row = i >> 5, c4 = i & 31;
        int s = ssh[row], r = rsh[row];
        float4 c = *(float4*)(Cf + row * 132 + c4 * 4);
        float4 zb = ((const float4*)(g_z + (size_t)s * 256))[c4];
        float4 zc = ((const float4*)(g_z + (size_t)r * 256 + 128))[c4];
        float4 b = ((const float4*)B1s)[c4];
        float4 v = make_float4(
            fmaxf(c.x + zb.x + zc.x + b.x, 0.f),
            fmaxf(c.y + zb.y + zc.y + b.y, 0.f),
            fmaxf(c.z + zb.z + zc.z + b.z, 0.f),
            fmaxf(c.w + zb.w + zc.w + b.w, 0.f));
        split_store4(v, Ahi + row * 136 + c4 * 4, Alo + row * 136 + c4 * 4);
    }
    __syncthreads();
    // stage W2 (overwrites Cf region)
    for (int i = tid; i < 2048; i += 256) {
        int rr = i >> 4, g = i & 15;
        *(float4*)(Whi + rr * 136 + g * 8) = ((const float4*)(wbase + EW2_HI + rr * 128))[g];
        *(float4*)(Wlo + rr * 136 + g * 8) = ((const float4*)(wbase + EW2_LO + rr * 128))[g];
    }
    __syncthreads();

#pragma unroll
    for (int f = 0; f < 4; f++) wmma::fill_fragment(acc[f], 0.f);
    for (int kk = 0; kk < 128; kk += 16) {
        AF ah, al;
        wmma::load_matrix_sync(ah, Ahi + rt * 16 * 136 + kk, 136);
        wmma::load_matrix_sync(al, Alo + rt * 16 * 136 + kk, 136);
#pragma unroll
        for (int f = 0; f < 4; f++) {
            BF bh, bl;
            wmma::load_matrix_sync(bh, Whi + kk * 136 + cg * 64 + f * 16, 136);
            wmma::load_matrix_sync(bl, Wlo + kk * 136 + cg * 64 + f * 16, 136);
            wmma::mma_sync(acc[f], ah, bh, acc[f]);
            wmma::mma_sync(acc[f], ah, bl, acc[f]);
            wmma::mma_sync(acc[f], al, bh, acc[f]);
        }
    }
    __syncthreads();
#pragma unroll
    for (int f = 0; f < 4; f++)
        wmma::store_matrix_sync(Cf + rt * 16 * 132 + cg * 64 + f * 16, acc[f], 132, wmma::mem_row_major);
    __syncthreads();

    // epilogue 2: el += C2 + b2; scatter-add into agg
    for (int i = tid; i < 2048; i += 256) {
        int row = i >> 5, c4 = i & 31;
        size_t go = (size_t)(ebase + row) * LL;
        float4 oldv = ((const float4*)(g_el + go))[c4];
        float4 c = *(float4*)(Cf + row * 132 + c4 * 4);
        float4 b = ((const float4*)B2s)[c4];
        float4 nv = make_float4(oldv.x + c.x + b.x, oldv.y + c.y + b.y,
                                oldv.z + c.z + b.z, oldv.w + c.w + b.w);
        ((float4*)(g_el + go))[c4] = nv;
        red_add_v4(g_agg + (size_t)rsh[row] * LL + c4 * 4, nv);
    }
}

// ---------------------------------------------------------------- node step (+fused projection for st+1)
// 64 nodes/block, 256 threads, 2 blocks/SM.
// smem: X planes @0 (64x264 bf16 x2 = 67584); W @68608 (64x136 bf16 x2 = 34816). Total 103424.
// Aliases after GEMM1: Cf fp32 @0 (64x132), H planes @33792/@51200 (64x136 bf16).
#define NS_XHI 0
#define NS_XLO 33792
#define NS_CF  0
#define NS_HHI 33792
#define NS_HLO 51200
#define NS_W   68608
#define NS_WLO 86016
#define NS_SMEM 103424

__global__ void __launch_bounds__(256, 2) k_node_step(
    int step, const float* __restrict__ B1, const float* __restrict__ B2, int do_proj)
{
    extern __shared__ char smc[];
    __nv_bfloat16* Xhi = (__nv_bfloat16*)(smc + NS_XHI);   // 64 x 264
    __nv_bfloat16* Xlo = (__nv_bfloat16*)(smc + NS_XLO);
    __nv_bfloat16* Whi = (__nv_bfloat16*)(smc + NS_W);     // 64 x 136 (K-chunk)
    __nv_bfloat16* Wlo = (__nv_bfloat16*)(smc + NS_WLO);
    float*         Cf  = (float*)(smc + NS_CF);            // 64 x 132
    __nv_bfloat16* Hhi = (__nv_bfloat16*)(smc + NS_HHI);   // 64 x 136
    __nv_bfloat16* Hlo = (__nv_bfloat16*)(smc + NS_HLO);
    const int tid = threadIdx.x;
    const int w = tid >> 5, rt = w >> 1, cg = w & 1;
    const int nbase = blockIdx.x * 64;
    const bool full = (nbase + 64 <= NN);
    const __nv_bfloat16* wbase = g_ws + (size_t)step * STEP_W;

    // X = [nl | agg]; zero agg as consumed
    for (int i = tid; i < 64 * 64; i += 256) {
        int row = i >> 6, c4 = i & 63;
        int n = nbase + row;
        float4 v = make_float4(0.f, 0.f, 0.f, 0.f);
        if (n < NN) {
            if (c4 < 32) {
                v = ((const float4*)(g_nl + (size_t)n * LL))[c4];
            } else {
                float4* ap = (float4*)(g_agg + (size_t)n * LL) + (c4 - 32);
                v = *ap;
                *ap = make_float4(0.f, 0.f, 0.f, 0.f);
            }
        }
        split_store4(v, Xhi + row * 264 + c4 * 4, Xlo + row * 264 + c4 * 4);
    }

    CF acc[4];
#pragma unroll
    for (int f = 0; f < 4; f++) wmma::fill_fragment(acc[f], 0.f);

    // GEMM1: X[64x256] @ NW1
    for (int kc = 0; kc < 256; kc += 64) {
        __syncthreads();
        for (int i = tid; i < 1024; i += 256) {
            int rr = i >> 4, g = i & 15;
            *(float4*)(Whi + rr * 136 + g * 8) = ((const float4*)(wbase + NW1_HI + (kc + rr) * 128))[g];
            *(float4*)(Wlo + rr * 136 + g * 8) = ((const float4*)(wbase + NW1_LO + (kc + rr) * 128))[g];
        }
        __syncthreads();
        for (int kk = 0; kk < 64; kk += 16) {
            AF ah, al;
            wmma::load_matrix_sync(ah, Xhi + rt * 16 * 264 + kc + kk, 264);
            wmma::load_matrix_sync(al, Xlo + rt * 16 * 264 + kc + kk, 264);
#pragma unroll
            for (int f = 0; f < 4; f++) {
                BF bh, bl;
                wmma::load_matrix_sync(bh, Whi + kk * 136 + cg * 64 + f * 16, 136);
                wmma::load_matrix_sync(bl, Wlo + kk * 136 + cg * 64 + f * 16, 136);
                wmma::mma_sync(acc[f], ah, bh, acc[f]);
                wmma::mma_sync(acc[f], ah, bl, acc[f]);
                wmma::mma_sync(acc[f], al, bh, acc[f]);
            }
        }
    }
    __syncthreads();
#pragma unroll
    for (int f = 0; f < 4; f++)
        wmma::store_matrix_sync(Cf + rt * 16 * 132 + cg * 64 + f * 16, acc[f], 132, wmma::mem_row_major);
    __syncthreads();
    // bias + relu -> H planes
    for (int i = tid; i < 64 * 32; i += 256) {
        int row = i >> 5, c4 = i & 31;
        float4 v = *(float4*)(Cf + row * 132 + c4 * 4);
        float4 bb = ((const float4*)B1)[c4];
        v.x = fmaxf(v.x + bb.x, 0.f);
        v.y = fmaxf(v.y + bb.y, 0.f);
        v.z = fmaxf(v.z + bb.z, 0.f);
        v.w = fmaxf(v.w + bb.w, 0.f);
        split_store4(v, Hhi + row * 136 + c4 * 4, Hlo + row * 136 + c4 * 4);
    }

    // GEMM2: H[64x128] @ NW2
#pragma unroll
    for (int f = 0; f < 4; f++) wmma::fill_fragment(acc[f], 0.f);
    for (int kc = 0; kc < 128; kc += 64) {
        __syncthreads();
        for (int i = tid; i < 1024; i += 256) {
            int rr = i >> 4, g = i & 15;
            *(float4*)(Whi + rr * 136 + g * 8) = ((const float4*)(wbase + NW2_HI + (kc + rr) * 128))[g];
            *(float4*)(Wlo + rr * 136 + g * 8) = ((const float4*)(wbase + NW2_LO + (kc + rr) * 128))[g];
        }
        __syncthreads();
        for (int kk = 0; kk < 64; kk += 16) {
            AF ah, al;
            wmma::load_matrix_sync(ah, Hhi + rt * 16 * 136 + kc + kk, 136);
            wmma::load_matrix_sync(al, Hlo + rt * 16 * 136 + kc + kk, 136);
#pragma unroll
            for (int f = 0; f < 4; f++) {
                BF bh, bl;
                wmma::load_matrix_sync(bh, Whi + kk * 136 + cg * 64 + f * 16, 136);
                wmma::load_matrix_sync(bl, Wlo + kk * 136 + cg * 64 + f * 16, 136);
                wmma::mma_sync(acc[f], ah, bh, acc[f]);
                wmma::mma_sync(acc[f], ah, bl, acc[f]);
                wmma::mma_sync(acc[f], al, bh, acc[f]);
            }
        }
    }
    __syncthreads();
#pragma unroll
    for (int f = 0; f < 4; f++)
        wmma::store_matrix_sync(Cf + rt * 16 * 132 + cg * 64 + f * 16, acc[f], 132, wmma::mem_row_major);
    __syncthreads();

    // epilogue: nl += C2 + b2; write back; split new nl -> H planes for projection
    for (int i = tid; i < 64 * 32; i += 256) {
        int row = i >> 5, c4 = i & 31;
        int n = nbase + row;
        float4 nv = make_float4(0.f, 0.f, 0.f, 0.f);
        if (n < NN) {
            float4 oldv = ((const float4*)(g_nl + (size_t)n * LL))[c4];
            float4 c2 = *(float4*)(Cf + row * 132 + c4 * 4);
            float4 bb = ((const float4*)B2)[c4];
            nv = make_float4(oldv.x + c2.x + bb.x, oldv.y + c2.y + bb.y,
                             oldv.z + c2.z + bb.z, oldv.w + c2.w + bb.w);
            ((float4*)(g_nl + (size_t)n * LL))[c4] = nv;
        }
        if (do_proj)
            split_store4(nv, Hhi + row * 136 + c4 * 4, Hlo + row * 136 + c4 * 4);
    }

    // fused projection: Z(step+1) = nl_new @ PRJ(step+1), two 128-N halves
    if (do_proj) {
        const __nv_bfloat16* wn = g_ws + (size_t)(step + 1) * STEP_W;
#pragma unroll 1
        for (int half = 0; half < 2; ++half) {
#pragma unroll
            for (int f = 0; f < 4; f++) wmma::fill_fragment(acc[f], 0.f);
            for (int kc = 0; kc < 128; kc += 64) {
                __syncthreads();
                for (int i = tid; i < 1024; i += 256) {
                    int rr = i >> 4, g = i & 15;
                    *(float4*)(Whi + rr * 136 + g * 8) =
                        ((const float4*)(wn + PRJ_HI + (size_t)(kc + rr) * 256 + half * 128))[g];
                    *(float4*)(Wlo + rr * 136 + g * 8) =
                        ((const float4*)(wn + PRJ_LO + (size_t)(kc + rr) * 256 + half * 128))[g];
                }
                __syncthreads();
                for (int kk = 0; kk < 64; kk += 16) {
                    AF ah, al;
                    wmma::load_matrix_sync(ah, Hhi + rt * 16 * 136 + kc + kk, 136);
                    wmma::load_matrix_sync(al, Hlo + rt * 16 * 136 + kc + kk, 136);
#pragma unroll
                    for (int f = 0; f < 4; f++) {
                        BF bh, bl;
                        wmma::load_matrix_sync(bh, Whi + kk * 136 + cg * 64 + f * 16, 136);
                        wmma::load_matrix_sync(bl, Wlo + kk * 136 + cg * 64 + f * 16, 136);
                        wmma::mma_sync(acc[f], ah, bh, acc[f]);
                        wmma::mma_sync(acc[f], ah, bl, acc[f]);
                        wmma::mma_sync(acc[f], al, bh, acc[f]);
                    }
                }
            }
            if (full) {
#pragma unroll
                for (int f = 0; f < 4; f++)
                    wmma::store_matrix_sync(g_z + (size_t)(nbase + rt * 16) * 256 + half * 128 + cg * 64 + f * 16,
                                            acc[f], 256, wmma::mem_row_major);
            } else {
                __syncthreads();
#pragma unroll
                for (int f = 0; f < 4; f++)
                    wmma::store_matrix_sync(Cf + rt * 16 * 132 + cg * 64 + f * 16, acc[f], 132, wmma::mem_row_major);
                __syncthreads();
                for (int i = tid; i < 64 * 32; i += 256) {
                    int row = i >> 5, c4 = i & 31;
                    int n = nbase + row;
                    if (n < NN)
                        ((float4*)(g_z + (size_t)n * 256 + half * 128))[c4] =
                            *(float4*)(Cf + row * 132 + c4 * 4);
                }
            }
        }
    }
}

// ---------------------------------------------------------------- decoder (SIMT fp32; exact)
__global__ void __launch_bounds__(128) k_decoder(
    const float* __restrict__ W1, const float* __restrict__ B1,
    const float* __restrict__ W2, const float* __restrict__ B2,
    float* __restrict__ out)
{
    __shared__ float Xs[32][128];
    __shared__ float H[32][128];
    const int tid = threadIdx.x;
    const int nbase = blockIdx.x * 32;

    for (int i = tid; i < 32 * 32; i += 128) {
        int n = i >> 5, c4 = i & 31;
        int gn = nbase + n;
        float4 v = make_float4(0.f, 0.f, 0.f, 0.f);
        if (gn < NN) v = ((const float4*)(g_nl + (size_t)gn * LL))[c4];
        ((float4*)Xs[n])[c4] = v;
    }
    __syncthreads();

    const int j = tid;
#pragma unroll 1
    for (int n = 0; n < 32; n++) {
        float acc = B1[j];
#pragma unroll 8
        for (int k = 0; k < 128; k++) acc += Xs[n][k] * W1[k * 128 + j];
        H[n][j] = fmaxf(acc, 0.f);
    }
    __syncthreads();

    if (tid < 96) {
        int n = tid / 3, d = tid % 3;
        int gn = nbase + n;
        float acc = B2[d];
#pragma unroll 8
        for (int k = 0; k < 128; k++) acc += H[n][k] * W2[k * 3 + d];
        if (gn < NN) out[gn * 3 + d] = acc;
    }
}

// ---------------------------------------------------------------- launch
extern "C" void kernel_launch(void* const* d_in, const int* in_sizes, int n_in,
                              void* d_out, int out_size)
{
    const float* pos   = (const float*)d_in[0];
    const float* vel   = (const float*)d_in[1];
    const int*   rid   = (const int*)d_in[2];
    const int*   snd   = (const int*)d_in[3];
    const int*   rcv   = (const int*)d_in[4];
    const float* remb  = (const float*)d_in[5];
    const float* ne_w1 = (const float*)d_in[6];
    const float* ne_b1 = (const float*)d_in[7];
    const float* ne_w2 = (const float*)d_in[8];
    const float* ne_b2 = (const float*)d_in[9];
    const float* ee_w1 = (const float*)d_in[10];
    const float* ee_b1 = (const float*)d_in[11];
    const float* ee_w2 = (const float*)d_in[12];
    const float* ee_b2 = (const float*)d_in[13];
    const float* pe_w1 = (const float*)d_in[14];
    const float* pe_b1 = (const float*)d_in[15];
    const float* pe_w2 = (const float*)d_in[16];
    const float* pe_b2 = (const float*)d_in[17];
    const float* pn_w1 = (const float*)d_in[18];
    const float* pn_b1 = (const float*)d_in[19];
    const float* pn_w2 = (const float*)d_in[20];
    const float* pn_b2 = (const float*)d_in[21];
    const float* de_w1 = (const float*)d_in[22];
    const float* de_b1 = (const float*)d_in[23];
    const float* de_w2 = (const float*)d_in[24];
    const float* de_b2 = (const float*)d_in[25];

    const int SMEM_EE = 141312;

    cudaFuncSetAttribute(k_edge_step, cudaFuncAttributeMaxDynamicSharedMemorySize, ES_SMEM);
    cudaFuncSetAttribute(k_node_step, cudaFuncAttributeMaxDynamicSharedMemorySize, NS_SMEM);
    cudaFuncSetAttribute(k_edge_enc, cudaFuncAttributeMaxDynamicSharedMemorySize, SMEM_EE);
    cudaFuncSetAttribute(k_node_project, cudaFuncAttributeMaxDynamicSharedMemorySize, PJ_SMEM);

    k_prep_w<<<(NSTEPS * 114688 + 255) / 256, 256>>>(pe_w1, pe_w2, pn_w1, pn_w2);
    k_init<<<(NN + 255) / 256, 256>>>();
    k_deg<<<(EE + 255) / 256, 256>>>(rcv);
    k_center<<<104, 256>>>(pos);
    k_node_enc<<<(NN + 31) / 32, 128>>>(pos, vel, rid, remb, ne_w1, ne_b1, ne_w2, ne_b2);
    k_edge_enc<<<EE / 64, 256, SMEM_EE>>>(pos, vel, rid, snd, rcv, ee_w1, ee_b1, ee_w2, ee_b2);
    k_node_project<<<(NN + 63) / 64, 256, PJ_SMEM>>>(0);

    for (int st = 0; st < NSTEPS; st++) {
        k_edge_step<<<EE / 64, 256, ES_SMEM>>>(
            snd, rcv, st, pe_b1 + (size_t)st * 128, pe_b2 + (size_t)st * 128);
        k_node_step<<<(NN + 63) / 64, 256, NS_SMEM>>>(
            st, pn_b1 + (size_t)st * 128, pn_b2 + (size_t)st * 128, (st < NSTEPS - 1) ? 1 : 0);
    }

    k_decoder<<<(NN + 31) / 32, 128>>>(de_w1, de_b1, de_w2, de_b2, (float*)d_out);
}

// round 7
// speedup vs baseline: 1.9192x; 1.1234x over previous
#include <cuda_runtime.h>
#include <cuda_bf16.h>
#include <mma.h>
#include <cstdint>

using namespace nvcuda;

#define NN 50000
#define EE 800000
#define LL 128
#define NSTEPS 10
#define NB_ENC 782          // ceil(NN/64)
#define EB_ENC 12500        // EE/64

// ---- scratch (device globals; no allocations allowed) ----
__device__ float g_nl[(size_t)NN * LL];
__device__ float g_el[(size_t)EE * LL];
__device__ float g_agg[(size_t)NN * LL];
__device__ float g_z[(size_t)NN * 256];
__device__ float g_deg[NN];
__device__ float g_center[3];

#define EW1A_HI 0
#define EW1A_LO 16384
#define EW2_HI  32768
#define EW2_LO  49152
#define PRJ_HI  65536
#define PRJ_LO  98304
#define NW1_HI  131072
#define NW1_LO  163840
#define NW2_HI  196608
#define NW2_LO  212992
#define STEP_W  229376
__device__ __nv_bfloat16 g_ws[(size_t)NSTEPS * STEP_W];

typedef wmma::fragment<wmma::matrix_a, 16, 16, 16, __nv_bfloat16, wmma::row_major> AF;
typedef wmma::fragment<wmma::matrix_b, 16, 16, 16, __nv_bfloat16, wmma::row_major> BF;
typedef wmma::fragment<wmma::accumulator, 16, 16, 16, float> CF;

__device__ __forceinline__ uint32_t smem_u32(const void* p) {
    uint32_t a;
    asm("{ .reg .u64 t; cvta.to.shared.u64 t, %1; cvt.u32.u64 %0, t; }" : "=r"(a) : "l"(p));
    return a;
}
__device__ __forceinline__ void cp_async16(uint32_t dst, const void* src) {
    asm volatile("cp.async.ca.shared.global [%0], [%1], 16;" :: "r"(dst), "l"(src) : "memory");
}
__device__ __forceinline__ void cp_commit_wait() {
    asm volatile("cp.async.commit_group;" ::: "memory");
    asm volatile("cp.async.wait_group 0;" ::: "memory");
}

__device__ __forceinline__ void split_store4(float4 v, __nv_bfloat16* hip, __nv_bfloat16* lop) {
    __nv_bfloat162 h0 = __floats2bfloat162_rn(v.x, v.y);
    __nv_bfloat162 h1 = __floats2bfloat162_rn(v.z, v.w);
    float2 f0 = __bfloat1622float2(h0);
    float2 f1 = __bfloat1622float2(h1);
    __nv_bfloat162 l0 = __floats2bfloat162_rn(v.x - f0.x, v.y - f0.y);
    __nv_bfloat162 l1 = __floats2bfloat162_rn(v.z - f1.x, v.w - f1.y);
    *(__nv_bfloat162*)(hip)     = h0;
    *(__nv_bfloat162*)(hip + 2) = h1;
    *(__nv_bfloat162*)(lop)     = l0;
    *(__nv_bfloat162*)(lop + 2) = l1;
}

__device__ __forceinline__ void red_add_v4(float* dst, float4 v) {
    asm volatile("red.global.add.v4.f32 [%0], {%1,%2,%3,%4};"
                 :: "l"(dst), "f"(v.x), "f"(v.y), "f"(v.z), "f"(v.w) : "memory");
}

// ---------------------------------------------------------------- launch 0: weight prep + init
__global__ void __launch_bounds__(256) k_setup(
    const float* __restrict__ pe_w1, const float* __restrict__ pe_w2,
    const float* __restrict__ pn_w1, const float* __restrict__ pn_w2)
{
    if (blockIdx.x < 4480) {
        int idx = blockIdx.x * 256 + threadIdx.x;
        int s = idx / 114688;
        int e = idx % 114688;
        float v;
        size_t dhi, dlo;
        if (e < 16384) {
            v = pe_w1[(size_t)s * 384 * 128 + e];
            dhi = EW1A_HI + e; dlo = EW1A_LO + e;
        } else if (e < 32768) {
            int e2 = e - 16384;
            v = pe_w2[(size_t)s * 128 * 128 + e2];
            dhi = EW2_HI + e2; dlo = EW2_LO + e2;
        } else if (e < 65536) {
            int e2 = e - 32768;
            int k = e2 >> 8, n = e2 & 255;
            int srcrow = 128 + (n >> 7) * 128 + k;
            v = pe_w1[(size_t)s * 384 * 128 + (size_t)srcrow * 128 + (n & 127)];
            dhi = PRJ_HI + e2; dlo = PRJ_LO + e2;
        } else if (e < 98304) {
            int e2 = e - 65536;
            v = pn_w1[(size_t)s * 256 * 128 + e2];
            dhi = NW1_HI + e2; dlo = NW1_LO + e2;
        } else {
            int e2 = e - 98304;
            v = pn_w2[(size_t)s * 128 * 128 + e2];
            dhi = NW2_HI + e2; dlo = NW2_LO + e2;
        }
        __nv_bfloat16 h = __float2bfloat16(v);
        g_ws[(size_t)s * STEP_W + dhi] = h;
        g_ws[(size_t)s * STEP_W + dlo] = __float2bfloat16(v - __bfloat162float(h));
    } else {
        int i = (blockIdx.x - 4480) * 256 + threadIdx.x;
        if (i < NN) g_deg[i] = 0.f;
        if (i < 3) g_center[i] = 0.f;
    }
}

// ---------------------------------------------------------------- launch 1: degree + center
__global__ void __launch_bounds__(256) k_degcenter(
    const int* __restrict__ rcv, const float* __restrict__ pos)
{
    if (blockIdx.x < 3125) {
        int i = blockIdx.x * 256 + threadIdx.x;
        if (i < EE) atomicAdd(&g_deg[rcv[i]], 1.f);
    } else {
        float sx = 0.f, sy = 0.f, sz = 0.f;
        for (int i = (blockIdx.x - 3125) * 256 + threadIdx.x; i < NN; i += 104 * 256) {
            sx += pos[i * 3 + 0];
            sy += pos[i * 3 + 1];
            sz += pos[i * 3 + 2];
        }
#pragma unroll
        for (int o = 16; o > 0; o >>= 1) {
            sx += __shfl_down_sync(0xffffffffu, sx, o);
            sy += __shfl_down_sync(0xffffffffu, sy, o);
            sz += __shfl_down_sync(0xffffffffu, sz, o);
        }
        if ((threadIdx.x & 31) == 0) {
            atomicAdd(&g_center[0], sx);
            atomicAdd(&g_center[1], sy);
            atomicAdd(&g_center[2], sz);
        }
    }
}

// ---------------------------------------------------------------- launch 2: all encoders
#define ENC_SMEM 141312

__global__ void __launch_bounds__(256, 1) k_enc_all(
    const float* __restrict__ pos, const float* __restrict__ vel,
    const int* __restrict__ rid, const float* __restrict__ remb,
    const int* __restrict__ snd, const int* __restrict__ rcv,
    const float* __restrict__ nW1, const float* __restrict__ nB1,
    const float* __restrict__ nW2, const float* __restrict__ nB2,
    const float* __restrict__ eW1, const float* __restrict__ eB1,
    const float* __restrict__ eW2, const float* __restrict__ eB2)
{
    extern __shared__ char smc[];
    const int tid = threadIdx.x;

    if (blockIdx.x < NB_ENC) {
        // ===== node encoder (64 nodes) + projection step 0 =====
        float* F = (float*)(smc + 0);                     // 64 x 24
        float* H = (float*)(smc + 8192);                  // 64 x 128
        __nv_bfloat16* Ahi = (__nv_bfloat16*)(smc + 40960);   // 64 x 136
        __nv_bfloat16* Alo = (__nv_bfloat16*)(smc + 58368);
        __nv_bfloat16* Wch = (__nv_bfloat16*)(smc + 75776);   // 64 x 136
        __nv_bfloat16* Wcl = (__nv_bfloat16*)(smc + 93184);
        const int nbase = blockIdx.x * 64;
        const float inv = 1.f / (float)NN;
        const float cx = g_center[0] * inv, cy = g_center[1] * inv, cz = g_center[2] * inv;

        for (int i = tid; i < 64 * 23; i += 256) {
            int n = i / 23, k = i % 23;
            int gn = nbase + n;
            float v = 0.f;
            if (gn < NN) {
                if (k < 3) v = vel[gn * 3 + k];
                else if (k < 6) v = pos[gn * 3 + (k - 3)] - ((k == 3) ? cx : (k == 4) ? cy : cz);
                else if (k == 6) v = g_deg[gn];
                else v = remb[rid[gn] * 16 + (k - 7)];
            }
            F[n * 24 + k] = v;
        }
        __syncthreads();

        const int j = tid & 127;
        for (int n = tid >> 7; n < 64; n += 2) {
            float acc = nB1[j];
#pragma unroll
            for (int k = 0; k < 23; k++) acc += F[n * 24 + k] * nW1[k * 128 + j];
            H[n * 128 + j] = fmaxf(acc, 0.f);
        }
        __syncthreads();
        for (int n = tid >> 7; n < 64; n += 2) {
            int gn = nbase + n;
            float acc = nB2[j];
#pragma unroll 8
            for (int k = 0; k < 128; k++) acc += H[n * 128 + k] * nW2[k * 128 + j];
            float v = (gn < NN) ? acc : 0.f;
            if (gn < NN) g_nl[(size_t)gn * LL + j] = v;
            __nv_bfloat16 h = __float2bfloat16(v);
            Ahi[n * 136 + j] = h;
            Alo[n * 136 + j] = __float2bfloat16(v - __bfloat162float(h));
        }
        __syncthreads();

        // projection Z(0) = nl @ PRJ(0)
        const int w = tid >> 5, rt = w >> 1, cg = w & 1;
        const bool full = (nbase + 64 <= NN);
        const __nv_bfloat16* wn = g_ws;   // step 0
        CF acc[4];
#pragma unroll 1
        for (int half = 0; half < 2; ++half) {
#pragma unroll
            for (int f = 0; f < 4; f++) wmma::fill_fragment(acc[f], 0.f);
            for (int kc = 0; kc < 128; kc += 64) {
                __syncthreads();
                for (int i = tid; i < 1024; i += 256) {
                    int rr = i >> 4, g = i & 15;
                    *(float4*)(Wch + rr * 136 + g * 8) =
                        ((const float4*)(wn + PRJ_HI + (size_t)(kc + rr) * 256 + half * 128))[g];
                    *(float4*)(Wcl + rr * 136 + g * 8) =
                        ((const float4*)(wn + PRJ_LO + (size_t)(kc + rr) * 256 + half * 128))[g];
                }
                __syncthreads();
                for (int kk = 0; kk < 64; kk += 16) {
                    AF ah, al;
                    wmma::load_matrix_sync(ah, Ahi + rt * 16 * 136 + kc + kk, 136);
                    wmma::load_matrix_sync(al, Alo + rt * 16 * 136 + kc + kk, 136);
#pragma unroll
                    for (int f = 0; f < 4; f++) {
                        BF bh, bl;
                        wmma::load_matrix_sync(bh, Wch + kk * 136 + cg * 64 + f * 16, 136);
                        wmma::load_matrix_sync(bl, Wcl + kk * 136 + cg * 64 + f * 16, 136);
                        wmma::mma_sync(acc[f], ah, bh, acc[f]);
                        wmma::mma_sync(acc[f], ah, bl, acc[f]);
                        wmma::mma_sync(acc[f], al, bh, acc[f]);
                    }
                }
            }
            if (full) {
#pragma unroll
                for (int f = 0; f < 4; f++)
                    wmma::store_matrix_sync(g_z + (size_t)(nbase + rt * 16) * 256 + half * 128 + cg * 64 + f * 16,
                                            acc[f], 256, wmma::mem_row_major);
            } else {
                // FIX (R6 bug): spill into the DEAD W-staging region (75776), NOT smc+8192
                // (which overlapped Ahi and corrupted half=1's A reads).
                float* Cf = (float*)(smc + 75776);   // 64 x 132 fp32; W restaged next half
                __syncthreads();
#pragma unroll
                for (int f = 0; f < 4; f++)
                    wmma::store_matrix_sync(Cf + rt * 16 * 132 + cg * 64 + f * 16, acc[f], 132, wmma::mem_row_major);
                __syncthreads();
                for (int i = tid; i < 64 * 32; i += 256) {
                    int row = i >> 5, c4 = i & 31;
                    int n = nbase + row;
                    if (n < NN)
                        ((float4*)(g_z + (size_t)n * 256 + half * 128))[c4] =
                            *(float4*)(Cf + row * 132 + c4 * 4);
                }
            }
        }
        return;
    }

    // ===== edge encoder =====
    {
        const int LDF = 12, LDH = 132, LDHB = 136, LDWB = 136;
        float*         F   = (float*)(smc + 0);
        float*         Hf  = (float*)(smc + 3072);
        __nv_bfloat16* Hhi = (__nv_bfloat16*)(smc + 36864);
        __nv_bfloat16* Hlo = (__nv_bfloat16*)(smc + 54272);
        __nv_bfloat16* Whi = (__nv_bfloat16*)(smc + 71680);
        __nv_bfloat16* Wlo = (__nv_bfloat16*)(smc + 106496);
        const int w = tid >> 5, rt = w >> 1, cg = w & 1;
        const int ebase = (blockIdx.x - NB_ENC) * 64;

        if (tid < 64) {
            int e = ebase + tid;
            int s = snd[e], r = rcv[e];
            float rp0 = pos[s * 3 + 0] - pos[r * 3 + 0];
            float rp1 = pos[s * 3 + 1] - pos[r * 3 + 1];
            float rp2 = pos[s * 3 + 2] - pos[r * 3 + 2];
            float rv0 = vel[s * 3 + 0] - vel[r * 3 + 0];
            float rv1 = vel[s * 3 + 1] - vel[r * 3 + 1];
            float rv2 = vel[s * 3 + 2] - vel[r * 3 + 2];
            float sq = rp0 * rp0 + rp1 * rp1 + rp2 * rp2;
            float dist = sqrtf(sq);
            float same = (rid[s] == rid[r]) ? 1.f : 0.f;
            float* f = F + tid * LDF;
            f[0] = rp0; f[1] = rp1; f[2] = rp2;
            f[3] = rv0; f[4] = rv1; f[5] = rv2;
            f[6] = dist; f[7] = sq; f[8] = same;
        }
        for (int i = tid; i < 128 * 32; i += 256) {
            int rr = i >> 5, c4 = i & 31;
            float4 v = ((const float4*)(eW2 + rr * 128))[c4];
            split_store4(v, Whi + rr * LDWB + c4 * 4, Wlo + rr * LDWB + c4 * 4);
        }
        __syncthreads();

        for (int i = tid; i < 64 * 128; i += 256) {
            int e = i >> 7, jj = i & 127;
            const float* f = F + e * LDF;
            float acc = eB1[jj];
#pragma unroll
            for (int k = 0; k < 9; k++) acc += f[k] * eW1[k * 128 + jj];
            Hf[e * LDH + jj] = fmaxf(acc, 0.f);
        }
        __syncthreads();
        for (int i = tid; i < 64 * 32; i += 256) {
            int row = i >> 5, c4 = i & 31;
            float4 v = ((const float4*)(Hf + row * LDH))[c4];
            split_store4(v, Hhi + row * LDHB + c4 * 4, Hlo + row * LDHB + c4 * 4);
        }
        __syncthreads();

        CF acc[4];
#pragma unroll
        for (int f = 0; f < 4; f++) wmma::fill_fragment(acc[f], 0.f);

        for (int kk = 0; kk < 128; kk += 16) {
            AF ah, al;
            wmma::load_matrix_sync(ah, Hhi + rt * 16 * LDHB + kk, LDHB);
            wmma::load_matrix_sync(al, Hlo + rt * 16 * LDHB + kk, LDHB);
#pragma unroll
            for (int f = 0; f < 4; f++) {
                BF bh, bl;
                wmma::load_matrix_sync(bh, Whi + kk * LDWB + cg * 64 + f * 16, LDWB);
                wmma::load_matrix_sync(bl, Wlo + kk * LDWB + cg * 64 + f * 16, LDWB);
                wmma::mma_sync(acc[f], ah, bh, acc[f]);
                wmma::mma_sync(acc[f], ah, bl, acc[f]);
                wmma::mma_sync(acc[f], al, bh, acc[f]);
            }
        }
        __syncthreads();
#pragma unroll
        for (int f = 0; f < 4; f++)
            wmma::store_matrix_sync(Hf + rt * 16 * LDH + cg * 64 + f * 16, acc[f], LDH, wmma::mem_row_major);
        __syncthreads();

        for (int i = tid; i < 64 * 32; i += 256) {
            int e = i >> 5, c4 = i & 31;
            float4 c2 = ((const float4*)(Hf + e * LDH))[c4];
            float4 bb = ((const float4*)eB2)[c4];
            float4 nv = make_float4(c2.x + bb.x, c2.y + bb.y, c2.z + bb.z, c2.w + bb.w);
            ((float4*)(g_el + (size_t)(ebase + e) * LL))[c4] = nv;
        }
    }
}

// ---------------------------------------------------------------- edge processor step
#define ES_SSH 0
#define ES_RSH 256
#define ES_B1  512
#define ES_B2  1024
#define ES_AHI 1536
#define ES_ALO 18944
#define ES_W   36352
#define ES_WLO 71168
#define ES_SMEM 105984

__global__ void __launch_bounds__(256, 2) k_edge_step(
    const int* __restrict__ snd, const int* __restrict__ rcv, int step,
    const float* __restrict__ B1, const float* __restrict__ B2)
{
    extern __shared__ char smc[];
    int*   ssh = (int*)(smc + ES_SSH);
    int*   rsh = (int*)(smc + ES_RSH);
    float* B1s = (float*)(smc + ES_B1);
    float* B2s = (float*)(smc + ES_B2);
    __nv_bfloat16* Ahi = (__nv_bfloat16*)(smc + ES_AHI);
    __nv_bfloat16* Alo = (__nv_bfloat16*)(smc + ES_ALO);
    __nv_bfloat16* Whi = (__nv_bfloat16*)(smc + ES_W);
    __nv_bfloat16* Wlo = (__nv_bfloat16*)(smc + ES_WLO);
    float*         Cf  = (float*)(smc + ES_W);
    const int tid = threadIdx.x;
    const int w = tid >> 5, rt = w >> 1, cg = w & 1;
    const int ebase = blockIdx.x * 64;
    const __nv_bfloat16* wbase = g_ws + (size_t)step * STEP_W;
    const uint32_t whi_b = smem_u32(Whi), wlo_b = smem_u32(Wlo);

    if (tid < 64) {
        ssh[tid] = snd[ebase + tid];
        rsh[tid] = rcv[ebase + tid];
    }
    if (tid < 128) {
        B1s[tid] = B1[tid];
        B2s[tid] = B2[tid];
    }
    // stage W1a via cp.async (overlaps with el gather below)
    for (int i = tid; i < 2048; i += 256) {
        int rr = i >> 4, g = i & 15;
        cp_async16(whi_b + (uint32_t)(rr * 136 + g * 8) * 2, wbase + EW1A_HI + rr * 128 + g * 8);
        cp_async16(wlo_b + (uint32_t)(rr * 136 + g * 8) * 2, wbase + EW1A_LO + rr * 128 + g * 8);
    }
    // gather el rows + split; HOLD values in registers for epilogue 2 residual
    float4 elv[8];
    {
        int j = 0;
        for (int i = tid; i < 2048; i += 256, j++) {
            int row = i >> 5, c4 = i & 31;
            float4 v = ((const float4*)(g_el + (size_t)(ebase + row) * LL))[c4];
            elv[j] = v;
            split_store4(v, Ahi + row * 136 + c4 * 4, Alo + row * 136 + c4 * 4);
        }
    }
    cp_commit_wait();
    __syncthreads();

    CF acc[4];
#pragma unroll
    for (int f = 0; f < 4; f++) wmma::fill_fragment(acc[f], 0.f);
    for (int kk = 0; kk < 128; kk += 16) {
        AF ah, al;
        wmma::load_matrix_sync(ah, Ahi + rt * 16 * 136 + kk, 136);
        wmma::load_matrix_sync(al, Alo + rt * 16 * 136 + kk, 136);
#pragma unroll
        for (int f = 0; f < 4; f++) {
            BF bh, bl;
            wmma::load_matrix_sync(bh, Whi + kk * 136 + cg * 64 + f * 16, 136);
            wmma::load_matrix_sync(bl, Wlo + kk * 136 + cg * 64 + f * 16, 136);
            wmma::mma_sync(acc[f], ah, bh, acc[f]);
            wmma::mma_sync(acc[f], ah, bl, acc[f]);
            wmma::mma_sync(acc[f], al, bh, acc[f]);
        }
    }
    __syncthreads();
#pragma unroll
    for (int f = 0; f < 4; f++)
        wmma::store_matrix_sync(Cf + rt * 16 * 132 + cg * 64 + f * 16, acc[f], 132, wmma::mem_row_major);
    __syncthreads();

    // epilogue 1: C1 + Z[s] + Z[r] + B1, relu -> A planes
    for (int i = tid; i < 2048; i += 256) {
        int row = i >> 5, c4 = i & 31;
        int s = ssh[row], r = rsh[row];
        float4 c = *(float4*)(Cf + row * 132 + c4 * 4);
        float4 zb = ((const float4*)(g_z + (size_t)s * 256))[c4];
        float4 zc = ((const float4*)(g_z + (size_t)r * 256 + 128))[c4];
        float4 b = ((const float4*)B1s)[c4];
        float4 v = make_float4(
            fmaxf(c.x + zb.x + zc.x + b.x, 0.f),
            fmaxf(c.y + zb.y + zc.y + b.y, 0.f),
            fmaxf(c.z + zb.z + zc.z + b.z, 0.f),
            fmaxf(c.w + zb.w + zc.w + b.w, 0.f));
        split_store4(v, Ahi + row * 136 + c4 * 4, Alo + row * 136 + c4 * 4);
    }
    __syncthreads();
    // stage W2 (overwrites Cf region)
    for (int i = tid; i < 2048; i += 256) {
        int rr = i >> 4, g = i & 15;
        cp_async16(whi_b + (uint32_t)(rr * 136 + g * 8) * 2, wbase + EW2_HI + rr * 128 + g * 8);
        cp_async16(wlo_b + (uint32_t)(rr * 136 + g * 8) * 2, wbase + EW2_LO + rr * 128 + g * 8);
    }
    cp_commit_wait();
    __syncthreads();

#pragma unroll
    for (int f = 0; f < 4; f++) wmma::fill_fragment(acc[f], 0.f);
    for (int kk = 0; kk < 128; kk += 16) {
        AF ah, al;
        wmma::load_matrix_sync(ah, Ahi + rt * 16 * 136 + kk, 136);
        wmma::load_matrix_sync(al, Alo + rt * 16 * 136 + kk, 136);
#pragma unroll
        for (int f = 0; f < 4; f++) {
            BF bh, bl;
            wmma::load_matrix_sync(bh, Whi + kk * 136 + cg * 64 + f * 16, 136);
            wmma::load_matrix_sync(bl, Wlo + kk * 136 + cg * 64 + f * 16, 136);
            wmma::mma_sync(acc[f], ah, bh, acc[f]);
            wmma::mma_sync(acc[f], ah, bl, acc[f]);
            wmma::mma_sync(acc[f], al, bh, acc[f]);
        }
    }
    __syncthreads();
#pragma unroll
    for (int f = 0; f < 4; f++)
        wmma::store_matrix_sync(Cf + rt * 16 * 132 + cg * 64 + f * 16, acc[f], 132, wmma::mem_row_major);
    __syncthreads();

    // epilogue 2: el += C2 + b2 (residual from registers); scatter-add into agg
    {
        int j = 0;
        for (int i = tid; i < 2048; i += 256, j++) {
            int row = i >> 5, c4 = i & 31;
            size_t go = (size_t)(ebase + row) * LL;
            float4 c = *(float4*)(Cf + row * 132 + c4 * 4);
            float4 b = ((const float4*)B2s)[c4];
            float4 nv = make_float4(elv[j].x + c.x + b.x, elv[j].y + c.y + b.y,
                                    elv[j].z + c.z + b.z, elv[j].w + c.w + b.w);
            ((float4*)(g_el + go))[c4] = nv;
            red_add_v4(g_agg + (size_t)rsh[row] * LL + c4 * 4, nv);
        }
    }
}

// ---------------------------------------------------------------- node step (+fused projection)
#define NS_XHI 0
#define NS_XLO 33792
#define NS_CF  0
#define NS_HHI 33792
#define NS_HLO 51200
#define NS_W   68608
#define NS_WLO 86016
#define NS_SMEM 103424

__global__ void __launch_bounds__(256, 2) k_node_step(
    int step, const float* __restrict__ B1, const float* __restrict__ B2, int do_proj)
{
    extern __shared__ char smc[];
    __nv_bfloat16* Xhi = (__nv_bfloat16*)(smc + NS_XHI);
    __nv_bfloat16* Xlo = (__nv_bfloat16*)(smc + NS_XLO);
    __nv_bfloat16* Whi = (__nv_bfloat16*)(smc + NS_W);
    __nv_bfloat16* Wlo = (__nv_bfloat16*)(smc + NS_WLO);
    float*         Cf  = (float*)(smc + NS_CF);
    __nv_bfloat16* Hhi = (__nv_bfloat16*)(smc + NS_HHI);
    __nv_bfloat16* Hlo = (__nv_bfloat16*)(smc + NS_HLO);
    const int tid = threadIdx.x;
    const int w = tid >> 5, rt = w >> 1, cg = w & 1;
    const int nbase = blockIdx.x * 64;
    const bool full = (nbase + 64 <= NN);
    const __nv_bfloat16* wbase = g_ws + (size_t)step * STEP_W;

    for (int i = tid; i < 64 * 64; i += 256) {
        int row = i >> 6, c4 = i & 63;
        int n = nbase + row;
        float4 v = make_float4(0.f, 0.f, 0.f, 0.f);
        if (n < NN) {
            if (c4 < 32) {
                v = ((const float4*)(g_nl + (size_t)n * LL))[c4];
            } else {
                float4* ap = (float4*)(g_agg + (size_t)n * LL) + (c4 - 32);
                v = *ap;
                *ap = make_float4(0.f, 0.f, 0.f, 0.f);
            }
        }
        split_store4(v, Xhi + row * 264 + c4 * 4, Xlo + row * 264 + c4 * 4);
    }

    CF acc[4];
#pragma unroll
    for (int f = 0; f < 4; f++) wmma::fill_fragment(acc[f], 0.f);

    for (int kc = 0; kc < 256; kc += 64) {
        __syncthreads();
        for (int i = tid; i < 1024; i += 256) {
            int rr = i >> 4, g = i & 15;
            *(float4*)(Whi + rr * 136 + g * 8) = ((const float4*)(wbase + NW1_HI + (kc + rr) * 128))[g];
            *(float4*)(Wlo + rr * 136 + g * 8) = ((const float4*)(wbase + NW1_LO + (kc + rr) * 128))[g];
        }
        __syncthreads();
        for (int kk = 0; kk < 64; kk += 16) {
            AF ah, al;
            wmma::load_matrix_sync(ah, Xhi + rt * 16 * 264 + kc + kk, 264);
            wmma::load_matrix_sync(al, Xlo + rt * 16 * 264 + kc + kk, 264);
#pragma unroll
            for (int f = 0; f < 4; f++) {
                BF bh, bl;
                wmma::load_matrix_sync(bh, Whi + kk * 136 + cg * 64 + f * 16, 136);
                wmma::load_matrix_sync(bl, Wlo + kk * 136 + cg * 64 + f * 16, 136);
                wmma::mma_sync(acc[f], ah, bh, acc[f]);
                wmma::mma_sync(acc[f], ah, bl, acc[f]);
                wmma::mma_sync(acc[f], al, bh, acc[f]);
            }
        }
    }
    __syncthreads();
#pragma unroll
    for (int f = 0; f < 4; f++)
        wmma::store_matrix_sync(Cf + rt * 16 * 132 + cg * 64 + f * 16, acc[f], 132, wmma::mem_row_major);
    __syncthreads();
    for (int i = tid; i < 64 * 32; i += 256) {
        int row = i >> 5, c4 = i & 31;
        float4 v = *(float4*)(Cf + row * 132 + c4 * 4);
        float4 bb = ((const float4*)B1)[c4];
        v.x = fmaxf(v.x + bb.x, 0.f);
        v.y = fmaxf(v.y + bb.y, 0.f);
        v.z = fmaxf(v.z + bb.z, 0.f);
        v.w = fmaxf(v.w + bb.w, 0.f);
        split_store4(v, Hhi + row * 136 + c4 * 4, Hlo + row * 136 + c4 * 4);
    }

#pragma unroll
    for (int f = 0; f < 4; f++) wmma::fill_fragment(acc[f], 0.f);
    for (int kc = 0; kc < 128; kc += 64) {
        __syncthreads();
        for (int i = tid; i < 1024; i += 256) {
            int rr = i >> 4, g = i & 15;
            *(float4*)(Whi + rr * 136 + g * 8) = ((const float4*)(wbase + NW2_HI + (kc + rr) * 128))[g];
            *(float4*)(Wlo + rr * 136 + g * 8) = ((const float4*)(wbase + NW2_LO + (kc + rr) * 128))[g];
        }
        __syncthreads();
        for (int kk = 0; kk < 64; kk += 16) {
            AF ah, al;
            wmma::load_matrix_sync(ah, Hhi + rt * 16 * 136 + kc + kk, 136);
            wmma::load_matrix_sync(al, Hlo + rt * 16 * 136 + kc + kk, 136);
#pragma unroll
            for (int f = 0; f < 4; f++) {
                BF bh, bl;
                wmma::load_matrix_sync(bh, Whi + kk * 136 + cg * 64 + f * 16, 136);
                wmma::load_matrix_sync(bl, Wlo + kk * 136 + cg * 64 + f * 16, 136);
                wmma::mma_sync(acc[f], ah, bh, acc[f]);
                wmma::mma_sync(acc[f], ah, bl, acc[f]);
                wmma::mma_sync(acc[f], al, bh, acc[f]);
            }
        }
    }
    __syncthreads();
#pragma unroll
    for (int f = 0; f < 4; f++)
        wmma::store_matrix_sync(Cf + rt * 16 * 132 + cg * 64 + f * 16, acc[f], 132, wmma::mem_row_major);
    __syncthreads();

    for (int i = tid; i < 64 * 32; i += 256) {
        int row = i >> 5, c4 = i & 31;
        int n = nbase + row;
        float4 nv = make_float4(0.f, 0.f, 0.f, 0.f);
        if (n < NN) {
            float4 oldv = ((const float4*)(g_nl + (size_t)n * LL))[c4];
            float4 c2 = *(float4*)(Cf + row * 132 + c4 * 4);
            float4 bb = ((const float4*)B2)[c4];
            nv = make_float4(oldv.x + c2.x + bb.x, oldv.y + c2.y + bb.y,
                             oldv.z + c2.z + bb.z, oldv.w + c2.w + bb.w);
            ((float4*)(g_nl + (size_t)n * LL))[c4] = nv;
        }
        if (do_proj)
            split_store4(nv, Hhi + row * 136 + c4 * 4, Hlo + row * 136 + c4 * 4);
    }

    if (do_proj) {
        const __nv_bfloat16* wn = g_ws + (size_t)(step + 1) * STEP_W;
#pragma unroll 1
        for (int half = 0; half < 2; ++half) {
#pragma unroll
            for (int f = 0; f < 4; f++) wmma::fill_fragment(acc[f], 0.f);
            for (int kc = 0; kc < 128; kc += 64) {
                __syncthreads();
                for (int i = tid; i < 1024; i += 256) {
                    int rr = i >> 4, g = i & 15;
                    *(float4*)(Whi + rr * 136 + g * 8) =
                        ((const float4*)(wn + PRJ_HI + (size_t)(kc + rr) * 256 + half * 128))[g];
                    *(float4*)(Wlo + rr * 136 + g * 8) =
                        ((const float4*)(wn + PRJ_LO + (size_t)(kc + rr) * 256 + half * 128))[g];
                }
                __syncthreads();
                for (int kk = 0; kk < 64; kk += 16) {
                    AF ah, al;
                    wmma::load_matrix_sync(ah, Hhi + rt * 16 * 136 + kc + kk, 136);
                    wmma::load_matrix_sync(al, Hlo + rt * 16 * 136 + kc + kk, 136);
#pragma unroll
                    for (int f = 0; f < 4; f++) {
                        BF bh, bl;
                        wmma::load_matrix_sync(bh, Whi + kk * 136 + cg * 64 + f * 16, 136);
                        wmma::load_matrix_sync(bl, Wlo + kk * 136 + cg * 64 + f * 16, 136);
                        wmma::mma_sync(acc[f], ah, bh, acc[f]);
                        wmma::mma_sync(acc[f], ah, bl, acc[f]);
                        wmma::mma_sync(acc[f], al, bh, acc[f]);
                    }
                }
            }
            if (full) {
#pragma unroll
                for (int f = 0; f < 4; f++)
                    wmma::store_matrix_sync(g_z + (size_t)(nbase + rt * 16) * 256 + half * 128 + cg * 64 + f * 16,
                                            acc[f], 256, wmma::mem_row_major);
            } else {
                __syncthreads();
#pragma unroll
                for (int f = 0; f < 4; f++)
                    wmma::store_matrix_sync(Cf + rt * 16 * 132 + cg * 64 + f * 16, acc[f], 132, wmma::mem_row_major);
                __syncthreads();
                for (int i = tid; i < 64 * 32; i += 256) {
                    int row = i >> 5, c4 = i & 31;
                    int n = nbase + row;
                    if (n < NN)
                        ((float4*)(g_z + (size_t)n * 256 + half * 128))[c4] =
                            *(float4*)(Cf + row * 132 + c4 * 4);
                }
            }
        }
    }
}

// ---------------------------------------------------------------- decoder (SIMT fp32; exact)
__global__ void __launch_bounds__(128) k_decoder(
    const float* __restrict__ W1, const float* __restrict__ B1,
    const float* __restrict__ W2, const float* __restrict__ B2,
    float* __restrict__ out)
{
    __shared__ float Xs[32][128];
    __shared__ float H[32][128];
    const int tid = threadIdx.x;
    const int nbase = blockIdx.x * 32;

    for (int i = tid; i < 32 * 32; i += 128) {
        int n = i >> 5, c4 = i & 31;
        int gn = nbase + n;
        float4 v = make_float4(0.f, 0.f, 0.f, 0.f);
        if (gn < NN) v = ((const float4*)(g_nl + (size_t)gn * LL))[c4];
        ((float4*)Xs[n])[c4] = v;
    }
    __syncthreads();

    const int j = tid;
#pragma unroll 1
    for (int n = 0; n < 32; n++) {
        float acc = B1[j];
#pragma unroll 8
        for (int k = 0; k < 128; k++) acc += Xs[n][k] * W1[k * 128 + j];
        H[n][j] = fmaxf(acc, 0.f);
    }
    __syncthreads();

    if (tid < 96) {
        int n = tid / 3, d = tid % 3;
        int gn = nbase + n;
        float acc = B2[d];
#pragma unroll 8
        for (int k = 0; k < 128; k++) acc += H[n][k] * W2[k * 3 + d];
        if (gn < NN) out[gn * 3 + d] = acc;
    }
}

// ---------------------------------------------------------------- launch
extern "C" void kernel_launch(void* const* d_in, const int* in_sizes, int n_in,
                              void* d_out, int out_size)
{
    const float* pos   = (const float*)d_in[0];
    const float* vel   = (const float*)d_in[1];
    const int*   rid   = (const int*)d_in[2];
    const int*   snd   = (const int*)d_in[3];
    const int*   rcv   = (const int*)d_in[4];
    const float* remb  = (const float*)d_in[5];
    const float* ne_w1 = (const float*)d_in[6];
    const float* ne_b1 = (const float*)d_in[7];
    const float* ne_w2 = (const float*)d_in[8];
    const float* ne_b2 = (const float*)d_in[9];
    const float* ee_w1 = (const float*)d_in[10];
    const float* ee_b1 = (const float*)d_in[11];
    const float* ee_w2 = (const float*)d_in[12];
    const float* ee_b2 = (const float*)d_in[13];
    const float* pe_w1 = (const float*)d_in[14];
    const float* pe_b1 = (const float*)d_in[15];
    const float* pe_w2 = (const float*)d_in[16];
    const float* pe_b2 = (const float*)d_in[17];
    const float* pn_w1 = (const float*)d_in[18];
    const float* pn_b1 = (const float*)d_in[19];
    const float* pn_w2 = (const float*)d_in[20];
    const float* pn_b2 = (const float*)d_in[21];
    const float* de_w1 = (const float*)d_in[22];
    const float* de_b1 = (const float*)d_in[23];
    const float* de_w2 = (const float*)d_in[24];
    const float* de_b2 = (const float*)d_in[25];

    cudaFuncSetAttribute(k_edge_step, cudaFuncAttributeMaxDynamicSharedMemorySize, ES_SMEM);
    cudaFuncSetAttribute(k_node_step, cudaFuncAttributeMaxDynamicSharedMemorySize, NS_SMEM);
    cudaFuncSetAttribute(k_enc_all, cudaFuncAttributeMaxDynamicSharedMemorySize, ENC_SMEM);

    // launches 0-2: setup, deg/center, encoders(+step-0 projection)
    k_setup<<<4676, 256>>>(pe_w1, pe_w2, pn_w1, pn_w2);
    k_degcenter<<<3229, 256>>>(rcv, pos);
    k_enc_all<<<NB_ENC + EB_ENC, 256, ENC_SMEM>>>(
        pos, vel, rid, remb, snd, rcv,
        ne_w1, ne_b1, ne_w2, ne_b2, ee_w1, ee_b1, ee_w2, ee_b2);

    // launch 3 = first k_edge_step (the profiled slot)
    for (int st = 0; st < NSTEPS; st++) {
        k_edge_step<<<EE / 64, 256, ES_SMEM>>>(
            snd, rcv, st, pe_b1 + (size_t)st * 128, pe_b2 + (size_t)st * 128);
        k_node_step<<<(NN + 63) / 64, 256, NS_SMEM>>>(
            st, pn_b1 + (size_t)st * 128, pn_b2 + (size_t)st * 128, (st < NSTEPS - 1) ? 1 : 0);
    }

    k_decoder<<<(NN + 31) / 32, 128>>>(de_w1, de_b1, de_w2, de_b2, (float*)d_out);
}

// round 8
// speedup vs baseline: 2.0661x; 1.0766x over previous
#include <cuda_runtime.h>
#include <cuda_bf16.h>
#include <mma.h>
#include <cstdint>

using namespace nvcuda;

#define NN 50000
#define EE 800000
#define LL 128
#define NSTEPS 10
#define NB_ENC 782          // ceil(NN/64)
#define EB_ENC 12500        // EE/64

// ---- scratch (device globals; no allocations allowed) ----
__device__ float g_nl[(size_t)NN * LL];
// el stored as bf16 hi/lo planes, tile-major: [tile(64 edges)][hi 64x128][lo 64x128]
__device__ __nv_bfloat16 g_el[(size_t)EE * 256];
__device__ float g_agg[(size_t)NN * LL];
__device__ float g_z[(size_t)NN * 256];
__device__ float g_deg[NN];
__device__ float g_center[3];

#define EW1A_HI 0
#define EW1A_LO 16384
#define EW2_HI  32768
#define EW2_LO  49152
#define PRJ_HI  65536
#define PRJ_LO  98304
#define NW1_HI  131072
#define NW1_LO  163840
#define NW2_HI  196608
#define NW2_LO  212992
#define STEP_W  229376
__device__ __nv_bfloat16 g_ws[(size_t)NSTEPS * STEP_W];

typedef wmma::fragment<wmma::matrix_a, 16, 16, 16, __nv_bfloat16, wmma::row_major> AF;
typedef wmma::fragment<wmma::matrix_b, 16, 16, 16, __nv_bfloat16, wmma::row_major> BF;
typedef wmma::fragment<wmma::accumulator, 16, 16, 16, float> CF;

__device__ __forceinline__ uint32_t smem_u32(const void* p) {
    uint32_t a;
    asm("{ .reg .u64 t; cvta.to.shared.u64 t, %1; cvt.u32.u64 %0, t; }" : "=r"(a) : "l"(p));
    return a;
}
__device__ __forceinline__ void cp_async16(uint32_t dst, const void* src) {
    asm volatile("cp.async.ca.shared.global [%0], [%1], 16;" :: "r"(dst), "l"(src) : "memory");
}
__device__ __forceinline__ void cp_commit_wait() {
    asm volatile("cp.async.commit_group;" ::: "memory");
    asm volatile("cp.async.wait_group 0;" ::: "memory");
}

__device__ __forceinline__ void split_store4(float4 v, __nv_bfloat16* hip, __nv_bfloat16* lop) {
    __nv_bfloat162 h0 = __floats2bfloat162_rn(v.x, v.y);
    __nv_bfloat162 h1 = __floats2bfloat162_rn(v.z, v.w);
    float2 f0 = __bfloat1622float2(h0);
    float2 f1 = __bfloat1622float2(h1);
    __nv_bfloat162 l0 = __floats2bfloat162_rn(v.x - f0.x, v.y - f0.y);
    __nv_bfloat162 l1 = __floats2bfloat162_rn(v.z - f1.x, v.w - f1.y);
    *(__nv_bfloat162*)(hip)     = h0;
    *(__nv_bfloat162*)(hip + 2) = h1;
    *(__nv_bfloat162*)(lop)     = l0;
    *(__nv_bfloat162*)(lop + 2) = l1;
}

// reconstruct fp32 float4 from hi/lo bf16 planes
__device__ __forceinline__ float4 join4(const __nv_bfloat16* hip, const __nv_bfloat16* lop) {
    float2 a = __bfloat1622float2(*(const __nv_bfloat162*)hip);
    float2 b = __bfloat1622float2(*(const __nv_bfloat162*)(hip + 2));
    float2 c = __bfloat1622float2(*(const __nv_bfloat162*)lop);
    float2 d = __bfloat1622float2(*(const __nv_bfloat162*)(lop + 2));
    return make_float4(a.x + c.x, a.y + c.y, b.x + d.x, b.y + d.y);
}

__device__ __forceinline__ void red_add_v4(float* dst, float4 v) {
    asm volatile("red.global.add.v4.f32 [%0], {%1,%2,%3,%4};"
                 :: "l"(dst), "f"(v.x), "f"(v.y), "f"(v.z), "f"(v.w) : "memory");
}

// ---------------------------------------------------------------- launch 0: weight prep + init
__global__ void __launch_bounds__(256) k_setup(
    const float* __restrict__ pe_w1, const float* __restrict__ pe_w2,
    const float* __restrict__ pn_w1, const float* __restrict__ pn_w2)
{
    if (blockIdx.x < 4480) {
        int idx = blockIdx.x * 256 + threadIdx.x;
        int s = idx / 114688;
        int e = idx % 114688;
        float v;
        size_t dhi, dlo;
        if (e < 16384) {
            v = pe_w1[(size_t)s * 384 * 128 + e];
            dhi = EW1A_HI + e; dlo = EW1A_LO + e;
        } else if (e < 32768) {
            int e2 = e - 16384;
            v = pe_w2[(size_t)s * 128 * 128 + e2];
            dhi = EW2_HI + e2; dlo = EW2_LO + e2;
        } else if (e < 65536) {
            int e2 = e - 32768;
            int k = e2 >> 8, n = e2 & 255;
            int srcrow = 128 + (n >> 7) * 128 + k;
            v = pe_w1[(size_t)s * 384 * 128 + (size_t)srcrow * 128 + (n & 127)];
            dhi = PRJ_HI + e2; dlo = PRJ_LO + e2;
        } else if (e < 98304) {
            int e2 = e - 65536;
            v = pn_w1[(size_t)s * 256 * 128 + e2];
            dhi = NW1_HI + e2; dlo = NW1_LO + e2;
        } else {
            int e2 = e - 98304;
            v = pn_w2[(size_t)s * 128 * 128 + e2];
            dhi = NW2_HI + e2; dlo = NW2_LO + e2;
        }
        __nv_bfloat16 h = __float2bfloat16(v);
        g_ws[(size_t)s * STEP_W + dhi] = h;
        g_ws[(size_t)s * STEP_W + dlo] = __float2bfloat16(v - __bfloat162float(h));
    } else {
        int i = (blockIdx.x - 4480) * 256 + threadIdx.x;
        if (i < NN) g_deg[i] = 0.f;
        if (i < 3) g_center[i] = 0.f;
    }
}

// ---------------------------------------------------------------- launch 1: degree + center
__global__ void __launch_bounds__(256) k_degcenter(
    const int* __restrict__ rcv, const float* __restrict__ pos)
{
    if (blockIdx.x < 3125) {
        int i = blockIdx.x * 256 + threadIdx.x;
        if (i < EE) atomicAdd(&g_deg[rcv[i]], 1.f);
    } else {
        float sx = 0.f, sy = 0.f, sz = 0.f;
        for (int i = (blockIdx.x - 3125) * 256 + threadIdx.x; i < NN; i += 104 * 256) {
            sx += pos[i * 3 + 0];
            sy += pos[i * 3 + 1];
            sz += pos[i * 3 + 2];
        }
#pragma unroll
        for (int o = 16; o > 0; o >>= 1) {
            sx += __shfl_down_sync(0xffffffffu, sx, o);
            sy += __shfl_down_sync(0xffffffffu, sy, o);
            sz += __shfl_down_sync(0xffffffffu, sz, o);
        }
        if ((threadIdx.x & 31) == 0) {
            atomicAdd(&g_center[0], sx);
            atomicAdd(&g_center[1], sy);
            atomicAdd(&g_center[2], sz);
        }
    }
}

// ---------------------------------------------------------------- launch 2: all encoders
#define ENC_SMEM 141312

__global__ void __launch_bounds__(256, 1) k_enc_all(
    const float* __restrict__ pos, const float* __restrict__ vel,
    const int* __restrict__ rid, const float* __restrict__ remb,
    const int* __restrict__ snd, const int* __restrict__ rcv,
    const float* __restrict__ nW1, const float* __restrict__ nB1,
    const float* __restrict__ nW2, const float* __restrict__ nB2,
    const float* __restrict__ eW1, const float* __restrict__ eB1,
    const float* __restrict__ eW2, const float* __restrict__ eB2)
{
    extern __shared__ char smc[];
    const int tid = threadIdx.x;

    if (blockIdx.x < NB_ENC) {
        // ===== node encoder (64 nodes) + projection step 0 =====
        float* F = (float*)(smc + 0);
        float* H = (float*)(smc + 8192);
        __nv_bfloat16* Ahi = (__nv_bfloat16*)(smc + 40960);
        __nv_bfloat16* Alo = (__nv_bfloat16*)(smc + 58368);
        __nv_bfloat16* Wch = (__nv_bfloat16*)(smc + 75776);
        __nv_bfloat16* Wcl = (__nv_bfloat16*)(smc + 93184);
        const int nbase = blockIdx.x * 64;
        const float inv = 1.f / (float)NN;
        const float cx = g_center[0] * inv, cy = g_center[1] * inv, cz = g_center[2] * inv;

        for (int i = tid; i < 64 * 23; i += 256) {
            int n = i / 23, k = i % 23;
            int gn = nbase + n;
            float v = 0.f;
            if (gn < NN) {
                if (k < 3) v = vel[gn * 3 + k];
                else if (k < 6) v = pos[gn * 3 + (k - 3)] - ((k == 3) ? cx : (k == 4) ? cy : cz);
                else if (k == 6) v = g_deg[gn];
                else v = remb[rid[gn] * 16 + (k - 7)];
            }
            F[n * 24 + k] = v;
        }
        __syncthreads();

        const int j = tid & 127;
        for (int n = tid >> 7; n < 64; n += 2) {
            float acc = nB1[j];
#pragma unroll
            for (int k = 0; k < 23; k++) acc += F[n * 24 + k] * nW1[k * 128 + j];
            H[n * 128 + j] = fmaxf(acc, 0.f);
        }
        __syncthreads();
        for (int n = tid >> 7; n < 64; n += 2) {
            int gn = nbase + n;
            float acc = nB2[j];
#pragma unroll 8
            for (int k = 0; k < 128; k++) acc += H[n * 128 + k] * nW2[k * 128 + j];
            float v = (gn < NN) ? acc : 0.f;
            if (gn < NN) g_nl[(size_t)gn * LL + j] = v;
            __nv_bfloat16 h = __float2bfloat16(v);
            Ahi[n * 136 + j] = h;
            Alo[n * 136 + j] = __float2bfloat16(v - __bfloat162float(h));
        }
        __syncthreads();

        // projection Z(0) = nl @ PRJ(0)
        const int w = tid >> 5, rt = w >> 1, cg = w & 1;
        const bool full = (nbase + 64 <= NN);
        const __nv_bfloat16* wn = g_ws;
        CF acc[4];
#pragma unroll 1
        for (int half = 0; half < 2; ++half) {
#pragma unroll
            for (int f = 0; f < 4; f++) wmma::fill_fragment(acc[f], 0.f);
            for (int kc = 0; kc < 128; kc += 64) {
                __syncthreads();
                for (int i = tid; i < 1024; i += 256) {
                    int rr = i >> 4, g = i & 15;
                    *(float4*)(Wch + rr * 136 + g * 8) =
                        ((const float4*)(wn + PRJ_HI + (size_t)(kc + rr) * 256 + half * 128))[g];
                    *(float4*)(Wcl + rr * 136 + g * 8) =
                        ((const float4*)(wn + PRJ_LO + (size_t)(kc + rr) * 256 + half * 128))[g];
                }
                __syncthreads();
                for (int kk = 0; kk < 64; kk += 16) {
                    AF ah, al;
                    wmma::load_matrix_sync(ah, Ahi + rt * 16 * 136 + kc + kk, 136);
                    wmma::load_matrix_sync(al, Alo + rt * 16 * 136 + kc + kk, 136);
#pragma unroll
                    for (int f = 0; f < 4; f++) {
                        BF bh, bl;
                        wmma::load_matrix_sync(bh, Wch + kk * 136 + cg * 64 + f * 16, 136);
                        wmma::load_matrix_sync(bl, Wcl + kk * 136 + cg * 64 + f * 16, 136);
                        wmma::mma_sync(acc[f], ah, bh, acc[f]);
                        wmma::mma_sync(acc[f], ah, bl, acc[f]);
                        wmma::mma_sync(acc[f], al, bh, acc[f]);
                    }
                }
            }
            if (full) {
#pragma unroll
                for (int f = 0; f < 4; f++)
                    wmma::store_matrix_sync(g_z + (size_t)(nbase + rt * 16) * 256 + half * 128 + cg * 64 + f * 16,
                                            acc[f], 256, wmma::mem_row_major);
            } else {
                float* Cf = (float*)(smc + 75776);   // dead W region; restaged next half
                __syncthreads();
#pragma unroll
                for (int f = 0; f < 4; f++)
                    wmma::store_matrix_sync(Cf + rt * 16 * 132 + cg * 64 + f * 16, acc[f], 132, wmma::mem_row_major);
                __syncthreads();
                for (int i = tid; i < 64 * 32; i += 256) {
                    int row = i >> 5, c4 = i & 31;
                    int n = nbase + row;
                    if (n < NN)
                        ((float4*)(g_z + (size_t)n * 256 + half * 128))[c4] =
                            *(float4*)(Cf + row * 132 + c4 * 4);
                }
            }
        }
        return;
    }

    // ===== edge encoder =====
    {
        const int LDF = 12, LDH = 132, LDHB = 136, LDWB = 136;
        float*         F   = (float*)(smc + 0);
        float*         Hf  = (float*)(smc + 3072);
        __nv_bfloat16* Hhi = (__nv_bfloat16*)(smc + 36864);
        __nv_bfloat16* Hlo = (__nv_bfloat16*)(smc + 54272);
        __nv_bfloat16* Whi = (__nv_bfloat16*)(smc + 71680);
        __nv_bfloat16* Wlo = (__nv_bfloat16*)(smc + 106496);
        const int w = tid >> 5, rt = w >> 1, cg = w & 1;
        const int tile = blockIdx.x - NB_ENC;
        const int ebase = tile * 64;

        if (tid < 64) {
            int e = ebase + tid;
            int s = snd[e], r = rcv[e];
            float rp0 = pos[s * 3 + 0] - pos[r * 3 + 0];
            float rp1 = pos[s * 3 + 1] - pos[r * 3 + 1];
            float rp2 = pos[s * 3 + 2] - pos[r * 3 + 2];
            float rv0 = vel[s * 3 + 0] - vel[r * 3 + 0];
            float rv1 = vel[s * 3 + 1] - vel[r * 3 + 1];
            float rv2 = vel[s * 3 + 2] - vel[r * 3 + 2];
            float sq = rp0 * rp0 + rp1 * rp1 + rp2 * rp2;
            float dist = sqrtf(sq);
            float same = (rid[s] == rid[r]) ? 1.f : 0.f;
            float* f = F + tid * LDF;
            f[0] = rp0; f[1] = rp1; f[2] = rp2;
            f[3] = rv0; f[4] = rv1; f[5] = rv2;
            f[6] = dist; f[7] = sq; f[8] = same;
        }
        for (int i = tid; i < 128 * 32; i += 256) {
            int rr = i >> 5, c4 = i & 31;
            float4 v = ((const float4*)(eW2 + rr * 128))[c4];
            split_store4(v, Whi + rr * LDWB + c4 * 4, Wlo + rr * LDWB + c4 * 4);
        }
        __syncthreads();

        for (int i = tid; i < 64 * 128; i += 256) {
            int e = i >> 7, jj = i & 127;
            const float* f = F + e * LDF;
            float acc = eB1[jj];
#pragma unroll
            for (int k = 0; k < 9; k++) acc += f[k] * eW1[k * 128 + jj];
            Hf[e * LDH + jj] = fmaxf(acc, 0.f);
        }
        __syncthreads();
        for (int i = tid; i < 64 * 32; i += 256) {
            int row = i >> 5, c4 = i & 31;
            float4 v = ((const float4*)(Hf + row * LDH))[c4];
            split_store4(v, Hhi + row * LDHB + c4 * 4, Hlo + row * LDHB + c4 * 4);
        }
        __syncthreads();

        CF acc[4];
#pragma unroll
        for (int f = 0; f < 4; f++) wmma::fill_fragment(acc[f], 0.f);

        for (int kk = 0; kk < 128; kk += 16) {
            AF ah, al;
            wmma::load_matrix_sync(ah, Hhi + rt * 16 * LDHB + kk, LDHB);
            wmma::load_matrix_sync(al, Hlo + rt * 16 * LDHB + kk, LDHB);
#pragma unroll
            for (int f = 0; f < 4; f++) {
                BF bh, bl;
                wmma::load_matrix_sync(bh, Whi + kk * LDWB + cg * 64 + f * 16, LDWB);
                wmma::load_matrix_sync(bl, Wlo + kk * LDWB + cg * 64 + f * 16, LDWB);
                wmma::mma_sync(acc[f], ah, bh, acc[f]);
                wmma::mma_sync(acc[f], ah, bl, acc[f]);
                wmma::mma_sync(acc[f], al, bh, acc[f]);
            }
        }
        __syncthreads();
#pragma unroll
        for (int f = 0; f < 4; f++)
            wmma::store_matrix_sync(Hf + rt * 16 * LDH + cg * 64 + f * 16, acc[f], LDH, wmma::mem_row_major);
        __syncthreads();

        // write el as bf16 hi/lo planes (tile-major layout)
        __nv_bfloat16* elbase = g_el + (size_t)tile * 16384;
        for (int i = tid; i < 64 * 32; i += 256) {
            int e = i >> 5, c4 = i & 31;
            float4 c2 = ((const float4*)(Hf + e * LDH))[c4];
            float4 bb = ((const float4*)eB2)[c4];
            float4 nv = make_float4(c2.x + bb.x, c2.y + bb.y, c2.z + bb.z, c2.w + bb.w);
            __nv_bfloat16* hp = elbase + e * 128 + c4 * 4;
            split_store4(nv, hp, hp + 8192);
        }
    }
}

// ---------------------------------------------------------------- edge processor step
// 64 edges/block, 256 threads, 8 warps tiled 2 (rows) x 4 (cols): warp = 32 rows x 32 cols.
#define ES_SSH 0
#define ES_RSH 256
#define ES_B1  512
#define ES_B2  1024
#define ES_AHI 1536
#define ES_ALO 18944
#define ES_W   36352
#define ES_WLO 71168
#define ES_SMEM 105984

__global__ void __launch_bounds__(256, 2) k_edge_step(
    const int* __restrict__ snd, const int* __restrict__ rcv, int step,
    const float* __restrict__ B1, const float* __restrict__ B2)
{
    extern __shared__ char smc[];
    int*   ssh = (int*)(smc + ES_SSH);
    int*   rsh = (int*)(smc + ES_RSH);
    float* B1s = (float*)(smc + ES_B1);
    float* B2s = (float*)(smc + ES_B2);
    __nv_bfloat16* Ahi = (__nv_bfloat16*)(smc + ES_AHI);
    __nv_bfloat16* Alo = (__nv_bfloat16*)(smc + ES_ALO);
    __nv_bfloat16* Whi = (__nv_bfloat16*)(smc + ES_W);
    __nv_bfloat16* Wlo = (__nv_bfloat16*)(smc + ES_WLO);
    float*         Cf  = (float*)(smc + ES_W);     // aliases W
    const int tid = threadIdx.x;
    const int w = tid >> 5, rt = w & 1, cg = w >> 1;   // 2 x 4 tiling
    const int ebase = blockIdx.x * 64;
    const __nv_bfloat16* wbase = g_ws + (size_t)step * STEP_W;
    __nv_bfloat16* elbase = g_el + (size_t)blockIdx.x * 16384;
    const uint32_t whi_b = smem_u32(Whi), wlo_b = smem_u32(Wlo);
    const uint32_t ahi_b = smem_u32(Ahi), alo_b = smem_u32(Alo);

    if (tid < 64) {
        ssh[tid] = snd[ebase + tid];
        rsh[tid] = rcv[ebase + tid];
    }
    if (tid < 128) {
        B1s[tid] = B1[tid];
        B2s[tid] = B2[tid];
    }
    // cp.async el planes (pre-split in global) straight into A region
    for (int i = tid; i < 1024; i += 256) {
        int r = i >> 4, g = i & 15;
        cp_async16(ahi_b + (uint32_t)(r * 272 + g * 16), elbase + r * 128 + g * 8);
        cp_async16(alo_b + (uint32_t)(r * 272 + g * 16), elbase + 8192 + r * 128 + g * 8);
    }
    // cp.async W1a planes
    for (int i = tid; i < 2048; i += 256) {
        int rr = i >> 4, g = i & 15;
        cp_async16(whi_b + (uint32_t)(rr * 136 + g * 8) * 2, wbase + EW1A_HI + rr * 128 + g * 8);
        cp_async16(wlo_b + (uint32_t)(rr * 136 + g * 8) * 2, wbase + EW1A_LO + rr * 128 + g * 8);
    }
    cp_commit_wait();
    __syncthreads();

    // ---- GEMM1: el @ W1a (2x4 warp tiling)
    CF acc[2][2];
#pragma unroll
    for (int sr = 0; sr < 2; sr++)
#pragma unroll
        for (int sc = 0; sc < 2; sc++) wmma::fill_fragment(acc[sr][sc], 0.f);
    for (int kk = 0; kk < 128; kk += 16) {
        AF ah[2], al[2];
#pragma unroll
        for (int sr = 0; sr < 2; sr++) {
            wmma::load_matrix_sync(ah[sr], Ahi + (rt * 32 + sr * 16) * 136 + kk, 136);
            wmma::load_matrix_sync(al[sr], Alo + (rt * 32 + sr * 16) * 136 + kk, 136);
        }
#pragma unroll
        for (int sc = 0; sc < 2; sc++) {
            BF bh, bl;
            wmma::load_matrix_sync(bh, Whi + kk * 136 + cg * 32 + sc * 16, 136);
            wmma::load_matrix_sync(bl, Wlo + kk * 136 + cg * 32 + sc * 16, 136);
#pragma unroll
            for (int sr = 0; sr < 2; sr++) {
                wmma::mma_sync(acc[sr][sc], ah[sr], bh, acc[sr][sc]);
                wmma::mma_sync(acc[sr][sc], ah[sr], bl, acc[sr][sc]);
                wmma::mma_sync(acc[sr][sc], al[sr], bh, acc[sr][sc]);
            }
        }
    }
    __syncthreads();
#pragma unroll
    for (int sr = 0; sr < 2; sr++)
#pragma unroll
        for (int sc = 0; sc < 2; sc++)
            wmma::store_matrix_sync(Cf + (rt * 32 + sr * 16) * 132 + cg * 32 + sc * 16,
                                    acc[sr][sc], 132, wmma::mem_row_major);
    __syncthreads();

    // ---- epilogue 1: reconstruct el_old -> regs; v = relu(C1 + Z[s] + Z[r] + B1) -> H planes (over A)
    float4 elv[8];
    {
        int j = 0;
        for (int i = tid; i < 2048; i += 256, j++) {
            int row = i >> 5, c4 = i & 31;
            elv[j] = join4(Ahi + row * 136 + c4 * 4, Alo + row * 136 + c4 * 4);
            int s = ssh[row], r = rsh[row];
            float4 c = *(float4*)(Cf + row * 132 + c4 * 4);
            float4 zb = ((const float4*)(g_z + (size_t)s * 256))[c4];
            float4 zc = ((const float4*)(g_z + (size_t)r * 256 + 128))[c4];
            float4 b = ((const float4*)B1s)[c4];
            float4 v = make_float4(
                fmaxf(c.x + zb.x + zc.x + b.x, 0.f),
                fmaxf(c.y + zb.y + zc.y + b.y, 0.f),
                fmaxf(c.z + zb.z + zc.z + b.z, 0.f),
                fmaxf(c.w + zb.w + zc.w + b.w, 0.f));
            split_store4(v, Ahi + row * 136 + c4 * 4, Alo + row * 136 + c4 * 4);
        }
    }
    __syncthreads();
    // stage W2 (over Cf)
    for (int i = tid; i < 2048; i += 256) {
        int rr = i >> 4, g = i & 15;
        cp_async16(whi_b + (uint32_t)(rr * 136 + g * 8) * 2, wbase + EW2_HI + rr * 128 + g * 8);
        cp_async16(wlo_b + (uint32_t)(rr * 136 + g * 8) * 2, wbase + EW2_LO + rr * 128 + g * 8);
    }
    cp_commit_wait();
    __syncthreads();

    // ---- GEMM2: H @ W2
#pragma unroll
    for (int sr = 0; sr < 2; sr++)
#pragma unroll
        for (int sc = 0; sc < 2; sc++) wmma::fill_fragment(acc[sr][sc], 0.f);
    for (int kk = 0; kk < 128; kk += 16) {
        AF ah[2], al[2];
#pragma unroll
        for (int sr = 0; sr < 2; sr++) {
            wmma::load_matrix_sync(ah[sr], Ahi + (rt * 32 + sr * 16) * 136 + kk, 136);
            wmma::load_matrix_sync(al[sr], Alo + (rt * 32 + sr * 16) * 136 + kk, 136);
        }
#pragma unroll
        for (int sc = 0; sc < 2; sc++) {
            BF bh, bl;
            wmma::load_matrix_sync(bh, Whi + kk * 136 + cg * 32 + sc * 16, 136);
            wmma::load_matrix_sync(bl, Wlo + kk * 136 + cg * 32 + sc * 16, 136);
#pragma unroll
            for (int sr = 0; sr < 2; sr++) {
                wmma::mma_sync(acc[sr][sc], ah[sr], bh, acc[sr][sc]);
                wmma::mma_sync(acc[sr][sc], ah[sr], bl, acc[sr][sc]);
                wmma::mma_sync(acc[sr][sc], al[sr], bh, acc[sr][sc]);
            }
        }
    }
    __syncthreads();
#pragma unroll
    for (int sr = 0; sr < 2; sr++)
#pragma unroll
        for (int sc = 0; sc < 2; sc++)
            wmma::store_matrix_sync(Cf + (rt * 32 + sr * 16) * 132 + cg * 32 + sc * 16,
                                    acc[sr][sc], 132, wmma::mem_row_major);
    __syncthreads();

    // ---- epilogue 2: el_new = el_old + C2 + b2 -> bf16 planes to global; scatter-add agg
    {
        int j = 0;
        for (int i = tid; i < 2048; i += 256, j++) {
            int row = i >> 5, c4 = i & 31;
            float4 c = *(float4*)(Cf + row * 132 + c4 * 4);
            float4 b = ((const float4*)B2s)[c4];
            float4 nv = make_float4(elv[j].x + c.x + b.x, elv[j].y + c.y + b.y,
                                    elv[j].z + c.z + b.z, elv[j].w + c.w + b.w);
            __nv_bfloat16* hp = elbase + row * 128 + c4 * 4;
            split_store4(nv, hp, hp + 8192);
            red_add_v4(g_agg + (size_t)rsh[row] * LL + c4 * 4, nv);
        }
    }
}

// ---------------------------------------------------------------- node step (+fused projection)
#define NS_XHI 0
#define NS_XLO 33792
#define NS_CF  0
#define NS_HHI 33792
#define NS_HLO 51200
#define NS_W   68608
#define NS_WLO 86016
#define NS_SMEM 103424

__global__ void __launch_bounds__(256, 2) k_node_step(
    int step, const float* __restrict__ B1, const float* __restrict__ B2, int do_proj)
{
    extern __shared__ char smc[];
    __nv_bfloat16* Xhi = (__nv_bfloat16*)(smc + NS_XHI);
    __nv_bfloat16* Xlo = (__nv_bfloat16*)(smc + NS_XLO);
    __nv_bfloat16* Whi = (__nv_bfloat16*)(smc + NS_W);
    __nv_bfloat16* Wlo = (__nv_bfloat16*)(smc + NS_WLO);
    float*         Cf  = (float*)(smc + NS_CF);
    __nv_bfloat16* Hhi = (__nv_bfloat16*)(smc + NS_HHI);
    __nv_bfloat16* Hlo = (__nv_bfloat16*)(smc + NS_HLO);
    const int tid = threadIdx.x;
    const int w = tid >> 5, rt = w >> 1, cg = w & 1;
    const int nbase = blockIdx.x * 64;
    const bool full = (nbase + 64 <= NN);
    const __nv_bfloat16* wbase = g_ws + (size_t)step * STEP_W;

    for (int i = tid; i < 64 * 64; i += 256) {
        int row = i >> 6, c4 = i & 63;
        int n = nbase + row;
        float4 v = make_float4(0.f, 0.f, 0.f, 0.f);
        if (n < NN) {
            if (c4 < 32) {
                v = ((const float4*)(g_nl + (size_t)n * LL))[c4];
            } else {
                float4* ap = (float4*)(g_agg + (size_t)n * LL) + (c4 - 32);
                v = *ap;
                *ap = make_float4(0.f, 0.f, 0.f, 0.f);
            }
        }
        split_store4(v, Xhi + row * 264 + c4 * 4, Xlo + row * 264 + c4 * 4);
    }

    CF acc[4];
#pragma unroll
    for (int f = 0; f < 4; f++) wmma::fill_fragment(acc[f], 0.f);

    for (int kc = 0; kc < 256; kc += 64) {
        __syncthreads();
        for (int i = tid; i < 1024; i += 256) {
            int rr = i >> 4, g = i & 15;
            *(float4*)(Whi + rr * 136 + g * 8) = ((const float4*)(wbase + NW1_HI + (kc + rr) * 128))[g];
            *(float4*)(Wlo + rr * 136 + g * 8) = ((const float4*)(wbase + NW1_LO + (kc + rr) * 128))[g];
        }
        __syncthreads();
        for (int kk = 0; kk < 64; kk += 16) {
            AF ah, al;
            wmma::load_matrix_sync(ah, Xhi + rt * 16 * 264 + kc + kk, 264);
            wmma::load_matrix_sync(al, Xlo + rt * 16 * 264 + kc + kk, 264);
#pragma unroll
            for (int f = 0; f < 4; f++) {
                BF bh, bl;
                wmma::load_matrix_sync(bh, Whi + kk * 136 + cg * 64 + f * 16, 136);
                wmma::load_matrix_sync(bl, Wlo + kk * 136 + cg * 64 + f * 16, 136);
                wmma::mma_sync(acc[f], ah, bh, acc[f]);
                wmma::mma_sync(acc[f], ah, bl, acc[f]);
                wmma::mma_sync(acc[f], al, bh, acc[f]);
            }
        }
    }
    __syncthreads();
#pragma unroll
    for (int f = 0; f < 4; f++)
        wmma::store_matrix_sync(Cf + rt * 16 * 132 + cg * 64 + f * 16, acc[f], 132, wmma::mem_row_major);
    __syncthreads();
    for (int i = tid; i < 64 * 32; i += 256) {
        int row = i >> 5, c4 = i & 31;
        float4 v = *(float4*)(Cf + row * 132 + c4 * 4);
        float4 bb = ((const float4*)B1)[c4];
        v.x = fmaxf(v.x + bb.x, 0.f);
        v.y = fmaxf(v.y + bb.y, 0.f);
        v.z = fmaxf(v.z + bb.z, 0.f);
        v.w = fmaxf(v.w + bb.w, 0.f);
        split_store4(v, Hhi + row * 136 + c4 * 4, Hlo + row * 136 + c4 * 4);
    }

#pragma unroll
    for (int f = 0; f < 4; f++) wmma::fill_fragment(acc[f], 0.f);
    for (int kc = 0; kc < 128; kc += 64) {
        __syncthreads();
        for (int i = tid; i < 1024; i += 256) {
            int rr = i >> 4, g = i & 15;
            *(float4*)(Whi + rr * 136 + g * 8) = ((const float4*)(wbase + NW2_HI + (kc + rr) * 128))[g];
            *(float4*)(Wlo + rr * 136 + g * 8) = ((const float4*)(wbase + NW2_LO + (kc + rr) * 128))[g];
        }
        __syncthreads();
        for (int kk = 0; kk < 64; kk += 16) {
            AF ah, al;
            wmma::load_matrix_sync(ah, Hhi + rt * 16 * 136 + kc + kk, 136);
            wmma::load_matrix_sync(al, Hlo + rt * 16 * 136 + kc + kk, 136);
#pragma unroll
            for (int f = 0; f < 4; f++) {
                BF bh, bl;
                wmma::load_matrix_sync(bh, Whi + kk * 136 + cg * 64 + f * 16, 136);
                wmma::load_matrix_sync(bl, Wlo + kk * 136 + cg * 64 + f * 16, 136);
                wmma::mma_sync(acc[f], ah, bh, acc[f]);
                wmma::mma_sync(acc[f], ah, bl, acc[f]);
                wmma::mma_sync(acc[f], al, bh, acc[f]);
            }
        }
    }
    __syncthreads();
#pragma unroll
    for (int f = 0; f < 4; f++)
        wmma::store_matrix_sync(Cf + rt * 16 * 132 + cg * 64 + f * 16, acc[f], 132, wmma::mem_row_major);
    __syncthreads();

    for (int i = tid; i < 64 * 32; i += 256) {
        int row = i >> 5, c4 = i & 31;
        int n = nbase + row;
        float4 nv = make_float4(0.f, 0.f, 0.f, 0.f);
        if (n < NN) {
            float4 oldv = ((const float4*)(g_nl + (size_t)n * LL))[c4];
            float4 c2 = *(float4*)(Cf + row * 132 + c4 * 4);
            float4 bb = ((const float4*)B2)[c4];
            nv = make_float4(oldv.x + c2.x + bb.x, oldv.y + c2.y + bb.y,
                             oldv.z + c2.z + bb.z, oldv.w + c2.w + bb.w);
            ((float4*)(g_nl + (size_t)n * LL))[c4] = nv;
        }
        if (do_proj)
            split_store4(nv, Hhi + row * 136 + c4 * 4, Hlo + row * 136 + c4 * 4);
    }

    if (do_proj) {
        const __nv_bfloat16* wn = g_ws + (size_t)(step + 1) * STEP_W;
#pragma unroll 1
        for (int half = 0; half < 2; ++half) {
#pragma unroll
            for (int f = 0; f < 4; f++) wmma::fill_fragment(acc[f], 0.f);
            for (int kc = 0; kc < 128; kc += 64) {
                __syncthreads();
                for (int i = tid; i < 1024; i += 256) {
                    int rr = i >> 4, g = i & 15;
                    *(float4*)(Whi + rr * 136 + g * 8) =
                        ((const float4*)(wn + PRJ_HI + (size_t)(kc + rr) * 256 + half * 128))[g];
                    *(float4*)(Wlo + rr * 136 + g * 8) =
                        ((const float4*)(wn + PRJ_LO + (size_t)(kc + rr) * 256 + half * 128))[g];
                }
                __syncthreads();
                for (int kk = 0; kk < 64; kk += 16) {
                    AF ah, al;
                    wmma::load_matrix_sync(ah, Hhi + rt * 16 * 136 + kc + kk, 136);
                    wmma::load_matrix_sync(al, Hlo + rt * 16 * 136 + kc + kk, 136);
#pragma unroll
                    for (int f = 0; f < 4; f++) {
                        BF bh, bl;
                        wmma::load_matrix_sync(bh, Whi + kk * 136 + cg * 64 + f * 16, 136);
                        wmma::load_matrix_sync(bl, Wlo + kk * 136 + cg * 64 + f * 16, 136);
                        wmma::mma_sync(acc[f], ah, bh, acc[f]);
                        wmma::mma_sync(acc[f], ah, bl, acc[f]);
                        wmma::mma_sync(acc[f], al, bh, acc[f]);
                    }
                }
            }
            if (full) {
#pragma unroll
                for (int f = 0; f < 4; f++)
                    wmma::store_matrix_sync(g_z + (size_t)(nbase + rt * 16) * 256 + half * 128 + cg * 64 + f * 16,
                                            acc[f], 256, wmma::mem_row_major);
            } else {
                __syncthreads();
#pragma unroll
                for (int f = 0; f < 4; f++)
                    wmma::store_matrix_sync(Cf + rt * 16 * 132 + cg * 64 + f * 16, acc[f], 132, wmma::mem_row_major);
                __syncthreads();
                for (int i = tid; i < 64 * 32; i += 256) {
                    int row = i >> 5, c4 = i & 31;
                    int n = nbase + row;
                    if (n < NN)
                        ((float4*)(g_z + (size_t)n * 256 + half * 128))[c4] =
                            *(float4*)(Cf + row * 132 + c4 * 4);
                }
            }
        }
    }
}

// ---------------------------------------------------------------- decoder (SIMT fp32; exact)
__global__ void __launch_bounds__(128) k_decoder(
    const float* __restrict__ W1, const float* __restrict__ B1,
    const float* __restrict__ W2, const float* __restrict__ B2,
    float* __restrict__ out)
{
    __shared__ float Xs[32][128];
    __shared__ float H[32][128];
    const int tid = threadIdx.x;
    const int nbase = blockIdx.x * 32;

    for (int i = tid; i < 32 * 32; i += 128) {
        int n = i >> 5, c4 = i & 31;
        int gn = nbase + n;
        float4 v = make_float4(0.f, 0.f, 0.f, 0.f);
        if (gn < NN) v = ((const float4*)(g_nl + (size_t)gn * LL))[c4];
        ((float4*)Xs[n])[c4] = v;
    }
    __syncthreads();

    const int j = tid;
#pragma unroll 1
    for (int n = 0; n < 32; n++) {
        float acc = B1[j];
#pragma unroll 8
        for (int k = 0; k < 128; k++) acc += Xs[n][k] * W1[k * 128 + j];
        H[n][j] = fmaxf(acc, 0.f);
    }
    __syncthreads();

    if (tid < 96) {
        int n = tid / 3, d = tid % 3;
        int gn = nbase + n;
        float acc = B2[d];
#pragma unroll 8
        for (int k = 0; k < 128; k++) acc += H[n][k] * W2[k * 3 + d];
        if (gn < NN) out[gn * 3 + d] = acc;
    }
}

// ---------------------------------------------------------------- launch
extern "C" void kernel_launch(void* const* d_in, const int* in_sizes, int n_in,
                              void* d_out, int out_size)
{
    const float* pos   = (const float*)d_in[0];
    const float* vel   = (const float*)d_in[1];
    const int*   rid   = (const int*)d_in[2];
    const int*   snd   = (const int*)d_in[3];
    const int*   rcv   = (const int*)d_in[4];
    const float* remb  = (const float*)d_in[5];
    const float* ne_w1 = (const float*)d_in[6];
    const float* ne_b1 = (const float*)d_in[7];
    const float* ne_w2 = (const float*)d_in[8];
    const float* ne_b2 = (const float*)d_in[9];
    const float* ee_w1 = (const float*)d_in[10];
    const float* ee_b1 = (const float*)d_in[11];
    const float* ee_w2 = (const float*)d_in[12];
    const float* ee_b2 = (const float*)d_in[13];
    const float* pe_w1 = (const float*)d_in[14];
    const float* pe_b1 = (const float*)d_in[15];
    const float* pe_w2 = (const float*)d_in[16];
    const float* pe_b2 = (const float*)d_in[17];
    const float* pn_w1 = (const float*)d_in[18];
    const float* pn_b1 = (const float*)d_in[19];
    const float* pn_w2 = (const float*)d_in[20];
    const float* pn_b2 = (const float*)d_in[21];
    const float* de_w1 = (const float*)d_in[22];
    const float* de_b1 = (const float*)d_in[23];
    const float* de_w2 = (const float*)d_in[24];
    const float* de_b2 = (const float*)d_in[25];

    cudaFuncSetAttribute(k_edge_step, cudaFuncAttributeMaxDynamicSharedMemorySize, ES_SMEM);
    cudaFuncSetAttribute(k_node_step, cudaFuncAttributeMaxDynamicSharedMemorySize, NS_SMEM);
    cudaFuncSetAttribute(k_enc_all, cudaFuncAttributeMaxDynamicSharedMemorySize, ENC_SMEM);

    k_setup<<<4676, 256>>>(pe_w1, pe_w2, pn_w1, pn_w2);
    k_degcenter<<<3229, 256>>>(rcv, pos);
    k_enc_all<<<NB_ENC + EB_ENC, 256, ENC_SMEM>>>(
        pos, vel, rid, remb, snd, rcv,
        ne_w1, ne_b1, ne_w2, ne_b2, ee_w1, ee_b1, ee_w2, ee_b2);

    // launch 3 = first k_edge_step (the profiled slot)
    for (int st = 0; st < NSTEPS; st++) {
        k_edge_step<<<EE / 64, 256, ES_SMEM>>>(
            snd, rcv, st, pe_b1 + (size_t)st * 128, pe_b2 + (size_t)st * 128);
        k_node_step<<<(NN + 63) / 64, 256, NS_SMEM>>>(
            st, pn_b1 + (size_t)st * 128, pn_b2 + (size_t)st * 128, (st < NSTEPS - 1) ? 1 : 0);
    }

    k_decoder<<<(NN + 31) / 32, 128>>>(de_w1, de_b1, de_w2, de_b2, (float*)d_out);
}

// round 9
// speedup vs baseline: 2.2253x; 1.0770x over previous
#include <cuda_runtime.h>
#include <cuda_bf16.h>
#include <mma.h>
#include <cstdint>

using namespace nvcuda;

#define NN 50000
#define EE 800000
#define LL 128
#define NSTEPS 10
#define NB_ENC 782          // ceil(NN/64)
#define EB_ENC 12500        // EE/64

// ---- scratch (device globals; no allocations allowed) ----
__device__ float g_nl[(size_t)NN * LL];
// el stored as bf16 hi/lo planes, tile-major: [tile(64 edges)][hi 64x128][lo 64x128]
__device__ __nv_bfloat16 g_el[(size_t)EE * 256];
__device__ float g_agg[(size_t)NN * LL];
__device__ float g_z[(size_t)NN * 256];
__device__ float g_deg[NN];
__device__ float g_center[3];

#define EW1A_HI 0
#define EW1A_LO 16384
#define EW2_HI  32768
#define EW2_LO  49152
#define PRJ_HI  65536
#define PRJ_LO  98304
#define NW1_HI  131072
#define NW1_LO  163840
#define NW2_HI  196608
#define NW2_LO  212992
#define STEP_W  229376
__device__ __nv_bfloat16 g_ws[(size_t)NSTEPS * STEP_W];

typedef wmma::fragment<wmma::matrix_a, 16, 16, 16, __nv_bfloat16, wmma::row_major> AF;
typedef wmma::fragment<wmma::matrix_b, 16, 16, 16, __nv_bfloat16, wmma::row_major> BF;
typedef wmma::fragment<wmma::accumulator, 16, 16, 16, float> CF;

__device__ __forceinline__ uint32_t smem_u32(const void* p) {
    uint32_t a;
    asm("{ .reg .u64 t; cvta.to.shared.u64 t, %1; cvt.u32.u64 %0, t; }" : "=r"(a) : "l"(p));
    return a;
}
__device__ __forceinline__ void cp_async16(uint32_t dst, const void* src) {
    asm volatile("cp.async.ca.shared.global [%0], [%1], 16;" :: "r"(dst), "l"(src) : "memory");
}
__device__ __forceinline__ void cp_commit_wait() {
    asm volatile("cp.async.commit_group;" ::: "memory");
    asm volatile("cp.async.wait_group 0;" ::: "memory");
}

__device__ __forceinline__ void split_store4(float4 v, __nv_bfloat16* hip, __nv_bfloat16* lop) {
    __nv_bfloat162 h0 = __floats2bfloat162_rn(v.x, v.y);
    __nv_bfloat162 h1 = __floats2bfloat162_rn(v.z, v.w);
    float2 f0 = __bfloat1622float2(h0);
    float2 f1 = __bfloat1622float2(h1);
    __nv_bfloat162 l0 = __floats2bfloat162_rn(v.x - f0.x, v.y - f0.y);
    __nv_bfloat162 l1 = __floats2bfloat162_rn(v.z - f1.x, v.w - f1.y);
    *(__nv_bfloat162*)(hip)     = h0;
    *(__nv_bfloat162*)(hip + 2) = h1;
    *(__nv_bfloat162*)(lop)     = l0;
    *(__nv_bfloat162*)(lop + 2) = l1;
}

__device__ __forceinline__ float4 join4(const __nv_bfloat16* hip, const __nv_bfloat16* lop) {
    float2 a = __bfloat1622float2(*(const __nv_bfloat162*)hip);
    float2 b = __bfloat1622float2(*(const __nv_bfloat162*)(hip + 2));
    float2 c = __bfloat1622float2(*(const __nv_bfloat162*)lop);
    float2 d = __bfloat1622float2(*(const __nv_bfloat162*)(lop + 2));
    return make_float4(a.x + c.x, a.y + c.y, b.x + d.x, b.y + d.y);
}

__device__ __forceinline__ void red_add_v4(float* dst, float4 v) {
    asm volatile("red.global.add.v4.f32 [%0], {%1,%2,%3,%4};"
                 :: "l"(dst), "f"(v.x), "f"(v.y), "f"(v.z), "f"(v.w) : "memory");
}

// ---------------------------------------------------------------- launch 0: weight prep + init
__global__ void __launch_bounds__(256) k_setup(
    const float* __restrict__ pe_w1, const float* __restrict__ pe_w2,
    const float* __restrict__ pn_w1, const float* __restrict__ pn_w2)
{
    if (blockIdx.x < 4480) {
        int idx = blockIdx.x * 256 + threadIdx.x;
        int s = idx / 114688;
        int e = idx % 114688;
        float v;
        size_t dhi, dlo;
        if (e < 16384) {
            v = pe_w1[(size_t)s * 384 * 128 + e];
            dhi = EW1A_HI + e; dlo = EW1A_LO + e;
        } else if (e < 32768) {
            int e2 = e - 16384;
            v = pe_w2[(size_t)s * 128 * 128 + e2];
            dhi = EW2_HI + e2; dlo = EW2_LO + e2;
        } else if (e < 65536) {
            int e2 = e - 32768;
            int k = e2 >> 8, n = e2 & 255;
            int srcrow = 128 + (n >> 7) * 128 + k;
            v = pe_w1[(size_t)s * 384 * 128 + (size_t)srcrow * 128 + (n & 127)];
            dhi = PRJ_HI + e2; dlo = PRJ_LO + e2;
        } else if (e < 98304) {
            int e2 = e - 65536;
            v = pn_w1[(size_t)s * 256 * 128 + e2];
            dhi = NW1_HI + e2; dlo = NW1_LO + e2;
        } else {
            int e2 = e - 98304;
            v = pn_w2[(size_t)s * 128 * 128 + e2];
            dhi = NW2_HI + e2; dlo = NW2_LO + e2;
        }
        __nv_bfloat16 h = __float2bfloat16(v);
        g_ws[(size_t)s * STEP_W + dhi] = h;
        g_ws[(size_t)s * STEP_W + dlo] = __float2bfloat16(v - __bfloat162float(h));
    } else {
        int i = (blockIdx.x - 4480) * 256 + threadIdx.x;
        if (i < NN) g_deg[i] = 0.f;
        if (i < 3) g_center[i] = 0.f;
    }
}

// ---------------------------------------------------------------- launch 1: degree + center
__global__ void __launch_bounds__(256) k_degcenter(
    const int* __restrict__ rcv, const float* __restrict__ pos)
{
    if (blockIdx.x < 3125) {
        int i = blockIdx.x * 256 + threadIdx.x;
        if (i < EE) atomicAdd(&g_deg[rcv[i]], 1.f);
    } else {
        float sx = 0.f, sy = 0.f, sz = 0.f;
        for (int i = (blockIdx.x - 3125) * 256 + threadIdx.x; i < NN; i += 104 * 256) {
            sx += pos[i * 3 + 0];
            sy += pos[i * 3 + 1];
            sz += pos[i * 3 + 2];
        }
#pragma unroll
        for (int o = 16; o > 0; o >>= 1) {
            sx += __shfl_down_sync(0xffffffffu, sx, o);
            sy += __shfl_down_sync(0xffffffffu, sy, o);
            sz += __shfl_down_sync(0xffffffffu, sz, o);
        }
        if ((threadIdx.x & 31) == 0) {
            atomicAdd(&g_center[0], sx);
            atomicAdd(&g_center[1], sy);
            atomicAdd(&g_center[2], sz);
        }
    }
}

// ---------------------------------------------------------------- launch 2: all encoders
#define ENC_SMEM 141312

__global__ void __launch_bounds__(256, 1) k_enc_all(
    const float* __restrict__ pos, const float* __restrict__ vel,
    const int* __restrict__ rid, const float* __restrict__ remb,
    const int* __restrict__ snd, const int* __restrict__ rcv,
    const float* __restrict__ nW1, const float* __restrict__ nB1,
    const float* __restrict__ nW2, const float* __restrict__ nB2,
    const float* __restrict__ eW1, const float* __restrict__ eB1,
    const float* __restrict__ eW2, const float* __restrict__ eB2)
{
    extern __shared__ char smc[];
    const int tid = threadIdx.x;

    if (blockIdx.x < NB_ENC) {
        // ===== node encoder (64 nodes) + projection step 0 =====
        float* F = (float*)(smc + 0);
        float* H = (float*)(smc + 8192);
        __nv_bfloat16* Ahi = (__nv_bfloat16*)(smc + 40960);
        __nv_bfloat16* Alo = (__nv_bfloat16*)(smc + 58368);
        __nv_bfloat16* Wch = (__nv_bfloat16*)(smc + 75776);
        __nv_bfloat16* Wcl = (__nv_bfloat16*)(smc + 93184);
        const int nbase = blockIdx.x * 64;
        const float inv = 1.f / (float)NN;
        const float cx = g_center[0] * inv, cy = g_center[1] * inv, cz = g_center[2] * inv;

        for (int i = tid; i < 64 * 23; i += 256) {
            int n = i / 23, k = i % 23;
            int gn = nbase + n;
            float v = 0.f;
            if (gn < NN) {
                if (k < 3) v = vel[gn * 3 + k];
                else if (k < 6) v = pos[gn * 3 + (k - 3)] - ((k == 3) ? cx : (k == 4) ? cy : cz);
                else if (k == 6) v = g_deg[gn];
                else v = remb[rid[gn] * 16 + (k - 7)];
            }
            F[n * 24 + k] = v;
        }
        __syncthreads();

        const int j = tid & 127;
        for (int n = tid >> 7; n < 64; n += 2) {
            float acc = nB1[j];
#pragma unroll
            for (int k = 0; k < 23; k++) acc += F[n * 24 + k] * nW1[k * 128 + j];
            H[n * 128 + j] = fmaxf(acc, 0.f);
        }
        __syncthreads();
        for (int n = tid >> 7; n < 64; n += 2) {
            int gn = nbase + n;
            float acc = nB2[j];
#pragma unroll 8
            for (int k = 0; k < 128; k++) acc += H[n * 128 + k] * nW2[k * 128 + j];
            float v = (gn < NN) ? acc : 0.f;
            if (gn < NN) g_nl[(size_t)gn * LL + j] = v;
            __nv_bfloat16 h = __float2bfloat16(v);
            Ahi[n * 136 + j] = h;
            Alo[n * 136 + j] = __float2bfloat16(v - __bfloat162float(h));
        }
        __syncthreads();

        // projection Z(0) = nl @ PRJ(0)
        const int w = tid >> 5, rt = w >> 1, cg = w & 1;
        const bool full = (nbase + 64 <= NN);
        const __nv_bfloat16* wn = g_ws;
        CF acc[4];
#pragma unroll 1
        for (int half = 0; half < 2; ++half) {
#pragma unroll
            for (int f = 0; f < 4; f++) wmma::fill_fragment(acc[f], 0.f);
            for (int kc = 0; kc < 128; kc += 64) {
                __syncthreads();
                for (int i = tid; i < 1024; i += 256) {
                    int rr = i >> 4, g = i & 15;
                    *(float4*)(Wch + rr * 136 + g * 8) =
                        ((const float4*)(wn + PRJ_HI + (size_t)(kc + rr) * 256 + half * 128))[g];
                    *(float4*)(Wcl + rr * 136 + g * 8) =
                        ((const float4*)(wn + PRJ_LO + (size_t)(kc + rr) * 256 + half * 128))[g];
                }
                __syncthreads();
                for (int kk = 0; kk < 64; kk += 16) {
                    AF ah, al;
                    wmma::load_matrix_sync(ah, Ahi + rt * 16 * 136 + kc + kk, 136);
                    wmma::load_matrix_sync(al, Alo + rt * 16 * 136 + kc + kk, 136);
#pragma unroll
                    for (int f = 0; f < 4; f++) {
                        BF bh, bl;
                        wmma::load_matrix_sync(bh, Wch + kk * 136 + cg * 64 + f * 16, 136);
                        wmma::load_matrix_sync(bl, Wcl + kk * 136 + cg * 64 + f * 16, 136);
                        wmma::mma_sync(acc[f], ah, bh, acc[f]);
                        wmma::mma_sync(acc[f], ah, bl, acc[f]);
                        wmma::mma_sync(acc[f], al, bh, acc[f]);
                    }
                }
            }
            if (full) {
#pragma unroll
                for (int f = 0; f < 4; f++)
                    wmma::store_matrix_sync(g_z + (size_t)(nbase + rt * 16) * 256 + half * 128 + cg * 64 + f * 16,
                                            acc[f], 256, wmma::mem_row_major);
            } else {
                float* Cf = (float*)(smc + 75776);   // dead W region; restaged next half
                __syncthreads();
#pragma unroll
                for (int f = 0; f < 4; f++)
                    wmma::store_matrix_sync(Cf + rt * 16 * 132 + cg * 64 + f * 16, acc[f], 132, wmma::mem_row_major);
                __syncthreads();
                for (int i = tid; i < 64 * 32; i += 256) {
                    int row = i >> 5, c4 = i & 31;
                    int n = nbase + row;
                    if (n < NN)
                        ((float4*)(g_z + (size_t)n * 256 + half * 128))[c4] =
                            *(float4*)(Cf + row * 132 + c4 * 4);
                }
            }
        }
        return;
    }

    // ===== edge encoder =====
    {
        const int LDF = 12, LDH = 132, LDHB = 136, LDWB = 136;
        float*         F   = (float*)(smc + 0);
        float*         Hf  = (float*)(smc + 3072);
        __nv_bfloat16* Hhi = (__nv_bfloat16*)(smc + 36864);
        __nv_bfloat16* Hlo = (__nv_bfloat16*)(smc + 54272);
        __nv_bfloat16* Whi = (__nv_bfloat16*)(smc + 71680);
        __nv_bfloat16* Wlo = (__nv_bfloat16*)(smc + 106496);
        const int w = tid >> 5, rt = w >> 1, cg = w & 1;
        const int tile = blockIdx.x - NB_ENC;
        const int ebase = tile * 64;

        if (tid < 64) {
            int e = ebase + tid;
            int s = snd[e], r = rcv[e];
            float rp0 = pos[s * 3 + 0] - pos[r * 3 + 0];
            float rp1 = pos[s * 3 + 1] - pos[r * 3 + 1];
            float rp2 = pos[s * 3 + 2] - pos[r * 3 + 2];
            float rv0 = vel[s * 3 + 0] - vel[r * 3 + 0];
            float rv1 = vel[s * 3 + 1] - vel[r * 3 + 1];
            float rv2 = vel[s * 3 + 2] - vel[r * 3 + 2];
            float sq = rp0 * rp0 + rp1 * rp1 + rp2 * rp2;
            float dist = sqrtf(sq);
            float same = (rid[s] == rid[r]) ? 1.f : 0.f;
            float* f = F + tid * LDF;
            f[0] = rp0; f[1] = rp1; f[2] = rp2;
            f[3] = rv0; f[4] = rv1; f[5] = rv2;
            f[6] = dist; f[7] = sq; f[8] = same;
        }
        for (int i = tid; i < 128 * 32; i += 256) {
            int rr = i >> 5, c4 = i & 31;
            float4 v = ((const float4*)(eW2 + rr * 128))[c4];
            split_store4(v, Whi + rr * LDWB + c4 * 4, Wlo + rr * LDWB + c4 * 4);
        }
        __syncthreads();

        for (int i = tid; i < 64 * 128; i += 256) {
            int e = i >> 7, jj = i & 127;
            const float* f = F + e * LDF;
            float acc = eB1[jj];
#pragma unroll
            for (int k = 0; k < 9; k++) acc += f[k] * eW1[k * 128 + jj];
            Hf[e * LDH + jj] = fmaxf(acc, 0.f);
        }
        __syncthreads();
        for (int i = tid; i < 64 * 32; i += 256) {
            int row = i >> 5, c4 = i & 31;
            float4 v = ((const float4*)(Hf + row * LDH))[c4];
            split_store4(v, Hhi + row * LDHB + c4 * 4, Hlo + row * LDHB + c4 * 4);
        }
        __syncthreads();

        CF acc[4];
#pragma unroll
        for (int f = 0; f < 4; f++) wmma::fill_fragment(acc[f], 0.f);

        for (int kk = 0; kk < 128; kk += 16) {
            AF ah, al;
            wmma::load_matrix_sync(ah, Hhi + rt * 16 * LDHB + kk, LDHB);
            wmma::load_matrix_sync(al, Hlo + rt * 16 * LDHB + kk, LDHB);
#pragma unroll
            for (int f = 0; f < 4; f++) {
                BF bh, bl;
                wmma::load_matrix_sync(bh, Whi + kk * LDWB + cg * 64 + f * 16, LDWB);
                wmma::load_matrix_sync(bl, Wlo + kk * LDWB + cg * 64 + f * 16, LDWB);
                wmma::mma_sync(acc[f], ah, bh, acc[f]);
                wmma::mma_sync(acc[f], ah, bl, acc[f]);
                wmma::mma_sync(acc[f], al, bh, acc[f]);
            }
        }
        __syncthreads();
#pragma unroll
        for (int f = 0; f < 4; f++)
            wmma::store_matrix_sync(Hf + rt * 16 * LDH + cg * 64 + f * 16, acc[f], LDH, wmma::mem_row_major);
        __syncthreads();

        __nv_bfloat16* elbase = g_el + (size_t)tile * 16384;
        for (int i = tid; i < 64 * 32; i += 256) {
            int e = i >> 5, c4 = i & 31;
            float4 c2 = ((const float4*)(Hf + e * LDH))[c4];
            float4 bb = ((const float4*)eB2)[c4];
            float4 nv = make_float4(c2.x + bb.x, c2.y + bb.y, c2.z + bb.z, c2.w + bb.w);
            __nv_bfloat16* hp = elbase + e * 128 + c4 * 4;
            split_store4(nv, hp, hp + 8192);
        }
    }
}

// ---------------------------------------------------------------- edge processor step
// 64 edges/block, 256 threads, 8 warps tiled 2x4 (warp = 32 rows x 32 cols).
// W staged in 64-K chunks -> smem 69.5 KB -> 3 blocks/SM.
#define ES_SSH 0
#define ES_RSH 256
#define ES_B1  512
#define ES_B2  1024
#define ES_AHI 1536
#define ES_ALO 18944
#define ES_W   36352
#define ES_WLO 53760
#define ES_SMEM 71168

__global__ void __launch_bounds__(256, 3) k_edge_step(
    const int* __restrict__ snd, const int* __restrict__ rcv, int step,
    const float* __restrict__ B1, const float* __restrict__ B2)
{
    extern __shared__ char smc[];
    int*   ssh = (int*)(smc + ES_SSH);
    int*   rsh = (int*)(smc + ES_RSH);
    float* B1s = (float*)(smc + ES_B1);
    float* B2s = (float*)(smc + ES_B2);
    __nv_bfloat16* Ahi = (__nv_bfloat16*)(smc + ES_AHI);   // 64 x 136
    __nv_bfloat16* Alo = (__nv_bfloat16*)(smc + ES_ALO);
    __nv_bfloat16* Whi = (__nv_bfloat16*)(smc + ES_W);     // 64 x 136 (K-chunk)
    __nv_bfloat16* Wlo = (__nv_bfloat16*)(smc + ES_WLO);
    float*         Cf  = (float*)(smc + ES_W);             // 64 x 132 fp32, aliases W hi+lo
    const int tid = threadIdx.x;
    const int w = tid >> 5, rt = w & 1, cg = w >> 1;       // 2 x 4 tiling
    const int ebase = blockIdx.x * 64;
    const __nv_bfloat16* wbase = g_ws + (size_t)step * STEP_W;
    __nv_bfloat16* elbase = g_el + (size_t)blockIdx.x * 16384;
    const uint32_t whi_b = smem_u32(Whi), wlo_b = smem_u32(Wlo);
    const uint32_t ahi_b = smem_u32(Ahi), alo_b = smem_u32(Alo);

    if (tid < 64) {
        ssh[tid] = snd[ebase + tid];
        rsh[tid] = rcv[ebase + tid];
    }
    if (tid < 128) {
        B1s[tid] = B1[tid];
        B2s[tid] = B2[tid];
    }
    // cp.async el planes into A; W1a chunk 0 (K rows 0..63)
    for (int i = tid; i < 1024; i += 256) {
        int r = i >> 4, g = i & 15;
        cp_async16(ahi_b + (uint32_t)(r * 272 + g * 16), elbase + r * 128 + g * 8);
        cp_async16(alo_b + (uint32_t)(r * 272 + g * 16), elbase + 8192 + r * 128 + g * 8);
        cp_async16(whi_b + (uint32_t)(r * 272 + g * 16), wbase + EW1A_HI + r * 128 + g * 8);
        cp_async16(wlo_b + (uint32_t)(r * 272 + g * 16), wbase + EW1A_LO + r * 128 + g * 8);
    }
    cp_commit_wait();
    __syncthreads();

    CF acc[2][2];
#pragma unroll
    for (int sr = 0; sr < 2; sr++)
#pragma unroll
        for (int sc = 0; sc < 2; sc++) wmma::fill_fragment(acc[sr][sc], 0.f);

    // ---- GEMM1: el @ W1a, K chunked by 64
#pragma unroll 1
    for (int kc = 0; kc < 128; kc += 64) {
        if (kc) {
            __syncthreads();
            for (int i = tid; i < 1024; i += 256) {
                int r = i >> 4, g = i & 15;
                cp_async16(whi_b + (uint32_t)(r * 272 + g * 16), wbase + EW1A_HI + (kc + r) * 128 + g * 8);
                cp_async16(wlo_b + (uint32_t)(r * 272 + g * 16), wbase + EW1A_LO + (kc + r) * 128 + g * 8);
            }
            cp_commit_wait();
            __syncthreads();
        }
        for (int kk = 0; kk < 64; kk += 16) {
            AF ah[2], al[2];
#pragma unroll
            for (int sr = 0; sr < 2; sr++) {
                wmma::load_matrix_sync(ah[sr], Ahi + (rt * 32 + sr * 16) * 136 + kc + kk, 136);
                wmma::load_matrix_sync(al[sr], Alo + (rt * 32 + sr * 16) * 136 + kc + kk, 136);
            }
#pragma unroll
            for (int sc = 0; sc < 2; sc++) {
                BF bh, bl;
                wmma::load_matrix_sync(bh, Whi + kk * 136 + cg * 32 + sc * 16, 136);
                wmma::load_matrix_sync(bl, Wlo + kk * 136 + cg * 32 + sc * 16, 136);
#pragma unroll
                for (int sr = 0; sr < 2; sr++) {
                    wmma::mma_sync(acc[sr][sc], ah[sr], bh, acc[sr][sc]);
                    wmma::mma_sync(acc[sr][sc], ah[sr], bl, acc[sr][sc]);
                    wmma::mma_sync(acc[sr][sc], al[sr], bh, acc[sr][sc]);
                }
            }
        }
    }
    __syncthreads();
#pragma unroll
    for (int sr = 0; sr < 2; sr++)
#pragma unroll
        for (int sc = 0; sc < 2; sc++)
            wmma::store_matrix_sync(Cf + (rt * 32 + sr * 16) * 132 + cg * 32 + sc * 16,
                                    acc[sr][sc], 132, wmma::mem_row_major);
    __syncthreads();

    // ---- epilogue 1: v = relu(C1 + Z[s] + Z[r] + B1) -> H planes (overwrite A)
    for (int i = tid; i < 2048; i += 256) {
        int row = i >> 5, c4 = i & 31;
        int s = ssh[row], r = rsh[row];
        float4 c = *(float4*)(Cf + row * 132 + c4 * 4);
        float4 zb = ((const float4*)(g_z + (size_t)s * 256))[c4];
        float4 zc = ((const float4*)(g_z + (size_t)r * 256 + 128))[c4];
        float4 b = ((const float4*)B1s)[c4];
        float4 v = make_float4(
            fmaxf(c.x + zb.x + zc.x + b.x, 0.f),
            fmaxf(c.y + zb.y + zc.y + b.y, 0.f),
            fmaxf(c.z + zb.z + zc.z + b.z, 0.f),
            fmaxf(c.w + zb.w + zc.w + b.w, 0.f));
        split_store4(v, Ahi + row * 136 + c4 * 4, Alo + row * 136 + c4 * 4);
    }
    __syncthreads();

    // ---- GEMM2: H @ W2, K chunked by 64
#pragma unroll
    for (int sr = 0; sr < 2; sr++)
#pragma unroll
        for (int sc = 0; sc < 2; sc++) wmma::fill_fragment(acc[sr][sc], 0.f);
#pragma unroll 1
    for (int kc = 0; kc < 128; kc += 64) {
        for (int i = tid; i < 1024; i += 256) {
            int r = i >> 4, g = i & 15;
            cp_async16(whi_b + (uint32_t)(r * 272 + g * 16), wbase + EW2_HI + (kc + r) * 128 + g * 8);
            cp_async16(wlo_b + (uint32_t)(r * 272 + g * 16), wbase + EW2_LO + (kc + r) * 128 + g * 8);
        }
        cp_commit_wait();
        __syncthreads();
        for (int kk = 0; kk < 64; kk += 16) {
            AF ah[2], al[2];
#pragma unroll
            for (int sr = 0; sr < 2; sr++) {
                wmma::load_matrix_sync(ah[sr], Ahi + (rt * 32 + sr * 16) * 136 + kc + kk, 136);
                wmma::load_matrix_sync(al[sr], Alo + (rt * 32 + sr * 16) * 136 + kc + kk, 136);
            }
#pragma unroll
            for (int sc = 0; sc < 2; sc++) {
                BF bh, bl;
                wmma::load_matrix_sync(bh, Whi + kk * 136 + cg * 32 + sc * 16, 136);
                wmma::load_matrix_sync(bl, Wlo + kk * 136 + cg * 32 + sc * 16, 136);
#pragma unroll
                for (int sr = 0; sr < 2; sr++) {
                    wmma::mma_sync(acc[sr][sc], ah[sr], bh, acc[sr][sc]);
                    wmma::mma_sync(acc[sr][sc], ah[sr], bl, acc[sr][sc]);
                    wmma::mma_sync(acc[sr][sc], al[sr], bh, acc[sr][sc]);
                }
            }
        }
        __syncthreads();
    }
#pragma unroll
    for (int sr = 0; sr < 2; sr++)
#pragma unroll
        for (int sc = 0; sc < 2; sc++)
            wmma::store_matrix_sync(Cf + (rt * 32 + sr * 16) * 132 + cg * 32 + sc * 16,
                                    acc[sr][sc], 132, wmma::mem_row_major);
    __syncthreads();

    // ---- epilogue 2: el_new = el_old (re-read from global planes, L2-hot) + C2 + b2
    for (int i = tid; i < 2048; i += 256) {
        int row = i >> 5, c4 = i & 31;
        __nv_bfloat16* hp = elbase + row * 128 + c4 * 4;
        float4 oldv = join4(hp, hp + 8192);
        float4 c = *(float4*)(Cf + row * 132 + c4 * 4);
        float4 b = ((const float4*)B2s)[c4];
        float4 nv = make_float4(oldv.x + c.x + b.x, oldv.y + c.y + b.y,
                                oldv.z + c.z + b.z, oldv.w + c.w + b.w);
        split_store4(nv, hp, hp + 8192);
        red_add_v4(g_agg + (size_t)rsh[row] * LL + c4 * 4, nv);
    }
}

// ---------------------------------------------------------------- node step (+fused projection)
#define NS_XHI 0
#define NS_XLO 33792
#define NS_CF  0
#define NS_HHI 33792
#define NS_HLO 51200
#define NS_W   68608
#define NS_WLO 86016
#define NS_SMEM 103424

__global__ void __launch_bounds__(256, 2) k_node_step(
    int step, const float* __restrict__ B1, const float* __restrict__ B2, int do_proj)
{
    extern __shared__ char smc[];
    __nv_bfloat16* Xhi = (__nv_bfloat16*)(smc + NS_XHI);
    __nv_bfloat16* Xlo = (__nv_bfloat16*)(smc + NS_XLO);
    __nv_bfloat16* Whi = (__nv_bfloat16*)(smc + NS_W);
    __nv_bfloat16* Wlo = (__nv_bfloat16*)(smc + NS_WLO);
    float*         Cf  = (float*)(smc + NS_CF);
    __nv_bfloat16* Hhi = (__nv_bfloat16*)(smc + NS_HHI);
    __nv_bfloat16* Hlo = (__nv_bfloat16*)(smc + NS_HLO);
    const int tid = threadIdx.x;
    const int w = tid >> 5, rt = w >> 1, cg = w & 1;
    const int nbase = blockIdx.x * 64;
    const bool full = (nbase + 64 <= NN);
    const __nv_bfloat16* wbase = g_ws + (size_t)step * STEP_W;
    const uint32_t whi_b = smem_u32(Whi), wlo_b = smem_u32(Wlo);

    for (int i = tid; i < 64 * 64; i += 256) {
        int row = i >> 6, c4 = i & 63;
        int n = nbase + row;
        float4 v = make_float4(0.f, 0.f, 0.f, 0.f);
        if (n < NN) {
            if (c4 < 32) {
                v = ((const float4*)(g_nl + (size_t)n * LL))[c4];
            } else {
                float4* ap = (float4*)(g_agg + (size_t)n * LL) + (c4 - 32);
                v = *ap;
                *ap = make_float4(0.f, 0.f, 0.f, 0.f);
            }
        }
        split_store4(v, Xhi + row * 264 + c4 * 4, Xlo + row * 264 + c4 * 4);
    }

    CF acc[4];
#pragma unroll
    for (int f = 0; f < 4; f++) wmma::fill_fragment(acc[f], 0.f);

    for (int kc = 0; kc < 256; kc += 64) {
        __syncthreads();
        for (int i = tid; i < 1024; i += 256) {
            int rr = i >> 4, g = i & 15;
            cp_async16(whi_b + (uint32_t)(rr * 136 + g * 8) * 2, wbase + NW1_HI + (kc + rr) * 128 + g * 8);
            cp_async16(wlo_b + (uint32_t)(rr * 136 + g * 8) * 2, wbase + NW1_LO + (kc + rr) * 128 + g * 8);
        }
        cp_commit_wait();
        __syncthreads();
        for (int kk = 0; kk < 64; kk += 16) {
            AF ah, al;
            wmma::load_matrix_sync(ah, Xhi + rt * 16 * 264 + kc + kk, 264);
            wmma::load_matrix_sync(al, Xlo + rt * 16 * 264 + kc + kk, 264);
#pragma unroll
            for (int f = 0; f < 4; f++) {
                BF bh, bl;
                wmma::load_matrix_sync(bh, Whi + kk * 136 + cg * 64 + f * 16, 136);
                wmma::load_matrix_sync(bl, Wlo + kk * 136 + cg * 64 + f * 16, 136);
                wmma::mma_sync(acc[f], ah, bh, acc[f]);
                wmma::mma_sync(acc[f], ah, bl, acc[f]);
                wmma::mma_sync(acc[f], al, bh, acc[f]);
            }
        }
    }
    __syncthreads();
#pragma unroll
    for (int f = 0; f < 4; f++)
        wmma::store_matrix_sync(Cf + rt * 16 * 132 + cg * 64 + f * 16, acc[f], 132, wmma::mem_row_major);
    __syncthreads();
    for (int i = tid; i < 64 * 32; i += 256) {
        int row = i >> 5, c4 = i & 31;
        float4 v = *(float4*)(Cf + row * 132 + c4 * 4);
        float4 bb = ((const float4*)B1)[c4];
        v.x = fmaxf(v.x + bb.x, 0.f);
        v.y = fmaxf(v.y + bb.y, 0.f);
        v.z = fmaxf(v.z + bb.z, 0.f);
        v.w = fmaxf(v.w + bb.w, 0.f);
        split_store4(v, Hhi + row * 136 + c4 * 4, Hlo + row * 136 + c4 * 4);
    }

#pragma unroll
    for (int f = 0; f < 4; f++) wmma::fill_fragment(acc[f], 0.f);
    for (int kc = 0; kc < 128; kc += 64) {
        __syncthreads();
        for (int i = tid; i < 1024; i += 256) {
            int rr = i >> 4, g = i & 15;
            cp_async16(whi_b + (uint32_t)(rr * 136 + g * 8) * 2, wbase + NW2_HI + (kc + rr) * 128 + g * 8);
            cp_async16(wlo_b + (uint32_t)(rr * 136 + g * 8) * 2, wbase + NW2_LO + (kc + rr) * 128 + g * 8);
        }
        cp_commit_wait();
        __syncthreads();
        for (int kk = 0; kk < 64; kk += 16) {
            AF ah, al;
            wmma::load_matrix_sync(ah, Hhi + rt * 16 * 136 + kc + kk, 136);
            wmma::load_matrix_sync(al, Hlo + rt * 16 * 136 + kc + kk, 136);
#pragma unroll
            for (int f = 0; f < 4; f++) {
                BF bh, bl;
                wmma::load_matrix_sync(bh, Whi + kk * 136 + cg * 64 + f * 16, 136);
                wmma::load_matrix_sync(bl, Wlo + kk * 136 + cg * 64 + f * 16, 136);
                wmma::mma_sync(acc[f], ah, bh, acc[f]);
                wmma::mma_sync(acc[f], ah, bl, acc[f]);
                wmma::mma_sync(acc[f], al, bh, acc[f]);
            }
        }
    }
    __syncthreads();
#pragma unroll
    for (int f = 0; f < 4; f++)
        wmma::store_matrix_sync(Cf + rt * 16 * 132 + cg * 64 + f * 16, acc[f], 132, wmma::mem_row_major);
    __syncthreads();

    for (int i = tid; i < 64 * 32; i += 256) {
        int row = i >> 5, c4 = i & 31;
        int n = nbase + row;
        float4 nv = make_float4(0.f, 0.f, 0.f, 0.f);
        if (n < NN) {
            float4 oldv = ((const float4*)(g_nl + (size_t)n * LL))[c4];
            float4 c2 = *(float4*)(Cf + row * 132 + c4 * 4);
            float4 bb = ((const float4*)B2)[c4];
            nv = make_float4(oldv.x + c2.x + bb.x, oldv.y + c2.y + bb.y,
                             oldv.z + c2.z + bb.z, oldv.w + c2.w + bb.w);
            ((float4*)(g_nl + (size_t)n * LL))[c4] = nv;
        }
        if (do_proj)
            split_store4(nv, Hhi + row * 136 + c4 * 4, Hlo + row * 136 + c4 * 4);
    }

    if (do_proj) {
        const __nv_bfloat16* wn = g_ws + (size_t)(step + 1) * STEP_W;
#pragma unroll 1
        for (int half = 0; half < 2; ++half) {
#pragma unroll
            for (int f = 0; f < 4; f++) wmma::fill_fragment(acc[f], 0.f);
            for (int kc = 0; kc < 128; kc += 64) {
                __syncthreads();
                for (int i = tid; i < 1024; i += 256) {
                    int rr = i >> 4, g = i & 15;
                    cp_async16(whi_b + (uint32_t)(rr * 136 + g * 8) * 2,
                               wn + PRJ_HI + (size_t)(kc + rr) * 256 + half * 128 + g * 8);
                    cp_async16(wlo_b + (uint32_t)(rr * 136 + g * 8) * 2,
                               wn + PRJ_LO + (size_t)(kc + rr) * 256 + half * 128 + g * 8);
                }
                cp_commit_wait();
                __syncthreads();
                for (int kk = 0; kk < 64; kk += 16) {
                    AF ah, al;
                    wmma::load_matrix_sync(ah, Hhi + rt * 16 * 136 + kc + kk, 136);
                    wmma::load_matrix_sync(al, Hlo + rt * 16 * 136 + kc + kk, 136);
#pragma unroll
                    for (int f = 0; f < 4; f++) {
                        BF bh, bl;
                        wmma::load_matrix_sync(bh, Whi + kk * 136 + cg * 64 + f * 16, 136);
                        wmma::load_matrix_sync(bl, Wlo + kk * 136 + cg * 64 + f * 16, 136);
                        wmma::mma_sync(acc[f], ah, bh, acc[f]);
                        wmma::mma_sync(acc[f], ah, bl, acc[f]);
                        wmma::mma_sync(acc[f], al, bh, acc[f]);
                    }
                }
            }
            if (full) {
#pragma unroll
                for (int f = 0; f < 4; f++)
                    wmma::store_matrix_sync(g_z + (size_t)(nbase + rt * 16) * 256 + half * 128 + cg * 64 + f * 16,
                                            acc[f], 256, wmma::mem_row_major);
            } else {
                __syncthreads();
#pragma unroll
                for (int f = 0; f < 4; f++)
                    wmma::store_matrix_sync(Cf + rt * 16 * 132 + cg * 64 + f * 16, acc[f], 132, wmma::mem_row_major);
                __syncthreads();
                for (int i = tid; i < 64 * 32; i += 256) {
                    int row = i >> 5, c4 = i & 31;
                    int n = nbase + row;
                    if (n < NN)
                        ((float4*)(g_z + (size_t)n * 256 + half * 128))[c4] =
                            *(float4*)(Cf + row * 132 + c4 * 4);
                }
            }
        }
    }
}

// ---------------------------------------------------------------- decoder (SIMT fp32; exact)
__global__ void __launch_bounds__(128) k_decoder(
    const float* __restrict__ W1, const float* __restrict__ B1,
    const float* __restrict__ W2, const float* __restrict__ B2,
    float* __restrict__ out)
{
    __shared__ float Xs[32][128];
    __shared__ float H[32][128];
    const int tid = threadIdx.x;
    const int nbase = blockIdx.x * 32;

    for (int i = tid; i < 32 * 32; i += 128) {
        int n = i >> 5, c4 = i & 31;
        int gn = nbase + n;
        float4 v = make_float4(0.f, 0.f, 0.f, 0.f);
        if (gn < NN) v = ((const float4*)(g_nl + (size_t)gn * LL))[c4];
        ((float4*)Xs[n])[c4] = v;
    }
    __syncthreads();

    const int j = tid;
#pragma unroll 1
    for (int n = 0; n < 32; n++) {
        float acc = B1[j];
#pragma unroll 8
        for (int k = 0; k < 128; k++) acc += Xs[n][k] * W1[k * 128 + j];
        H[n][j] = fmaxf(acc, 0.f);
    }
    __syncthreads();

    if (tid < 96) {
        int n = tid / 3, d = tid % 3;
        int gn = nbase + n;
        float acc = B2[d];
#pragma unroll 8
        for (int k = 0; k < 128; k++) acc += H[n][k] * W2[k * 3 + d];
        if (gn < NN) out[gn * 3 + d] = acc;
    }
}

// ---------------------------------------------------------------- launch
extern "C" void kernel_launch(void* const* d_in, const int* in_sizes, int n_in,
                              void* d_out, int out_size)
{
    const float* pos   = (const float*)d_in[0];
    const float* vel   = (const float*)d_in[1];
    const int*   rid   = (const int*)d_in[2];
    const int*   snd   = (const int*)d_in[3];
    const int*   rcv   = (const int*)d_in[4];
    const float* remb  = (const float*)d_in[5];
    const float* ne_w1 = (const float*)d_in[6];
    const float* ne_b1 = (const float*)d_in[7];
    const float* ne_w2 = (const float*)d_in[8];
    const float* ne_b2 = (const float*)d_in[9];
    const float* ee_w1 = (const float*)d_in[10];
    const float* ee_b1 = (const float*)d_in[11];
    const float* ee_w2 = (const float*)d_in[12];
    const float* ee_b2 = (const float*)d_in[13];
    const float* pe_w1 = (const float*)d_in[14];
    const float* pe_b1 = (const float*)d_in[15];
    const float* pe_w2 = (const float*)d_in[16];
    const float* pe_b2 = (const float*)d_in[17];
    const float* pn_w1 = (const float*)d_in[18];
    const float* pn_b1 = (const float*)d_in[19];
    const float* pn_w2 = (const float*)d_in[20];
    const float* pn_b2 = (const float*)d_in[21];
    const float* de_w1 = (const float*)d_in[22];
    const float* de_b1 = (const float*)d_in[23];
    const float* de_w2 = (const float*)d_in[24];
    const float* de_b2 = (const float*)d_in[25];

    cudaFuncSetAttribute(k_edge_step, cudaFuncAttributeMaxDynamicSharedMemorySize, ES_SMEM);
    cudaFuncSetAttribute(k_node_step, cudaFuncAttributeMaxDynamicSharedMemorySize, NS_SMEM);
    cudaFuncSetAttribute(k_enc_all, cudaFuncAttributeMaxDynamicSharedMemorySize, ENC_SMEM);

    k_setup<<<4676, 256>>>(pe_w1, pe_w2, pn_w1, pn_w2);
    k_degcenter<<<3229, 256>>>(rcv, pos);
    k_enc_all<<<NB_ENC + EB_ENC, 256, ENC_SMEM>>>(
        pos, vel, rid, remb, snd, rcv,
        ne_w1, ne_b1, ne_w2, ne_b2, ee_w1, ee_b1, ee_w2, ee_b2);

    // launch 3 = first k_edge_step (the profiled slot)
    for (int st = 0; st < NSTEPS; st++) {
        k_edge_step<<<EE / 64, 256, ES_SMEM>>>(
            snd, rcv, st, pe_b1 + (size_t)st * 128, pe_b2 + (size_t)st * 128);
        k_node_step<<<(NN + 63) / 64, 256, NS_SMEM>>>(
            st, pn_b1 + (size_t)st * 128, pn_b2 + (size_t)st * 128, (st < NSTEPS - 1) ? 1 : 0);
    }

    k_decoder<<<(NN + 31) / 32, 128>>>(de_w1, de_b1, de_w2, de_b2, (float*)d_out);
}